// round 1
// baseline (speedup 1.0000x reference)
#include <cuda_runtime.h>

#define DIM    1024
#define HEADS  16
#define DHEAD  64
#define BATCH  4
#define SEQ    2048
#define MTOT   (BATCH * SEQ)   // 8192

// Scratch (device globals: allocation-free)
__device__ float g_h[MTOT * DIM];
__device__ float g_q[MTOT * DIM];   // [b, h, n, d]
__device__ float g_k[MTOT * DIM];
__device__ float g_v[MTOT * DIM];

__device__ __forceinline__ float4 f4fma(float a, float4 b, float4 c) {
    c.x = fmaf(a, b.x, c.x);
    c.y = fmaf(a, b.y, c.y);
    c.z = fmaf(a, b.z, c.z);
    c.w = fmaf(a, b.w, c.w);
    return c;
}

// ---------------------------------------------------------------------------
// LayerNorm: one block per row, 256 threads, float4 per thread
// ---------------------------------------------------------------------------
__global__ __launch_bounds__(256) void ln_kernel(
    const float* __restrict__ x,
    const float* __restrict__ w,
    const float* __restrict__ bvec)
{
    const int row = blockIdx.x;
    const int t = threadIdx.x;
    float4 v = ((const float4*)(x + (size_t)row * DIM))[t];
    float s  = v.x + v.y + v.z + v.w;
    float ss = v.x * v.x + v.y * v.y + v.z * v.z + v.w * v.w;
    #pragma unroll
    for (int off = 16; off; off >>= 1) {
        s  += __shfl_xor_sync(0xffffffffu, s,  off);
        ss += __shfl_xor_sync(0xffffffffu, ss, off);
    }
    __shared__ float sh[16];
    const int wid = t >> 5, lane = t & 31;
    if (lane == 0) { sh[wid] = s; sh[8 + wid] = ss; }
    __syncthreads();
    float ts = 0.f, tss = 0.f;
    #pragma unroll
    for (int i = 0; i < 8; i++) { ts += sh[i]; tss += sh[8 + i]; }
    const float mu  = ts * (1.0f / DIM);
    const float var = tss * (1.0f / DIM) - mu * mu;
    const float r   = rsqrtf(var + 1e-5f);
    float4 wv = ((const float4*)w)[t];
    float4 bv = ((const float4*)bvec)[t];
    float4 o;
    o.x = (v.x - mu) * r * wv.x + bv.x;
    o.y = (v.y - mu) * r * wv.y + bv.y;
    o.z = (v.z - mu) * r * wv.z + bv.z;
    o.w = (v.w - mu) * r * wv.w + bv.w;
    ((float4*)(g_h + (size_t)row * DIM))[t] = o;
}

// ---------------------------------------------------------------------------
// QKV GEMM: C = h @ W + b, 128x128x8 tile, 256 threads, 8x8 per thread.
// blockIdx.z selects q/k/v. Epilogue writes [b, h, n, d] layout directly.
// ---------------------------------------------------------------------------
__global__ __launch_bounds__(256) void qkv_gemm(
    const float* __restrict__ Wq, const float* __restrict__ Bq,
    const float* __restrict__ Wk, const float* __restrict__ Bk,
    const float* __restrict__ Wv, const float* __restrict__ Bv)
{
    const int which = blockIdx.z;
    const float* W    = (which == 0) ? Wq : (which == 1) ? Wk : Wv;
    const float* bias = (which == 0) ? Bq : (which == 1) ? Bk : Bv;
    float* C          = (which == 0) ? g_q : (which == 1) ? g_k : g_v;

    __shared__ float As[8][128];   // [k][m]
    __shared__ float Bs[8][128];   // [k][n]

    const int tid = threadIdx.x;
    const int m0 = blockIdx.y * 128;
    const int n0 = blockIdx.x * 128;

    const int arow = tid >> 1;          // 0..127
    const int acol = (tid & 1) << 2;    // 0 or 4
    const int brow = tid >> 5;          // 0..7
    const int bcol = (tid & 31) << 2;   // 0..124

    const int ty = tid >> 4, tx = tid & 15;

    float4 acc[8][2];
    #pragma unroll
    for (int i = 0; i < 8; i++) {
        acc[i][0] = make_float4(0.f, 0.f, 0.f, 0.f);
        acc[i][1] = make_float4(0.f, 0.f, 0.f, 0.f);
    }

    const float* Ap = g_h + (size_t)(m0 + arow) * DIM + acol;
    const float* Bp = W + (size_t)brow * DIM + n0 + bcol;

    for (int k0 = 0; k0 < DIM; k0 += 8) {
        float4 av = *(const float4*)(Ap + k0);
        float4 bv = *(const float4*)(Bp + (size_t)k0 * DIM);
        As[acol + 0][arow] = av.x;
        As[acol + 1][arow] = av.y;
        As[acol + 2][arow] = av.z;
        As[acol + 3][arow] = av.w;
        *(float4*)&Bs[brow][bcol] = bv;
        __syncthreads();
        #pragma unroll
        for (int k = 0; k < 8; k++) {
            float4 a0 = *(const float4*)&As[k][ty * 4];
            float4 a1 = *(const float4*)&As[k][64 + ty * 4];
            float4 b0 = *(const float4*)&Bs[k][tx * 4];
            float4 b1 = *(const float4*)&Bs[k][64 + tx * 4];
            float avr[8];
            avr[0] = a0.x; avr[1] = a0.y; avr[2] = a0.z; avr[3] = a0.w;
            avr[4] = a1.x; avr[5] = a1.y; avr[6] = a1.z; avr[7] = a1.w;
            #pragma unroll
            for (int i = 0; i < 8; i++) {
                acc[i][0] = f4fma(avr[i], b0, acc[i][0]);
                acc[i][1] = f4fma(avr[i], b1, acc[i][1]);
            }
        }
        __syncthreads();
    }

    // Epilogue: bias + scatter to [b, h, n, d]
    const float4 bias0 = *(const float4*)(bias + n0 + tx * 4);
    const float4 bias1 = *(const float4*)(bias + n0 + 64 + tx * 4);
    const int hh0 = (n0 >> 6);      // head of column-group 0
    const int dd  = tx * 4;         // d within head (same for both groups)
    #pragma unroll
    for (int i = 0; i < 8; i++) {
        const int m  = m0 + ((i < 4) ? (ty * 4 + i) : (60 + ty * 4 + i));
        const int bb = m >> 11;
        const int nn = m & (SEQ - 1);
        float4 r0 = acc[i][0];
        r0.x += bias0.x; r0.y += bias0.y; r0.z += bias0.z; r0.w += bias0.w;
        float4 r1 = acc[i][1];
        r1.x += bias1.x; r1.y += bias1.y; r1.z += bias1.z; r1.w += bias1.w;
        *(float4*)&C[(((size_t)(bb * HEADS + hh0)     * SEQ) + nn) * DHEAD + dd] = r0;
        *(float4*)&C[(((size_t)(bb * HEADS + hh0 + 1) * SEQ) + nn) * DHEAD + dd] = r1;
    }
}

// ---------------------------------------------------------------------------
// Flash attention: 64-query x 64-key tiles, 256 threads (16x16),
// each thread owns a 4x4 output patch. 48KB static smem exactly.
// ---------------------------------------------------------------------------
__global__ __launch_bounds__(256) void attn_kernel(float* __restrict__ out)
{
    const int bh = blockIdx.y;              // 0..63
    const int q0 = blockIdx.x * 64;
    const float* Qb = g_q + (size_t)bh * SEQ * DHEAD;
    const float* Kb = g_k + (size_t)bh * SEQ * DHEAD;
    const float* Vb = g_v + (size_t)bh * SEQ * DHEAD;

    __shared__ float Qs[64][64];    // [row][d], pre-scaled
    __shared__ float KPs[64][64];   // K^T tile [d][key], reused as P [row][key]
    __shared__ float Vs[64][64];    // [key][d]

    const int tid = threadIdx.x;
    const int ty = tid >> 4, tx = tid & 15;
    const int lr = tid >> 2;            // load row 0..63
    const int lc = (tid & 3) << 4;      // load col base 0/16/32/48

    #pragma unroll
    for (int u = 0; u < 4; u++) {
        float4 qv = *(const float4*)(Qb + (size_t)(q0 + lr) * DHEAD + lc + u * 4);
        qv.x *= 0.125f; qv.y *= 0.125f; qv.z *= 0.125f; qv.w *= 0.125f;
        *(float4*)&Qs[lr][lc + u * 4] = qv;
    }

    float m_i[4], l_i[4];
    float4 o4[4];
    #pragma unroll
    for (int i = 0; i < 4; i++) {
        m_i[i] = -1e30f;
        l_i[i] = 0.f;
        o4[i] = make_float4(0.f, 0.f, 0.f, 0.f);
    }

    for (int kt = 0; kt < SEQ / 64; kt++) {
        const int k0 = kt * 64;
        __syncthreads();   // prior-iteration reads of KPs/Vs complete
        #pragma unroll
        for (int u = 0; u < 4; u++) {
            float4 kv = *(const float4*)(Kb + (size_t)(k0 + lr) * DHEAD + lc + u * 4);
            KPs[lc + u * 4 + 0][lr] = kv.x;
            KPs[lc + u * 4 + 1][lr] = kv.y;
            KPs[lc + u * 4 + 2][lr] = kv.z;
            KPs[lc + u * 4 + 3][lr] = kv.w;
            *(float4*)&Vs[lr][lc + u * 4] =
                *(const float4*)(Vb + (size_t)(k0 + lr) * DHEAD + lc + u * 4);
        }
        __syncthreads();

        // S = Q * K^T (4x4 per thread)
        float4 s4[4];
        #pragma unroll
        for (int i = 0; i < 4; i++) s4[i] = make_float4(0.f, 0.f, 0.f, 0.f);
        #pragma unroll
        for (int k4 = 0; k4 < 16; k4++) {
            float4 q[4], kv[4];
            #pragma unroll
            for (int i = 0; i < 4; i++)
                q[i] = *(const float4*)&Qs[ty * 4 + i][k4 * 4];
            #pragma unroll
            for (int kk = 0; kk < 4; kk++)
                kv[kk] = *(const float4*)&KPs[k4 * 4 + kk][tx * 4];
            #pragma unroll
            for (int i = 0; i < 4; i++) {
                s4[i] = f4fma(q[i].x, kv[0], s4[i]);
                s4[i] = f4fma(q[i].y, kv[1], s4[i]);
                s4[i] = f4fma(q[i].z, kv[2], s4[i]);
                s4[i] = f4fma(q[i].w, kv[3], s4[i]);
            }
        }
        __syncthreads();   // everyone done reading KPs before P overwrite

        // online softmax + write P into KPs
        #pragma unroll
        for (int i = 0; i < 4; i++) {
            float mx = fmaxf(fmaxf(s4[i].x, s4[i].y), fmaxf(s4[i].z, s4[i].w));
            #pragma unroll
            for (int off = 8; off; off >>= 1)
                mx = fmaxf(mx, __shfl_xor_sync(0xffffffffu, mx, off));
            const float mn = fmaxf(m_i[i], mx);
            const float alpha = __expf(m_i[i] - mn);
            m_i[i] = mn;
            float4 p;
            p.x = __expf(s4[i].x - mn);
            p.y = __expf(s4[i].y - mn);
            p.z = __expf(s4[i].z - mn);
            p.w = __expf(s4[i].w - mn);
            float rs = p.x + p.y + p.z + p.w;
            #pragma unroll
            for (int off = 8; off; off >>= 1)
                rs += __shfl_xor_sync(0xffffffffu, rs, off);
            l_i[i] = l_i[i] * alpha + rs;
            o4[i].x *= alpha; o4[i].y *= alpha; o4[i].z *= alpha; o4[i].w *= alpha;
            *(float4*)&KPs[ty * 4 + i][tx * 4] = p;
        }
        __syncthreads();

        // O += P * V
        #pragma unroll
        for (int k4 = 0; k4 < 16; k4++) {
            float4 p[4], vv[4];
            #pragma unroll
            for (int i = 0; i < 4; i++)
                p[i] = *(const float4*)&KPs[ty * 4 + i][k4 * 4];
            #pragma unroll
            for (int kk = 0; kk < 4; kk++)
                vv[kk] = *(const float4*)&Vs[k4 * 4 + kk][tx * 4];
            #pragma unroll
            for (int i = 0; i < 4; i++) {
                o4[i] = f4fma(p[i].x, vv[0], o4[i]);
                o4[i] = f4fma(p[i].y, vv[1], o4[i]);
                o4[i] = f4fma(p[i].z, vv[2], o4[i]);
                o4[i] = f4fma(p[i].w, vv[3], o4[i]);
            }
        }
    }

    // finalize + write output (b, n, h*64 + d)
    const int bb = bh >> 4, hh = bh & 15;
    #pragma unroll
    for (int i = 0; i < 4; i++) {
        const int row = q0 + ty * 4 + i;
        const float inv = 1.f / l_i[i];
        float4 ov;
        ov.x = o4[i].x * inv; ov.y = o4[i].y * inv;
        ov.z = o4[i].z * inv; ov.w = o4[i].w * inv;
        *(float4*)(out + ((size_t)bb * SEQ + row) * (HEADS * DHEAD)
                   + hh * DHEAD + tx * 4) = ov;
    }
}

// ---------------------------------------------------------------------------
extern "C" void kernel_launch(void* const* d_in, const int* in_sizes, int n_in,
                              void* d_out, int out_size) {
    const float* x    = (const float*)d_in[0];
    const float* ln_w = (const float*)d_in[1];
    const float* ln_b = (const float*)d_in[2];
    const float* wq   = (const float*)d_in[3];
    const float* bq   = (const float*)d_in[4];
    const float* wk   = (const float*)d_in[5];
    const float* bk   = (const float*)d_in[6];
    const float* wv   = (const float*)d_in[7];
    const float* bv   = (const float*)d_in[8];
    float* out = (float*)d_out;

    ln_kernel<<<MTOT, 256>>>(x, ln_w, ln_b);
    qkv_gemm<<<dim3(DIM / 128, MTOT / 128, 3), 256>>>(wq, bq, wk, bk, wv, bv);
    attn_kernel<<<dim3(SEQ / 64, BATCH * HEADS), 256>>>(out);
}

// round 3
// speedup vs baseline: 1.1917x; 1.1917x over previous
#include <cuda_runtime.h>
#include <cstdint>

#define DIM    1024
#define HEADS  16
#define DHEAD  64
#define BATCH  4
#define SEQ    2048
#define MTOT   (BATCH * SEQ)   // 8192

// Scratch (device globals: allocation-free)
__device__ float g_h[MTOT * DIM];
__device__ float g_q[MTOT * DIM];   // [b, h, n, d]
__device__ float g_k[MTOT * DIM];
__device__ float g_v[MTOT * DIM];

__device__ __forceinline__ uint32_t tf32_rn(float x) {
    uint32_t r;
    asm("cvt.rn.tf32.f32 %0, %1;" : "=r"(r) : "f"(x));
    return r;
}

__device__ __forceinline__ float4 f4fma(float a, float4 b, float4 c) {
    c.x = fmaf(a, b.x, c.x);
    c.y = fmaf(a, b.y, c.y);
    c.z = fmaf(a, b.z, c.z);
    c.w = fmaf(a, b.w, c.w);
    return c;
}

__device__ __forceinline__ void mma_tf32(
    float& d0, float& d1, float& d2, float& d3,
    uint32_t a0, uint32_t a1, uint32_t a2, uint32_t a3,
    uint32_t b0, uint32_t b1)
{
    asm volatile(
        "mma.sync.aligned.m16n8k8.row.col.f32.tf32.tf32.f32 "
        "{%0,%1,%2,%3}, {%4,%5,%6,%7}, {%8,%9}, {%0,%1,%2,%3};"
        : "+f"(d0), "+f"(d1), "+f"(d2), "+f"(d3)
        : "r"(a0), "r"(a1), "r"(a2), "r"(a3), "r"(b0), "r"(b1));
}

// ---------------------------------------------------------------------------
// LayerNorm: one block per row, 256 threads, float4 per thread
// ---------------------------------------------------------------------------
__global__ __launch_bounds__(256) void ln_kernel(
    const float* __restrict__ x,
    const float* __restrict__ w,
    const float* __restrict__ bvec)
{
    const int row = blockIdx.x;
    const int t = threadIdx.x;
    float4 v = ((const float4*)(x + (size_t)row * DIM))[t];
    float s  = v.x + v.y + v.z + v.w;
    float ss = v.x * v.x + v.y * v.y + v.z * v.z + v.w * v.w;
    #pragma unroll
    for (int off = 16; off; off >>= 1) {
        s  += __shfl_xor_sync(0xffffffffu, s,  off);
        ss += __shfl_xor_sync(0xffffffffu, ss, off);
    }
    __shared__ float sh[16];
    const int wid = t >> 5, lane = t & 31;
    if (lane == 0) { sh[wid] = s; sh[8 + wid] = ss; }
    __syncthreads();
    float ts = 0.f, tss = 0.f;
    #pragma unroll
    for (int i = 0; i < 8; i++) { ts += sh[i]; tss += sh[8 + i]; }
    const float mu  = ts * (1.0f / DIM);
    const float var = tss * (1.0f / DIM) - mu * mu;
    const float r   = rsqrtf(var + 1e-5f);
    float4 wv = ((const float4*)w)[t];
    float4 bv = ((const float4*)bvec)[t];
    float4 o;
    o.x = (v.x - mu) * r * wv.x + bv.x;
    o.y = (v.y - mu) * r * wv.y + bv.y;
    o.z = (v.z - mu) * r * wv.z + bv.z;
    o.w = (v.w - mu) * r * wv.w + bv.w;
    ((float4*)(g_h + (size_t)row * DIM))[t] = o;
}

// ---------------------------------------------------------------------------
// QKV GEMM via mma.sync tf32 (m16n8k8), CTA tile 128x128, K-chunk 32,
// 8 warps in 2(m) x 4(n), warptile 64x32. Double-buffered smem with
// register prefetch. Epilogue adds bias + scatters to [b, h, n, d].
//
// SMEM (uint32 tf32 bits):
//   As[k 0..31][m 0..127], element (k,m) stored at col m ^ ((k&3)<<3)
//   Bs[k 0..31][n 0..127], element (k,n) stored at col n ^ ((k&3)<<3)
// Each buffer 4096 words (16KB); 4 buffers total = 64KB dynamic smem.
// ---------------------------------------------------------------------------
__global__ __launch_bounds__(256) void qkv_gemm_mma(
    const float* __restrict__ Wq, const float* __restrict__ Bq,
    const float* __restrict__ Wk, const float* __restrict__ Bk,
    const float* __restrict__ Wv, const float* __restrict__ Bv)
{
    extern __shared__ uint32_t smem[];
    uint32_t* const As[2] = { smem,        smem + 4096 };
    uint32_t* const Bs[2] = { smem + 8192, smem + 12288 };

    const int which = blockIdx.z;
    const float* W    = (which == 0) ? Wq : (which == 1) ? Wk : Wv;
    const float* bias = (which == 0) ? Bq : (which == 1) ? Bk : Bv;
    float* C          = (which == 0) ? g_q : (which == 1) ? g_k : g_v;

    const int tid  = threadIdx.x;
    const int wid  = tid >> 5;
    const int lane = tid & 31;
    const int gid  = lane >> 2;      // 0..7
    const int tig  = lane & 3;       // 0..3
    const int wm   = wid & 1;        // 0..1  (64-row slab)
    const int wn   = wid >> 1;       // 0..3  (32-col slab)

    const int m0 = blockIdx.y * 128;
    const int n0 = blockIdx.x * 128;

    // A loader: m_l = tid>>1 (row), kk = tid&1 (k half), 4 float4 each
    const int a_m = tid >> 1;
    const int a_k = (tid & 1) * 16;
    // B loader: warp = k row group, lane = n float4
    const float* Arow = g_h + (size_t)(m0 + a_m) * DIM + a_k;

    float acc[4][4][4];
    #pragma unroll
    for (int i = 0; i < 4; i++)
        #pragma unroll
        for (int j = 0; j < 4; j++)
            #pragma unroll
            for (int r = 0; r < 4; r++) acc[i][j][r] = 0.f;

    float4 aReg[4], bReg[4];

    // prefetch chunk 0
    #pragma unroll
    for (int c = 0; c < 4; c++) {
        aReg[c] = *(const float4*)(Arow + c * 4);
        bReg[c] = *(const float4*)(W + (size_t)(wid + 8 * c) * DIM + n0 + lane * 4);
    }

    const int NCHUNK = DIM / 32;
    #pragma unroll 1
    for (int i = 0; i < NCHUNK; ++i) {
        const int p = i & 1;
        // ---- store prefetched regs into buffer p ----
        {
            uint32_t* A = As[p];
            #pragma unroll
            for (int c = 0; c < 4; c++) {
                const int kl = a_k + c * 4;
                A[(kl + 0) * 128 + (a_m ^ 0)]  = tf32_rn(aReg[c].x);
                A[(kl + 1) * 128 + (a_m ^ 8)]  = tf32_rn(aReg[c].y);
                A[(kl + 2) * 128 + (a_m ^ 16)] = tf32_rn(aReg[c].z);
                A[(kl + 3) * 128 + (a_m ^ 24)] = tf32_rn(aReg[c].w);
            }
            uint32_t* B = Bs[p];
            #pragma unroll
            for (int c = 0; c < 4; c++) {
                const int k = wid + 8 * c;
                const int col = (lane * 4) ^ ((k & 3) << 3);
                uint4 u = make_uint4(tf32_rn(bReg[c].x), tf32_rn(bReg[c].y),
                                     tf32_rn(bReg[c].z), tf32_rn(bReg[c].w));
                *(uint4*)&B[k * 128 + col] = u;
            }
        }
        __syncthreads();

        // ---- issue LDG for next chunk ----
        if (i + 1 < NCHUNK) {
            const int k0n = (i + 1) * 32;
            #pragma unroll
            for (int c = 0; c < 4; c++) {
                aReg[c] = *(const float4*)(Arow + k0n + c * 4);
                bReg[c] = *(const float4*)(W + (size_t)(k0n + wid + 8 * c) * DIM
                                           + n0 + lane * 4);
            }
        }

        // ---- compute on buffer p ----
        const uint32_t* A = As[p];
        const uint32_t* B = Bs[p];
        #pragma unroll
        for (int s = 0; s < 4; s++) {
            const int r0 = s * 8 + tig;
            const int r1 = r0 + 4;
            const int X  = tig << 3;
            uint32_t af[4][4];
            #pragma unroll
            for (int mt = 0; mt < 4; mt++) {
                const int bm = wm * 64 + mt * 16;
                af[mt][0] = A[r0 * 128 + ((bm + gid)     ^ X)];
                af[mt][1] = A[r0 * 128 + ((bm + gid + 8) ^ X)];
                af[mt][2] = A[r1 * 128 + ((bm + gid)     ^ X)];
                af[mt][3] = A[r1 * 128 + ((bm + gid + 8) ^ X)];
            }
            uint32_t bf[4][2];
            #pragma unroll
            for (int nt = 0; nt < 4; nt++) {
                const int bn = wn * 32 + nt * 8;
                bf[nt][0] = B[r0 * 128 + ((bn + gid) ^ X)];
                bf[nt][1] = B[r1 * 128 + ((bn + gid) ^ X)];
            }
            #pragma unroll
            for (int mt = 0; mt < 4; mt++)
                #pragma unroll
                for (int nt = 0; nt < 4; nt++)
                    mma_tf32(acc[mt][nt][0], acc[mt][nt][1],
                             acc[mt][nt][2], acc[mt][nt][3],
                             af[mt][0], af[mt][1], af[mt][2], af[mt][3],
                             bf[nt][0], bf[nt][1]);
        }
        __syncthreads();
    }

    // ---- epilogue: bias + scatter to [b, h, n, d] ----
    #pragma unroll
    for (int mt = 0; mt < 4; mt++) {
        const int m  = m0 + wm * 64 + mt * 16 + gid;
        const int bb = m >> 11;
        const int nn = m & (SEQ - 1);
        #pragma unroll
        for (int nt = 0; nt < 4; nt++) {
            const int n  = n0 + wn * 32 + nt * 8 + 2 * tig;
            const int hh = n >> 6;
            const int dd = n & 63;
            const float bx = bias[n], by = bias[n + 1];
            float* base = C + (((size_t)(bb * HEADS + hh) * SEQ) + nn) * DHEAD + dd;
            float2 v0 = make_float2(acc[mt][nt][0] + bx, acc[mt][nt][1] + by);
            float2 v1 = make_float2(acc[mt][nt][2] + bx, acc[mt][nt][3] + by);
            *(float2*)base = v0;
            *(float2*)(base + 8 * DHEAD) = v1;   // row m+8, same b/h
        }
    }
}

// ---------------------------------------------------------------------------
// Flash attention: 64-query x 64-key tiles, 256 threads (16x16),
// each thread owns a 4x4 output patch. 48KB static smem exactly.
// ---------------------------------------------------------------------------
__global__ __launch_bounds__(256) void attn_kernel(float* __restrict__ out)
{
    const int bh = blockIdx.y;              // 0..63
    const int q0 = blockIdx.x * 64;
    const float* Qb = g_q + (size_t)bh * SEQ * DHEAD;
    const float* Kb = g_k + (size_t)bh * SEQ * DHEAD;
    const float* Vb = g_v + (size_t)bh * SEQ * DHEAD;

    __shared__ float Qs[64][64];    // [row][d], pre-scaled
    __shared__ float KPs[64][64];   // K^T tile [d][key], reused as P [row][key]
    __shared__ float Vs[64][64];    // [key][d]

    const int tid = threadIdx.x;
    const int ty = tid >> 4, tx = tid & 15;
    const int lr = tid >> 2;            // load row 0..63
    const int lc = (tid & 3) << 4;      // load col base 0/16/32/48

    #pragma unroll
    for (int u = 0; u < 4; u++) {
        float4 qv = *(const float4*)(Qb + (size_t)(q0 + lr) * DHEAD + lc + u * 4);
        qv.x *= 0.125f; qv.y *= 0.125f; qv.z *= 0.125f; qv.w *= 0.125f;
        *(float4*)&Qs[lr][lc + u * 4] = qv;
    }

    float m_i[4], l_i[4];
    float4 o4[4];
    #pragma unroll
    for (int i = 0; i < 4; i++) {
        m_i[i] = -1e30f;
        l_i[i] = 0.f;
        o4[i] = make_float4(0.f, 0.f, 0.f, 0.f);
    }

    for (int kt = 0; kt < SEQ / 64; kt++) {
        const int k0 = kt * 64;
        __syncthreads();   // prior-iteration reads of KPs/Vs complete
        #pragma unroll
        for (int u = 0; u < 4; u++) {
            float4 kv = *(const float4*)(Kb + (size_t)(k0 + lr) * DHEAD + lc + u * 4);
            KPs[lc + u * 4 + 0][lr] = kv.x;
            KPs[lc + u * 4 + 1][lr] = kv.y;
            KPs[lc + u * 4 + 2][lr] = kv.z;
            KPs[lc + u * 4 + 3][lr] = kv.w;
            *(float4*)&Vs[lr][lc + u * 4] =
                *(const float4*)(Vb + (size_t)(k0 + lr) * DHEAD + lc + u * 4);
        }
        __syncthreads();

        // S = Q * K^T (4x4 per thread)
        float4 s4[4];
        #pragma unroll
        for (int i = 0; i < 4; i++) s4[i] = make_float4(0.f, 0.f, 0.f, 0.f);
        #pragma unroll
        for (int k4 = 0; k4 < 16; k4++) {
            float4 q[4], kv[4];
            #pragma unroll
            for (int i = 0; i < 4; i++)
                q[i] = *(const float4*)&Qs[ty * 4 + i][k4 * 4];
            #pragma unroll
            for (int kk = 0; kk < 4; kk++)
                kv[kk] = *(const float4*)&KPs[k4 * 4 + kk][tx * 4];
            #pragma unroll
            for (int i = 0; i < 4; i++) {
                s4[i] = f4fma(q[i].x, kv[0], s4[i]);
                s4[i] = f4fma(q[i].y, kv[1], s4[i]);
                s4[i] = f4fma(q[i].z, kv[2], s4[i]);
                s4[i] = f4fma(q[i].w, kv[3], s4[i]);
            }
        }
        __syncthreads();   // everyone done reading KPs before P overwrite

        // online softmax + write P into KPs
        #pragma unroll
        for (int i = 0; i < 4; i++) {
            float mx = fmaxf(fmaxf(s4[i].x, s4[i].y), fmaxf(s4[i].z, s4[i].w));
            #pragma unroll
            for (int off = 8; off; off >>= 1)
                mx = fmaxf(mx, __shfl_xor_sync(0xffffffffu, mx, off));
            const float mn = fmaxf(m_i[i], mx);
            const float alpha = __expf(m_i[i] - mn);
            m_i[i] = mn;
            float4 p;
            p.x = __expf(s4[i].x - mn);
            p.y = __expf(s4[i].y - mn);
            p.z = __expf(s4[i].z - mn);
            p.w = __expf(s4[i].w - mn);
            float rs = p.x + p.y + p.z + p.w;
            #pragma unroll
            for (int off = 8; off; off >>= 1)
                rs += __shfl_xor_sync(0xffffffffu, rs, off);
            l_i[i] = l_i[i] * alpha + rs;
            o4[i].x *= alpha; o4[i].y *= alpha; o4[i].z *= alpha; o4[i].w *= alpha;
            *(float4*)&KPs[ty * 4 + i][tx * 4] = p;
        }
        __syncthreads();

        // O += P * V
        #pragma unroll
        for (int k4 = 0; k4 < 16; k4++) {
            float4 p[4], vv[4];
            #pragma unroll
            for (int i = 0; i < 4; i++)
                p[i] = *(const float4*)&KPs[ty * 4 + i][k4 * 4];
            #pragma unroll
            for (int kk = 0; kk < 4; kk++)
                vv[kk] = *(const float4*)&Vs[k4 * 4 + kk][tx * 4];
            #pragma unroll
            for (int i = 0; i < 4; i++) {
                o4[i] = f4fma(p[i].x, vv[0], o4[i]);
                o4[i] = f4fma(p[i].y, vv[1], o4[i]);
                o4[i] = f4fma(p[i].z, vv[2], o4[i]);
                o4[i] = f4fma(p[i].w, vv[3], o4[i]);
            }
        }
    }

    // finalize + write output (b, n, h*64 + d)
    const int bb = bh >> 4, hh = bh & 15;
    #pragma unroll
    for (int i = 0; i < 4; i++) {
        const int row = q0 + ty * 4 + i;
        const float inv = 1.f / l_i[i];
        float4 ov;
        ov.x = o4[i].x * inv; ov.y = o4[i].y * inv;
        ov.z = o4[i].z * inv; ov.w = o4[i].w * inv;
        *(float4*)(out + ((size_t)bb * SEQ + row) * (HEADS * DHEAD)
                   + hh * DHEAD + tx * 4) = ov;
    }
}

// ---------------------------------------------------------------------------
extern "C" void kernel_launch(void* const* d_in, const int* in_sizes, int n_in,
                              void* d_out, int out_size) {
    const float* x    = (const float*)d_in[0];
    const float* ln_w = (const float*)d_in[1];
    const float* ln_b = (const float*)d_in[2];
    const float* wq   = (const float*)d_in[3];
    const float* bq   = (const float*)d_in[4];
    const float* wk   = (const float*)d_in[5];
    const float* bk   = (const float*)d_in[6];
    const float* wv   = (const float*)d_in[7];
    const float* bv   = (const float*)d_in[8];
    float* out = (float*)d_out;

    cudaFuncSetAttribute(qkv_gemm_mma,
                         cudaFuncAttributeMaxDynamicSharedMemorySize, 65536);

    ln_kernel<<<MTOT, 256>>>(x, ln_w, ln_b);
    qkv_gemm_mma<<<dim3(DIM / 128, MTOT / 128, 3), 256, 65536>>>(
        wq, bq, wk, bk, wv, bv);
    attn_kernel<<<dim3(SEQ / 64, BATCH * HEADS), 256>>>(out);
}

// round 4
// speedup vs baseline: 2.2822x; 1.9151x over previous
#include <cuda_runtime.h>
#include <cstdint>

#define DIM    1024
#define HEADS  16
#define DHEAD  64
#define BATCH  4
#define SEQ    2048
#define MTOT   (BATCH * SEQ)   // 8192

// Scratch (device globals: allocation-free)
__device__ float g_h[MTOT * DIM];
__device__ float g_q[MTOT * DIM];   // [b, h, n, d]
__device__ float g_k[MTOT * DIM];
__device__ float g_v[MTOT * DIM];

__device__ __forceinline__ uint32_t tf32_rn(float x) {
    uint32_t r;
    asm("cvt.rn.tf32.f32 %0, %1;" : "=r"(r) : "f"(x));
    return r;
}

__device__ __forceinline__ void mma_tf32(
    float& d0, float& d1, float& d2, float& d3,
    uint32_t a0, uint32_t a1, uint32_t a2, uint32_t a3,
    uint32_t b0, uint32_t b1)
{
    asm volatile(
        "mma.sync.aligned.m16n8k8.row.col.f32.tf32.tf32.f32 "
        "{%0,%1,%2,%3}, {%4,%5,%6,%7}, {%8,%9}, {%0,%1,%2,%3};"
        : "+f"(d0), "+f"(d1), "+f"(d2), "+f"(d3)
        : "r"(a0), "r"(a1), "r"(a2), "r"(a3), "r"(b0), "r"(b1));
}

// ---------------------------------------------------------------------------
// LayerNorm: one block per row, 256 threads, float4 per thread
// ---------------------------------------------------------------------------
__global__ __launch_bounds__(256) void ln_kernel(
    const float* __restrict__ x,
    const float* __restrict__ w,
    const float* __restrict__ bvec)
{
    const int row = blockIdx.x;
    const int t = threadIdx.x;
    float4 v = ((const float4*)(x + (size_t)row * DIM))[t];
    float s  = v.x + v.y + v.z + v.w;
    float ss = v.x * v.x + v.y * v.y + v.z * v.z + v.w * v.w;
    #pragma unroll
    for (int off = 16; off; off >>= 1) {
        s  += __shfl_xor_sync(0xffffffffu, s,  off);
        ss += __shfl_xor_sync(0xffffffffu, ss, off);
    }
    __shared__ float sh[16];
    const int wid = t >> 5, lane = t & 31;
    if (lane == 0) { sh[wid] = s; sh[8 + wid] = ss; }
    __syncthreads();
    float ts = 0.f, tss = 0.f;
    #pragma unroll
    for (int i = 0; i < 8; i++) { ts += sh[i]; tss += sh[8 + i]; }
    const float mu  = ts * (1.0f / DIM);
    const float var = tss * (1.0f / DIM) - mu * mu;
    const float r   = rsqrtf(var + 1e-5f);
    float4 wv = ((const float4*)w)[t];
    float4 bv = ((const float4*)bvec)[t];
    float4 o;
    o.x = (v.x - mu) * r * wv.x + bv.x;
    o.y = (v.y - mu) * r * wv.y + bv.y;
    o.z = (v.z - mu) * r * wv.z + bv.z;
    o.w = (v.w - mu) * r * wv.w + bv.w;
    ((float4*)(g_h + (size_t)row * DIM))[t] = o;
}

// ---------------------------------------------------------------------------
// QKV GEMM via mma.sync tf32 (m16n8k8), CTA tile 128x128, K-chunk 32,
// 8 warps in 2(m) x 4(n). Double-buffered smem with register prefetch.
// ---------------------------------------------------------------------------
__global__ __launch_bounds__(256) void qkv_gemm_mma(
    const float* __restrict__ Wq, const float* __restrict__ Bq,
    const float* __restrict__ Wk, const float* __restrict__ Bk,
    const float* __restrict__ Wv, const float* __restrict__ Bv)
{
    extern __shared__ uint32_t smem[];
    uint32_t* const As[2] = { smem,        smem + 4096 };
    uint32_t* const Bs[2] = { smem + 8192, smem + 12288 };

    const int which = blockIdx.z;
    const float* W    = (which == 0) ? Wq : (which == 1) ? Wk : Wv;
    const float* bias = (which == 0) ? Bq : (which == 1) ? Bk : Bv;
    float* C          = (which == 0) ? g_q : (which == 1) ? g_k : g_v;

    const int tid  = threadIdx.x;
    const int wid  = tid >> 5;
    const int lane = tid & 31;
    const int gid  = lane >> 2;      // 0..7
    const int tig  = lane & 3;       // 0..3
    const int wm   = wid & 1;        // 0..1  (64-row slab)
    const int wn   = wid >> 1;       // 0..3  (32-col slab)

    const int m0 = blockIdx.y * 128;
    const int n0 = blockIdx.x * 128;

    const int a_m = tid >> 1;
    const int a_k = (tid & 1) * 16;
    const float* Arow = g_h + (size_t)(m0 + a_m) * DIM + a_k;

    float acc[4][4][4];
    #pragma unroll
    for (int i = 0; i < 4; i++)
        #pragma unroll
        for (int j = 0; j < 4; j++)
            #pragma unroll
            for (int r = 0; r < 4; r++) acc[i][j][r] = 0.f;

    float4 aReg[4], bReg[4];

    #pragma unroll
    for (int c = 0; c < 4; c++) {
        aReg[c] = *(const float4*)(Arow + c * 4);
        bReg[c] = *(const float4*)(W + (size_t)(wid + 8 * c) * DIM + n0 + lane * 4);
    }

    const int NCHUNK = DIM / 32;
    #pragma unroll 1
    for (int i = 0; i < NCHUNK; ++i) {
        const int p = i & 1;
        {
            uint32_t* A = As[p];
            #pragma unroll
            for (int c = 0; c < 4; c++) {
                const int kl = a_k + c * 4;
                A[(kl + 0) * 128 + (a_m ^ 0)]  = tf32_rn(aReg[c].x);
                A[(kl + 1) * 128 + (a_m ^ 8)]  = tf32_rn(aReg[c].y);
                A[(kl + 2) * 128 + (a_m ^ 16)] = tf32_rn(aReg[c].z);
                A[(kl + 3) * 128 + (a_m ^ 24)] = tf32_rn(aReg[c].w);
            }
            uint32_t* B = Bs[p];
            #pragma unroll
            for (int c = 0; c < 4; c++) {
                const int k = wid + 8 * c;
                const int col = (lane * 4) ^ ((k & 3) << 3);
                uint4 u = make_uint4(tf32_rn(bReg[c].x), tf32_rn(bReg[c].y),
                                     tf32_rn(bReg[c].z), tf32_rn(bReg[c].w));
                *(uint4*)&B[k * 128 + col] = u;
            }
        }
        __syncthreads();

        if (i + 1 < NCHUNK) {
            const int k0n = (i + 1) * 32;
            #pragma unroll
            for (int c = 0; c < 4; c++) {
                aReg[c] = *(const float4*)(Arow + k0n + c * 4);
                bReg[c] = *(const float4*)(W + (size_t)(k0n + wid + 8 * c) * DIM
                                           + n0 + lane * 4);
            }
        }

        const uint32_t* A = As[p];
        const uint32_t* B = Bs[p];
        #pragma unroll
        for (int s = 0; s < 4; s++) {
            const int r0 = s * 8 + tig;
            const int r1 = r0 + 4;
            const int X  = tig << 3;
            uint32_t af[4][4];
            #pragma unroll
            for (int mt = 0; mt < 4; mt++) {
                const int bm = wm * 64 + mt * 16;
                af[mt][0] = A[r0 * 128 + ((bm + gid)     ^ X)];
                af[mt][1] = A[r0 * 128 + ((bm + gid + 8) ^ X)];
                af[mt][2] = A[r1 * 128 + ((bm + gid)     ^ X)];
                af[mt][3] = A[r1 * 128 + ((bm + gid + 8) ^ X)];
            }
            uint32_t bf[4][2];
            #pragma unroll
            for (int nt = 0; nt < 4; nt++) {
                const int bn = wn * 32 + nt * 8;
                bf[nt][0] = B[r0 * 128 + ((bn + gid) ^ X)];
                bf[nt][1] = B[r1 * 128 + ((bn + gid) ^ X)];
            }
            #pragma unroll
            for (int mt = 0; mt < 4; mt++)
                #pragma unroll
                for (int nt = 0; nt < 4; nt++)
                    mma_tf32(acc[mt][nt][0], acc[mt][nt][1],
                             acc[mt][nt][2], acc[mt][nt][3],
                             af[mt][0], af[mt][1], af[mt][2], af[mt][3],
                             bf[nt][0], bf[nt][1]);
        }
        __syncthreads();
    }

    #pragma unroll
    for (int mt = 0; mt < 4; mt++) {
        const int m  = m0 + wm * 64 + mt * 16 + gid;
        const int bb = m >> 11;
        const int nn = m & (SEQ - 1);
        #pragma unroll
        for (int nt = 0; nt < 4; nt++) {
            const int n  = n0 + wn * 32 + nt * 8 + 2 * tig;
            const int hh = n >> 6;
            const int dd = n & 63;
            const float bx = bias[n], by = bias[n + 1];
            float* base = C + (((size_t)(bb * HEADS + hh) * SEQ) + nn) * DHEAD + dd;
            float2 v0 = make_float2(acc[mt][nt][0] + bx, acc[mt][nt][1] + by);
            float2 v1 = make_float2(acc[mt][nt][2] + bx, acc[mt][nt][3] + by);
            *(float2*)base = v0;
            *(float2*)(base + 8 * DHEAD) = v1;   // row m+8, same b/h
        }
    }
}

// ---------------------------------------------------------------------------
// Flash attention on mma.sync tf32:
//   CTA = 128 Q rows of one (b,h); 8 warps x 16 rows; key tiles of 64.
//   SMEM (dynamic 64KB words):
//     Qs[128][64]  rotated: word = row*64 + (((d>>2 + row)&15)<<2) + (d&3)
//     Ks[64][64]   rotated by key (natural [key][d])
//     Vt[64][64]   transposed [d][key], rotated by d
//   All fragment LDS / loader STS conflict-free by construction.
// ---------------------------------------------------------------------------
__global__ __launch_bounds__(256) void attn_mma(float* __restrict__ out)
{
    extern __shared__ uint32_t sm[];
    uint32_t* Qs = sm;            // 8192 words
    uint32_t* Ks = sm + 8192;     // 4096 words
    uint32_t* Vt = sm + 12288;    // 4096 words

    const int bh = blockIdx.y;               // 0..63
    const int q0 = blockIdx.x * 128;
    const float* Qb = g_q + (size_t)bh * SEQ * DHEAD;
    const float* Kb = g_k + (size_t)bh * SEQ * DHEAD;
    const float* Vb = g_v + (size_t)bh * SEQ * DHEAD;

    const int tid  = threadIdx.x;
    const int wid  = tid >> 5, lane = tid & 31;
    const int g    = lane >> 2, t = lane & 3;
    const int wrow = wid * 16;

    // ---- stage Q (x 1/8 scale, tf32, rotated) ----
    {
        const int row  = tid & 127;
        const int half = tid >> 7;             // 0..1
        const float* src = Qb + (size_t)(q0 + row) * DHEAD;
        #pragma unroll
        for (int i = 0; i < 8; i++) {
            const int c = half * 8 + i;        // chunk 0..15
            float4 v = *(const float4*)(src + c * 4);
            uint4 u = make_uint4(tf32_rn(v.x * 0.125f), tf32_rn(v.y * 0.125f),
                                 tf32_rn(v.z * 0.125f), tf32_rn(v.w * 0.125f));
            *(uint4*)&Qs[row * 64 + (((c + row) & 15) << 2)] = u;
        }
    }

    // ---- prefetch K/V tile 0 ----
    const int lkey = tid & 63;
    const int lq   = tid >> 6;                 // 0..3
    float4 kr[4], vr[4];
    {
        const float* ksrc = Kb + (size_t)lkey * DHEAD;
        const float* vsrc = Vb + (size_t)lkey * DHEAD;
        #pragma unroll
        for (int i = 0; i < 4; i++) {
            kr[i] = *(const float4*)(ksrc + (lq * 4 + i) * 4);
            vr[i] = *(const float4*)(vsrc + lq * 16 + i * 4);
        }
    }
    __syncthreads();

    // ---- Q fragments (persistent in regs) ----
    uint32_t qf[8][4];
    {
        const int r0 = wrow + g, r1 = r0 + 8;
        #pragma unroll
        for (int ks = 0; ks < 8; ks++) {
            qf[ks][0] = Qs[r0 * 64 + (((2 * ks     + r0) & 15) << 2) + t];
            qf[ks][1] = Qs[r1 * 64 + (((2 * ks     + r1) & 15) << 2) + t];
            qf[ks][2] = Qs[r0 * 64 + (((2 * ks + 1 + r0) & 15) << 2) + t];
            qf[ks][3] = Qs[r1 * 64 + (((2 * ks + 1 + r1) & 15) << 2) + t];
        }
    }

    float o[8][4];
    #pragma unroll
    for (int nt = 0; nt < 8; nt++)
        #pragma unroll
        for (int r = 0; r < 4; r++) o[nt][r] = 0.f;
    float m0 = -1e30f, m1 = -1e30f, l0 = 0.f, l1 = 0.f;

    #pragma unroll 1
    for (int kt = 0; kt < SEQ / 64; kt++) {
        __syncthreads();   // previous compute done reading Ks/Vt
        // store K tile (rotated, tf32)
        #pragma unroll
        for (int i = 0; i < 4; i++) {
            const int c = lq * 4 + i;
            uint4 u = make_uint4(tf32_rn(kr[i].x), tf32_rn(kr[i].y),
                                 tf32_rn(kr[i].z), tf32_rn(kr[i].w));
            *(uint4*)&Ks[lkey * 64 + (((c + lkey) & 15) << 2)] = u;
        }
        // store V transposed (rotated by d, tf32)
        #pragma unroll
        for (int i = 0; i < 4; i++) {
            const int d = lq * 16 + i * 4;
            const int kq = lkey >> 2, k3 = lkey & 3;
            Vt[(d + 0) * 64 + (((kq + d + 0) & 15) << 2) + k3] = tf32_rn(vr[i].x);
            Vt[(d + 1) * 64 + (((kq + d + 1) & 15) << 2) + k3] = tf32_rn(vr[i].y);
            Vt[(d + 2) * 64 + (((kq + d + 2) & 15) << 2) + k3] = tf32_rn(vr[i].z);
            Vt[(d + 3) * 64 + (((kq + d + 3) & 15) << 2) + k3] = tf32_rn(vr[i].w);
        }
        __syncthreads();

        // prefetch next tile
        if (kt + 1 < SEQ / 64) {
            const float* ksrc = Kb + (size_t)((kt + 1) * 64 + lkey) * DHEAD;
            const float* vsrc = Vb + (size_t)((kt + 1) * 64 + lkey) * DHEAD;
            #pragma unroll
            for (int i = 0; i < 4; i++) {
                kr[i] = *(const float4*)(ksrc + (lq * 4 + i) * 4);
                vr[i] = *(const float4*)(vsrc + lq * 16 + i * 4);
            }
        }

        // ---- S = Q K^T ----
        float s[8][4];
        #pragma unroll
        for (int nt = 0; nt < 8; nt++)
            #pragma unroll
            for (int r = 0; r < 4; r++) s[nt][r] = 0.f;
        #pragma unroll
        for (int ks = 0; ks < 8; ks++) {
            #pragma unroll
            for (int nt = 0; nt < 8; nt++) {
                const int key = nt * 8 + g;
                uint32_t b0 = Ks[key * 64 + (((2 * ks     + key) & 15) << 2) + t];
                uint32_t b1 = Ks[key * 64 + (((2 * ks + 1 + key) & 15) << 2) + t];
                mma_tf32(s[nt][0], s[nt][1], s[nt][2], s[nt][3],
                         qf[ks][0], qf[ks][1], qf[ks][2], qf[ks][3], b0, b1);
            }
        }

        // ---- online softmax (rows g / g+8 of warp tile) ----
        float mx0 = -1e30f, mx1 = -1e30f;
        #pragma unroll
        for (int nt = 0; nt < 8; nt++) {
            mx0 = fmaxf(mx0, fmaxf(s[nt][0], s[nt][1]));
            mx1 = fmaxf(mx1, fmaxf(s[nt][2], s[nt][3]));
        }
        #pragma unroll
        for (int off = 1; off <= 2; off <<= 1) {
            mx0 = fmaxf(mx0, __shfl_xor_sync(0xffffffffu, mx0, off));
            mx1 = fmaxf(mx1, __shfl_xor_sync(0xffffffffu, mx1, off));
        }
        const float mn0 = fmaxf(m0, mx0);
        const float mn1 = fmaxf(m1, mx1);
        const float al0 = __expf(m0 - mn0);
        const float al1 = __expf(m1 - mn1);
        m0 = mn0; m1 = mn1;
        float sum0 = 0.f, sum1 = 0.f;
        #pragma unroll
        for (int nt = 0; nt < 8; nt++) {
            s[nt][0] = __expf(s[nt][0] - mn0);
            s[nt][1] = __expf(s[nt][1] - mn0);
            s[nt][2] = __expf(s[nt][2] - mn1);
            s[nt][3] = __expf(s[nt][3] - mn1);
            sum0 += s[nt][0] + s[nt][1];
            sum1 += s[nt][2] + s[nt][3];
        }
        #pragma unroll
        for (int off = 1; off <= 2; off <<= 1) {
            sum0 += __shfl_xor_sync(0xffffffffu, sum0, off);
            sum1 += __shfl_xor_sync(0xffffffffu, sum1, off);
        }
        l0 = l0 * al0 + sum0;
        l1 = l1 * al1 + sum1;
        #pragma unroll
        for (int nt = 0; nt < 8; nt++) {
            o[nt][0] *= al0; o[nt][1] *= al0;
            o[nt][2] *= al1; o[nt][3] *= al1;
        }

        // ---- O += P V ----
        const int src  = (lane & ~3) | (t >> 1);
        const int src2 = src + 2;
        #pragma unroll
        for (int ks = 0; ks < 8; ks++) {
            // C-layout (cols 2t,2t+1) -> A-layout (cols t,t+4) via quad shuffles
            float x0 = __shfl_sync(0xffffffffu, s[ks][0], src);
            float x1 = __shfl_sync(0xffffffffu, s[ks][1], src);
            float y0 = __shfl_sync(0xffffffffu, s[ks][0], src2);
            float y1 = __shfl_sync(0xffffffffu, s[ks][1], src2);
            float z0 = __shfl_sync(0xffffffffu, s[ks][2], src);
            float z1 = __shfl_sync(0xffffffffu, s[ks][3], src);
            float w0 = __shfl_sync(0xffffffffu, s[ks][2], src2);
            float w1 = __shfl_sync(0xffffffffu, s[ks][3], src2);
            const uint32_t a0 = tf32_rn((t & 1) ? x1 : x0);
            const uint32_t a2 = tf32_rn((t & 1) ? y1 : y0);
            const uint32_t a1 = tf32_rn((t & 1) ? z1 : z0);
            const uint32_t a3 = tf32_rn((t & 1) ? w1 : w0);
            #pragma unroll
            for (int nt = 0; nt < 8; nt++) {
                const int d = nt * 8 + g;
                uint32_t b0 = Vt[d * 64 + (((2 * ks     + d) & 15) << 2) + t];
                uint32_t b1 = Vt[d * 64 + (((2 * ks + 1 + d) & 15) << 2) + t];
                mma_tf32(o[nt][0], o[nt][1], o[nt][2], o[nt][3],
                         a0, a1, a2, a3, b0, b1);
            }
        }
    }

    // ---- epilogue ----
    const int bb = bh >> 4, hh = bh & 15;
    const float inv0 = 1.f / l0, inv1 = 1.f / l1;
    const int r0 = q0 + wrow + g, r1 = r0 + 8;
    #pragma unroll
    for (int nt = 0; nt < 8; nt++) {
        const int d = hh * DHEAD + nt * 8 + 2 * t;
        *(float2*)(out + ((size_t)bb * SEQ + r0) * (HEADS * DHEAD) + d) =
            make_float2(o[nt][0] * inv0, o[nt][1] * inv0);
        *(float2*)(out + ((size_t)bb * SEQ + r1) * (HEADS * DHEAD) + d) =
            make_float2(o[nt][2] * inv1, o[nt][3] * inv1);
    }
}

// ---------------------------------------------------------------------------
extern "C" void kernel_launch(void* const* d_in, const int* in_sizes, int n_in,
                              void* d_out, int out_size) {
    const float* x    = (const float*)d_in[0];
    const float* ln_w = (const float*)d_in[1];
    const float* ln_b = (const float*)d_in[2];
    const float* wq   = (const float*)d_in[3];
    const float* bq   = (const float*)d_in[4];
    const float* wk   = (const float*)d_in[5];
    const float* bk   = (const float*)d_in[6];
    const float* wv   = (const float*)d_in[7];
    const float* bv   = (const float*)d_in[8];
    float* out = (float*)d_out;

    cudaFuncSetAttribute(qkv_gemm_mma,
                         cudaFuncAttributeMaxDynamicSharedMemorySize, 65536);
    cudaFuncSetAttribute(attn_mma,
                         cudaFuncAttributeMaxDynamicSharedMemorySize, 65536);

    ln_kernel<<<MTOT, 256>>>(x, ln_w, ln_b);
    qkv_gemm_mma<<<dim3(DIM / 128, MTOT / 128, 3), 256, 65536>>>(
        wq, bq, wk, bk, wv, bv);
    attn_mma<<<dim3(SEQ / 128, BATCH * HEADS), 256, 65536>>>(out);
}

// round 5
// speedup vs baseline: 2.3379x; 1.0244x over previous
#include <cuda_runtime.h>
#include <cstdint>

#define DIM    1024
#define HEADS  16
#define DHEAD  64
#define BATCH  4
#define SEQ    2048
#define MTOT   (BATCH * SEQ)   // 8192

// Scratch (device globals). g_h/g_q/g_k/g_v/g_wt hold tf32 BITS (as float storage).
__device__ float g_h[MTOT * DIM];
__device__ float g_q[MTOT * DIM];   // [b, h, n, d], tf32 bits, q pre-scaled by 0.125
__device__ float g_k[MTOT * DIM];
__device__ float g_v[MTOT * DIM];
__device__ float g_wt[3 * DIM * DIM];

__device__ __forceinline__ uint32_t tf32_rn(float x) {
    uint32_t r;
    asm("cvt.rn.tf32.f32 %0, %1;" : "=r"(r) : "f"(x));
    return r;
}

__device__ __forceinline__ void mma_tf32(
    float& d0, float& d1, float& d2, float& d3,
    uint32_t a0, uint32_t a1, uint32_t a2, uint32_t a3,
    uint32_t b0, uint32_t b1)
{
    asm volatile(
        "mma.sync.aligned.m16n8k8.row.col.f32.tf32.tf32.f32 "
        "{%0,%1,%2,%3}, {%4,%5,%6,%7}, {%8,%9}, {%0,%1,%2,%3};"
        : "+f"(d0), "+f"(d1), "+f"(d2), "+f"(d3)
        : "r"(a0), "r"(a1), "r"(a2), "r"(a3), "r"(b0), "r"(b1));
}

// store pair-interleaved chunk: words [u.x,v.x,u.y,v.y,u.z,v.z,u.w,v.w]
__device__ __forceinline__ void sts_pair(uint32_t* base, uint4 u, uint4 v) {
    *(uint4*)(base)     = make_uint4(u.x, v.x, u.y, v.y);
    *(uint4*)(base + 4) = make_uint4(u.z, v.z, u.w, v.w);
}

// ---------------------------------------------------------------------------
// LayerNorm -> tf32 bits in g_h
// ---------------------------------------------------------------------------
__global__ __launch_bounds__(256) void ln_kernel(
    const float* __restrict__ x,
    const float* __restrict__ w,
    const float* __restrict__ bvec)
{
    const int row = blockIdx.x;
    const int t = threadIdx.x;
    float4 v = ((const float4*)(x + (size_t)row * DIM))[t];
    float s  = v.x + v.y + v.z + v.w;
    float ss = v.x * v.x + v.y * v.y + v.z * v.z + v.w * v.w;
    #pragma unroll
    for (int off = 16; off; off >>= 1) {
        s  += __shfl_xor_sync(0xffffffffu, s,  off);
        ss += __shfl_xor_sync(0xffffffffu, ss, off);
    }
    __shared__ float sh[16];
    const int wid = t >> 5, lane = t & 31;
    if (lane == 0) { sh[wid] = s; sh[8 + wid] = ss; }
    __syncthreads();
    float ts = 0.f, tss = 0.f;
    #pragma unroll
    for (int i = 0; i < 8; i++) { ts += sh[i]; tss += sh[8 + i]; }
    const float mu  = ts * (1.0f / DIM);
    const float var = tss * (1.0f / DIM) - mu * mu;
    const float r   = rsqrtf(var + 1e-5f);
    float4 wv = ((const float4*)w)[t];
    float4 bv = ((const float4*)bvec)[t];
    uint4 o;
    o.x = tf32_rn((v.x - mu) * r * wv.x + bv.x);
    o.y = tf32_rn((v.y - mu) * r * wv.y + bv.y);
    o.z = tf32_rn((v.z - mu) * r * wv.z + bv.z);
    o.w = tf32_rn((v.w - mu) * r * wv.w + bv.w);
    ((uint4*)(g_h + (size_t)row * DIM))[t] = o;
}

// ---------------------------------------------------------------------------
// One-shot weight converter: wq/wk/wv fp32 -> tf32 bits in g_wt
// ---------------------------------------------------------------------------
__global__ __launch_bounds__(256) void cvt_w(
    const float* __restrict__ Wq,
    const float* __restrict__ Wk,
    const float* __restrict__ Wv)
{
    const int z = blockIdx.y;
    const float* src = (z == 0) ? Wq : (z == 1) ? Wk : Wv;
    const size_t idx = (size_t)blockIdx.x * 256 + threadIdx.x;
    float4 v = ((const float4*)src)[idx];
    uint4 u = make_uint4(tf32_rn(v.x), tf32_rn(v.y), tf32_rn(v.z), tf32_rn(v.w));
    ((uint4*)(g_wt + (size_t)z * DIM * DIM))[idx] = u;
}

// ---------------------------------------------------------------------------
// QKV GEMM via mma.sync tf32 (m16n8k8), CTA tile 128x128, K-chunk 32,
// 8 warps in 2(m) x 4(n). Inputs pre-converted tf32 bits (no cvt in loop).
//   As: [m 0..127][k-chunk c 0..7], 16B chunk at word m*32 + ((c ^ (m&7))<<2)
//   Bs: [k 0..31][n], word (k,n) at k*128 + (n ^ ((k&3)<<3))
// Epilogue: bias (fp32) + tf32-convert + scatter to [b,h,n,d] (q scaled 1/8).
// ---------------------------------------------------------------------------
__global__ __launch_bounds__(256) void qkv_gemm_mma(
    const float* __restrict__ Bq,
    const float* __restrict__ Bk,
    const float* __restrict__ Bv)
{
    extern __shared__ uint32_t smem[];
    uint32_t* const As[2] = { smem,        smem + 4096 };
    uint32_t* const Bs[2] = { smem + 8192, smem + 12288 };

    const int which = blockIdx.z;
    const uint32_t* W = (const uint32_t*)g_wt + (size_t)which * DIM * DIM;
    const float* bias = (which == 0) ? Bq : (which == 1) ? Bk : Bv;
    float* C          = (which == 0) ? g_q : (which == 1) ? g_k : g_v;
    const float qscale = (which == 0) ? 0.125f : 1.0f;

    const int tid  = threadIdx.x;
    const int wid  = tid >> 5;
    const int lane = tid & 31;
    const int gid  = lane >> 2;      // 0..7
    const int tig  = lane & 3;       // 0..3
    const int wm   = wid & 1;        // 0..1  (64-row slab)
    const int wn   = wid >> 1;       // 0..3  (32-col slab)

    const int m0 = blockIdx.y * 128;
    const int n0 = blockIdx.x * 128;

    const int a_m = tid >> 1;            // 0..127
    const int a_c = (tid & 1) * 4;       // chunk base 0 or 4
    const uint32_t* Arow = (const uint32_t*)g_h + (size_t)(m0 + a_m) * DIM + a_c * 4;

    float acc[4][4][4];
    #pragma unroll
    for (int i = 0; i < 4; i++)
        #pragma unroll
        for (int j = 0; j < 4; j++)
            #pragma unroll
            for (int r = 0; r < 4; r++) acc[i][j][r] = 0.f;

    uint4 aReg[4], bReg[4];

    #pragma unroll
    for (int c = 0; c < 4; c++) {
        aReg[c] = *(const uint4*)(Arow + c * 4);
        bReg[c] = *(const uint4*)(W + (size_t)(wid + 8 * c) * DIM + n0 + lane * 4);
    }

    const int NCHUNK = DIM / 32;
    #pragma unroll 1
    for (int i = 0; i < NCHUNK; ++i) {
        const int p = i & 1;
        {
            uint32_t* A = As[p];
            const int r7 = a_m & 7;
            #pragma unroll
            for (int c = 0; c < 4; c++)
                *(uint4*)&A[a_m * 32 + (((a_c + c) ^ r7) << 2)] = aReg[c];
            uint32_t* B = Bs[p];
            #pragma unroll
            for (int c = 0; c < 4; c++) {
                const int k = wid + 8 * c;
                const int col = (lane * 4) ^ ((k & 3) << 3);
                *(uint4*)&B[k * 128 + col] = bReg[c];
            }
        }
        __syncthreads();

        if (i + 1 < NCHUNK) {
            const int k0n = (i + 1) * 32;
            #pragma unroll
            for (int c = 0; c < 4; c++) {
                aReg[c] = *(const uint4*)(Arow + k0n + c * 4);
                bReg[c] = *(const uint4*)(W + (size_t)(k0n + wid + 8 * c) * DIM
                                          + n0 + lane * 4);
            }
        }

        const uint32_t* A = As[p];
        const uint32_t* B = Bs[p];
        #pragma unroll
        for (int s = 0; s < 4; s++) {
            const int r0 = s * 8 + tig;
            const int r1 = r0 + 4;
            const int X  = tig << 3;
            const int w0 = ((2 * s)     ^ gid) << 2;
            const int w1 = ((2 * s + 1) ^ gid) << 2;
            uint32_t af[4][4];
            #pragma unroll
            for (int mt = 0; mt < 4; mt++) {
                const int mr = wm * 64 + mt * 16 + gid;
                af[mt][0] = A[mr * 32       + w0 + tig];
                af[mt][1] = A[(mr + 8) * 32 + w0 + tig];
                af[mt][2] = A[mr * 32       + w1 + tig];
                af[mt][3] = A[(mr + 8) * 32 + w1 + tig];
            }
            uint32_t bf[4][2];
            #pragma unroll
            for (int nt = 0; nt < 4; nt++) {
                const int bn = wn * 32 + nt * 8;
                bf[nt][0] = B[r0 * 128 + ((bn + gid) ^ X)];
                bf[nt][1] = B[r1 * 128 + ((bn + gid) ^ X)];
            }
            #pragma unroll
            for (int mt = 0; mt < 4; mt++)
                #pragma unroll
                for (int nt = 0; nt < 4; nt++)
                    mma_tf32(acc[mt][nt][0], acc[mt][nt][1],
                             acc[mt][nt][2], acc[mt][nt][3],
                             af[mt][0], af[mt][1], af[mt][2], af[mt][3],
                             bf[nt][0], bf[nt][1]);
        }
        __syncthreads();
    }

    // epilogue: +bias (fp32), scale (q), tf32-convert, scatter [b,h,n,d]
    #pragma unroll
    for (int mt = 0; mt < 4; mt++) {
        const int m  = m0 + wm * 64 + mt * 16 + gid;
        const int bb = m >> 11;
        const int nn = m & (SEQ - 1);
        #pragma unroll
        for (int nt = 0; nt < 4; nt++) {
            const int n  = n0 + wn * 32 + nt * 8 + 2 * tig;
            const int hh = n >> 6;
            const int dd = n & 63;
            const float bx = bias[n], by = bias[n + 1];
            float* base = C + (((size_t)(bb * HEADS + hh) * SEQ) + nn) * DHEAD + dd;
            uint2 v0 = make_uint2(tf32_rn((acc[mt][nt][0] + bx) * qscale),
                                  tf32_rn((acc[mt][nt][1] + by) * qscale));
            uint2 v1 = make_uint2(tf32_rn((acc[mt][nt][2] + bx) * qscale),
                                  tf32_rn((acc[mt][nt][3] + by) * qscale));
            *(uint2*)base = v0;
            *(uint2*)(base + 8 * DHEAD) = v1;   // row m+8, same b/h
        }
    }
}

// ---------------------------------------------------------------------------
// Flash attention on mma.sync tf32. Pair-interleaved smem layouts:
//   For row r, k-chunk ks (d = 8ks..8ks+7), slot = (ks + (r&7)) & 7:
//     words r*64 + slot*8 + 2t   = elem d = 8ks+t
//     words r*64 + slot*8 + 2t+1 = elem d = 8ks+4+t
//   -> every MMA B/A-row fragment is ONE LDS.64, conflict-free per 16-lane phase.
//   Qs: 128 rows (8192 w), Ks: 64 rows (4096 w), Vs (key-major pairs over keys,
//   d as "row"): 64 rows (4096 w). Total 64KB dynamic.
// ---------------------------------------------------------------------------
__global__ __launch_bounds__(256) void attn_mma(float* __restrict__ out)
{
    extern __shared__ uint32_t sm[];
    uint32_t* Qs = sm;            // 8192 words
    uint32_t* Ks = sm + 8192;     // 4096 words
    uint32_t* Vs = sm + 12288;    // 4096 words

    const int bh = blockIdx.y;               // 0..63
    const int q0 = blockIdx.x * 128;
    const uint32_t* Qb = (const uint32_t*)g_q + (size_t)bh * SEQ * DHEAD;
    const uint32_t* Kb = (const uint32_t*)g_k + (size_t)bh * SEQ * DHEAD;
    const uint32_t* Vb = (const uint32_t*)g_v + (size_t)bh * SEQ * DHEAD;

    const int tid  = threadIdx.x;
    const int wid  = tid >> 5, lane = tid & 31;
    const int g    = lane >> 2, t = lane & 3;
    const int wrow = wid * 16;

    // ---- stage Q (already tf32 + 1/8-scaled): pair-interleaved ----
    {
        const int row  = tid & 127;
        const int half = tid >> 7;             // 0..1
        const uint32_t* src = Qb + (size_t)(q0 + row) * DHEAD + half * 32;
        const int r7 = row & 7;
        #pragma unroll
        for (int j = 0; j < 4; j++) {
            uint4 u = *(const uint4*)(src + j * 8);
            uint4 v = *(const uint4*)(src + j * 8 + 4);
            const int ks = half * 4 + j;
            sts_pair(&Qs[row * 64 + (((ks + r7) & 7) << 3)], u, v);
        }
    }

    // ---- prefetch K/V tile 0 ----
    const int lkey = tid & 63;
    const int lq   = tid >> 6;                 // 0..3 (d-block of 16)
    uint4 kr[4], vr[4];
    {
        const uint32_t* ksrc = Kb + (size_t)lkey * DHEAD + lq * 16;
        const uint32_t* vsrc = Vb + (size_t)lkey * DHEAD + lq * 16;
        #pragma unroll
        for (int i = 0; i < 4; i++) {
            kr[i] = *(const uint4*)(ksrc + i * 4);
            vr[i] = *(const uint4*)(vsrc + i * 4);
        }
    }

    float o[8][4];
    #pragma unroll
    for (int nt = 0; nt < 8; nt++)
        #pragma unroll
        for (int r = 0; r < 4; r++) o[nt][r] = 0.f;
    float m0 = -1e30f, m1 = -1e30f, l0 = 0.f, l1 = 0.f;

    // V scatter constants (thread writes its key's 16 d-values into pair slots)
    const int ksv  = lkey >> 3;
    const int w7   = lkey & 7;
    const int lohi = w7 >> 2;              // 0 = lo of pair, 1 = hi
    const int toff = 2 * (w7 & 3) + lohi;  // word offset within slot

    #pragma unroll 1
    for (int kt = 0; kt < SEQ / 64; kt++) {
        __syncthreads();   // previous compute done reading Ks/Vs (and Q stage on kt=0)
        // K: pair-interleaved rows
        {
            const int r7 = lkey & 7;
            #pragma unroll
            for (int j = 0; j < 2; j++) {
                const int ks = 2 * lq + j;
                sts_pair(&Ks[lkey * 64 + (((ks + r7) & 7) << 3)],
                         kr[2 * j], kr[2 * j + 1]);
            }
        }
        // V: scalar scatter into d-major pair rows
        #pragma unroll
        for (int i = 0; i < 4; i++) {
            const uint32_t vv[4] = { vr[i].x, vr[i].y, vr[i].z, vr[i].w };
            #pragma unroll
            for (int e = 0; e < 4; e++) {
                const int d = lq * 16 + i * 4 + e;
                Vs[d * 64 + (((ksv + (d & 7)) & 7) << 3) + toff] = vv[e];
            }
        }
        __syncthreads();

        // prefetch next tile
        if (kt + 1 < SEQ / 64) {
            const uint32_t* ksrc = Kb + (size_t)((kt + 1) * 64 + lkey) * DHEAD + lq * 16;
            const uint32_t* vsrc = Vb + (size_t)((kt + 1) * 64 + lkey) * DHEAD + lq * 16;
            #pragma unroll
            for (int i = 0; i < 4; i++) {
                kr[i] = *(const uint4*)(ksrc + i * 4);
                vr[i] = *(const uint4*)(vsrc + i * 4);
            }
        }

        // ---- S = Q K^T ----
        const int r0 = wrow + g, r1 = r0 + 8;   // r0&7 == r1&7 == g
        float s[8][4];
        #pragma unroll
        for (int nt = 0; nt < 8; nt++)
            #pragma unroll
            for (int r = 0; r < 4; r++) s[nt][r] = 0.f;
        #pragma unroll
        for (int ks = 0; ks < 8; ks++) {
            const int slot = (((ks + g) & 7) << 3) + 2 * t;
            uint2 qa = *(const uint2*)&Qs[r0 * 64 + slot];
            uint2 qb = *(const uint2*)&Qs[r1 * 64 + slot];
            #pragma unroll
            for (int nt = 0; nt < 8; nt++) {
                uint2 bb = *(const uint2*)&Ks[(nt * 8 + g) * 64 + slot];
                mma_tf32(s[nt][0], s[nt][1], s[nt][2], s[nt][3],
                         qa.x, qb.x, qa.y, qb.y, bb.x, bb.y);
            }
        }

        // ---- online softmax ----
        float mx0 = -1e30f, mx1 = -1e30f;
        #pragma unroll
        for (int nt = 0; nt < 8; nt++) {
            mx0 = fmaxf(mx0, fmaxf(s[nt][0], s[nt][1]));
            mx1 = fmaxf(mx1, fmaxf(s[nt][2], s[nt][3]));
        }
        #pragma unroll
        for (int off = 1; off <= 2; off <<= 1) {
            mx0 = fmaxf(mx0, __shfl_xor_sync(0xffffffffu, mx0, off));
            mx1 = fmaxf(mx1, __shfl_xor_sync(0xffffffffu, mx1, off));
        }
        const float mn0 = fmaxf(m0, mx0);
        const float mn1 = fmaxf(m1, mx1);
        const float al0 = __expf(m0 - mn0);
        const float al1 = __expf(m1 - mn1);
        m0 = mn0; m1 = mn1;
        float sum0 = 0.f, sum1 = 0.f;
        #pragma unroll
        for (int nt = 0; nt < 8; nt++) {
            s[nt][0] = __expf(s[nt][0] - mn0);
            s[nt][1] = __expf(s[nt][1] - mn0);
            s[nt][2] = __expf(s[nt][2] - mn1);
            s[nt][3] = __expf(s[nt][3] - mn1);
            sum0 += s[nt][0] + s[nt][1];
            sum1 += s[nt][2] + s[nt][3];
        }
        #pragma unroll
        for (int off = 1; off <= 2; off <<= 1) {
            sum0 += __shfl_xor_sync(0xffffffffu, sum0, off);
            sum1 += __shfl_xor_sync(0xffffffffu, sum1, off);
        }
        l0 = l0 * al0 + sum0;
        l1 = l1 * al1 + sum1;
        #pragma unroll
        for (int nt = 0; nt < 8; nt++) {
            o[nt][0] *= al0; o[nt][1] *= al0;
            o[nt][2] *= al1; o[nt][3] *= al1;
        }

        // ---- O += P V ----
        const int src  = (lane & ~3) | (t >> 1);
        const int src2 = src + 2;
        #pragma unroll
        for (int ks = 0; ks < 8; ks++) {
            // C-layout (cols 2t,2t+1) -> A-layout (cols t,t+4) via quad shuffles
            float x0 = __shfl_sync(0xffffffffu, s[ks][0], src);
            float x1 = __shfl_sync(0xffffffffu, s[ks][1], src);
            float y0 = __shfl_sync(0xffffffffu, s[ks][0], src2);
            float y1 = __shfl_sync(0xffffffffu, s[ks][1], src2);
            float z0 = __shfl_sync(0xffffffffu, s[ks][2], src);
            float z1 = __shfl_sync(0xffffffffu, s[ks][3], src);
            float w0 = __shfl_sync(0xffffffffu, s[ks][2], src2);
            float w1 = __shfl_sync(0xffffffffu, s[ks][3], src2);
            const uint32_t a0 = tf32_rn((t & 1) ? x1 : x0);
            const uint32_t a2 = tf32_rn((t & 1) ? y1 : y0);
            const uint32_t a1 = tf32_rn((t & 1) ? z1 : z0);
            const uint32_t a3 = tf32_rn((t & 1) ? w1 : w0);
            const int slot = (((ks + g) & 7) << 3) + 2 * t;
            #pragma unroll
            for (int nt = 0; nt < 8; nt++) {
                uint2 vb = *(const uint2*)&Vs[(nt * 8 + g) * 64 + slot];
                mma_tf32(o[nt][0], o[nt][1], o[nt][2], o[nt][3],
                         a0, a1, a2, a3, vb.x, vb.y);
            }
        }
    }

    // ---- epilogue ----
    const int bb = bh >> 4, hh = bh & 15;
    const float inv0 = 1.f / l0, inv1 = 1.f / l1;
    const int rr0 = q0 + wrow + g, rr1 = rr0 + 8;
    #pragma unroll
    for (int nt = 0; nt < 8; nt++) {
        const int d = hh * DHEAD + nt * 8 + 2 * t;
        *(float2*)(out + ((size_t)bb * SEQ + rr0) * (HEADS * DHEAD) + d) =
            make_float2(o[nt][0] * inv0, o[nt][1] * inv0);
        *(float2*)(out + ((size_t)bb * SEQ + rr1) * (HEADS * DHEAD) + d) =
            make_float2(o[nt][2] * inv1, o[nt][3] * inv1);
    }
}

// ---------------------------------------------------------------------------
extern "C" void kernel_launch(void* const* d_in, const int* in_sizes, int n_in,
                              void* d_out, int out_size) {
    const float* x    = (const float*)d_in[0];
    const float* ln_w = (const float*)d_in[1];
    const float* ln_b = (const float*)d_in[2];
    const float* wq   = (const float*)d_in[3];
    const float* bq   = (const float*)d_in[4];
    const float* wk   = (const float*)d_in[5];
    const float* bk   = (const float*)d_in[6];
    const float* wv   = (const float*)d_in[7];
    const float* bv   = (const float*)d_in[8];
    float* out = (float*)d_out;

    cudaFuncSetAttribute(qkv_gemm_mma,
                         cudaFuncAttributeMaxDynamicSharedMemorySize, 65536);
    cudaFuncSetAttribute(attn_mma,
                         cudaFuncAttributeMaxDynamicSharedMemorySize, 65536);

    ln_kernel<<<MTOT, 256>>>(x, ln_w, ln_b);
    cvt_w<<<dim3(DIM * DIM / (256 * 4), 3), 256>>>(wq, wk, wv);
    qkv_gemm_mma<<<dim3(DIM / 128, MTOT / 128, 3), 256, 65536>>>(bq, bk, bv);
    attn_mma<<<dim3(SEQ / 128, BATCH * HEADS), 256, 65536>>>(out);
}

// round 6
// speedup vs baseline: 2.5836x; 1.1051x over previous
#include <cuda_runtime.h>
#include <cstdint>

#define DIM    1024
#define HEADS  16
#define DHEAD  64
#define BATCH  4
#define SEQ    2048
#define MTOT   (BATCH * SEQ)   // 8192

// Scratch (device globals). g_h/g_q/g_k/g_v/g_wt hold tf32 BITS (as float storage).
__device__ float g_h[MTOT * DIM];
__device__ float g_q[MTOT * DIM];   // [b, h, n, d], tf32 bits, q pre-scaled by 0.125
__device__ float g_k[MTOT * DIM];
__device__ float g_v[MTOT * DIM];
__device__ float g_wt[3 * DIM * DIM];

__device__ __forceinline__ uint32_t tf32_rn(float x) {
    uint32_t r;
    asm("cvt.rn.tf32.f32 %0, %1;" : "=r"(r) : "f"(x));
    return r;
}

__device__ __forceinline__ uint32_t smem_u32(const void* p) {
    uint32_t a;
    asm("{ .reg .u64 t; cvta.to.shared.u64 t, %1; cvt.u32.u64 %0, t; }"
        : "=r"(a) : "l"(p));
    return a;
}

#define CP16(dst, src) \
    asm volatile("cp.async.cg.shared.global [%0], [%1], 16;" \
                 :: "r"(dst), "l"(src) : "memory")
#define CP_COMMIT() asm volatile("cp.async.commit_group;" ::: "memory")
#define CP_WAIT1()  asm volatile("cp.async.wait_group 1;" ::: "memory")

__device__ __forceinline__ void mma_tf32(
    float& d0, float& d1, float& d2, float& d3,
    uint32_t a0, uint32_t a1, uint32_t a2, uint32_t a3,
    uint32_t b0, uint32_t b1)
{
    asm volatile(
        "mma.sync.aligned.m16n8k8.row.col.f32.tf32.tf32.f32 "
        "{%0,%1,%2,%3}, {%4,%5,%6,%7}, {%8,%9}, {%0,%1,%2,%3};"
        : "+f"(d0), "+f"(d1), "+f"(d2), "+f"(d3)
        : "r"(a0), "r"(a1), "r"(a2), "r"(a3), "r"(b0), "r"(b1));
}

// ---------------------------------------------------------------------------
// LayerNorm -> tf32 bits in g_h
// ---------------------------------------------------------------------------
__global__ __launch_bounds__(256) void ln_kernel(
    const float* __restrict__ x,
    const float* __restrict__ w,
    const float* __restrict__ bvec)
{
    const int row = blockIdx.x;
    const int t = threadIdx.x;
    float4 v = ((const float4*)(x + (size_t)row * DIM))[t];
    float s  = v.x + v.y + v.z + v.w;
    float ss = v.x * v.x + v.y * v.y + v.z * v.z + v.w * v.w;
    #pragma unroll
    for (int off = 16; off; off >>= 1) {
        s  += __shfl_xor_sync(0xffffffffu, s,  off);
        ss += __shfl_xor_sync(0xffffffffu, ss, off);
    }
    __shared__ float sh[16];
    const int wid = t >> 5, lane = t & 31;
    if (lane == 0) { sh[wid] = s; sh[8 + wid] = ss; }
    __syncthreads();
    float ts = 0.f, tss = 0.f;
    #pragma unroll
    for (int i = 0; i < 8; i++) { ts += sh[i]; tss += sh[8 + i]; }
    const float mu  = ts * (1.0f / DIM);
    const float var = tss * (1.0f / DIM) - mu * mu;
    const float r   = rsqrtf(var + 1e-5f);
    float4 wv = ((const float4*)w)[t];
    float4 bv = ((const float4*)bvec)[t];
    uint4 o;
    o.x = tf32_rn((v.x - mu) * r * wv.x + bv.x);
    o.y = tf32_rn((v.y - mu) * r * wv.y + bv.y);
    o.z = tf32_rn((v.z - mu) * r * wv.z + bv.z);
    o.w = tf32_rn((v.w - mu) * r * wv.w + bv.w);
    ((uint4*)(g_h + (size_t)row * DIM))[t] = o;
}

// ---------------------------------------------------------------------------
// One-shot weight converter: wq/wk/wv fp32 -> tf32 bits in g_wt
// ---------------------------------------------------------------------------
__global__ __launch_bounds__(256) void cvt_w(
    const float* __restrict__ Wq,
    const float* __restrict__ Wk,
    const float* __restrict__ Wv)
{
    const int z = blockIdx.y;
    const float* src = (z == 0) ? Wq : (z == 1) ? Wk : Wv;
    const size_t idx = (size_t)blockIdx.x * 256 + threadIdx.x;
    float4 v = ((const float4*)src)[idx];
    uint4 u = make_uint4(tf32_rn(v.x), tf32_rn(v.y), tf32_rn(v.z), tf32_rn(v.w));
    ((uint4*)(g_wt + (size_t)z * DIM * DIM))[idx] = u;
}

// ---------------------------------------------------------------------------
// QKV GEMM via mma.sync tf32 (m16n8k8), CTA tile 128x128, K-chunk 32,
// 8 warps in 2(m) x 4(n). Inputs pre-converted tf32 bits (no cvt in loop).
// ---------------------------------------------------------------------------
__global__ __launch_bounds__(256) void qkv_gemm_mma(
    const float* __restrict__ Bq,
    const float* __restrict__ Bk,
    const float* __restrict__ Bv)
{
    extern __shared__ uint32_t smem[];
    uint32_t* const As[2] = { smem,        smem + 4096 };
    uint32_t* const Bs[2] = { smem + 8192, smem + 12288 };

    const int which = blockIdx.z;
    const uint32_t* W = (const uint32_t*)g_wt + (size_t)which * DIM * DIM;
    const float* bias = (which == 0) ? Bq : (which == 1) ? Bk : Bv;
    float* C          = (which == 0) ? g_q : (which == 1) ? g_k : g_v;
    const float qscale = (which == 0) ? 0.125f : 1.0f;

    const int tid  = threadIdx.x;
    const int wid  = tid >> 5;
    const int lane = tid & 31;
    const int gid  = lane >> 2;      // 0..7
    const int tig  = lane & 3;       // 0..3
    const int wm   = wid & 1;
    const int wn   = wid >> 1;

    const int m0 = blockIdx.y * 128;
    const int n0 = blockIdx.x * 128;

    const int a_m = tid >> 1;
    const int a_c = (tid & 1) * 4;
    const uint32_t* Arow = (const uint32_t*)g_h + (size_t)(m0 + a_m) * DIM + a_c * 4;

    float acc[4][4][4];
    #pragma unroll
    for (int i = 0; i < 4; i++)
        #pragma unroll
        for (int j = 0; j < 4; j++)
            #pragma unroll
            for (int r = 0; r < 4; r++) acc[i][j][r] = 0.f;

    uint4 aReg[4], bReg[4];

    #pragma unroll
    for (int c = 0; c < 4; c++) {
        aReg[c] = *(const uint4*)(Arow + c * 4);
        bReg[c] = *(const uint4*)(W + (size_t)(wid + 8 * c) * DIM + n0 + lane * 4);
    }

    const int NCHUNK = DIM / 32;
    #pragma unroll 1
    for (int i = 0; i < NCHUNK; ++i) {
        const int p = i & 1;
        {
            uint32_t* A = As[p];
            const int r7 = a_m & 7;
            #pragma unroll
            for (int c = 0; c < 4; c++)
                *(uint4*)&A[a_m * 32 + (((a_c + c) ^ r7) << 2)] = aReg[c];
            uint32_t* B = Bs[p];
            #pragma unroll
            for (int c = 0; c < 4; c++) {
                const int k = wid + 8 * c;
                const int col = (lane * 4) ^ ((k & 3) << 3);
                *(uint4*)&B[k * 128 + col] = bReg[c];
            }
        }
        __syncthreads();

        if (i + 1 < NCHUNK) {
            const int k0n = (i + 1) * 32;
            #pragma unroll
            for (int c = 0; c < 4; c++) {
                aReg[c] = *(const uint4*)(Arow + k0n + c * 4);
                bReg[c] = *(const uint4*)(W + (size_t)(k0n + wid + 8 * c) * DIM
                                          + n0 + lane * 4);
            }
        }

        const uint32_t* A = As[p];
        const uint32_t* B = Bs[p];
        #pragma unroll
        for (int s = 0; s < 4; s++) {
            const int r0 = s * 8 + tig;
            const int r1 = r0 + 4;
            const int X  = tig << 3;
            const int w0 = ((2 * s)     ^ gid) << 2;
            const int w1 = ((2 * s + 1) ^ gid) << 2;
            uint32_t af[4][4];
            #pragma unroll
            for (int mt = 0; mt < 4; mt++) {
                const int mr = wm * 64 + mt * 16 + gid;
                af[mt][0] = A[mr * 32       + w0 + tig];
                af[mt][1] = A[(mr + 8) * 32 + w0 + tig];
                af[mt][2] = A[mr * 32       + w1 + tig];
                af[mt][3] = A[(mr + 8) * 32 + w1 + tig];
            }
            uint32_t bf[4][2];
            #pragma unroll
            for (int nt = 0; nt < 4; nt++) {
                const int bn = wn * 32 + nt * 8;
                bf[nt][0] = B[r0 * 128 + ((bn + gid) ^ X)];
                bf[nt][1] = B[r1 * 128 + ((bn + gid) ^ X)];
            }
            #pragma unroll
            for (int mt = 0; mt < 4; mt++)
                #pragma unroll
                for (int nt = 0; nt < 4; nt++)
                    mma_tf32(acc[mt][nt][0], acc[mt][nt][1],
                             acc[mt][nt][2], acc[mt][nt][3],
                             af[mt][0], af[mt][1], af[mt][2], af[mt][3],
                             bf[nt][0], bf[nt][1]);
        }
        __syncthreads();
    }

    #pragma unroll
    for (int mt = 0; mt < 4; mt++) {
        const int m  = m0 + wm * 64 + mt * 16 + gid;
        const int bb = m >> 11;
        const int nn = m & (SEQ - 1);
        #pragma unroll
        for (int nt = 0; nt < 4; nt++) {
            const int n  = n0 + wn * 32 + nt * 8 + 2 * tig;
            const int hh = n >> 6;
            const int dd = n & 63;
            const float bx = bias[n], by = bias[n + 1];
            float* base = C + (((size_t)(bb * HEADS + hh) * SEQ) + nn) * DHEAD + dd;
            uint2 v0 = make_uint2(tf32_rn((acc[mt][nt][0] + bx) * qscale),
                                  tf32_rn((acc[mt][nt][1] + by) * qscale));
            uint2 v1 = make_uint2(tf32_rn((acc[mt][nt][2] + bx) * qscale),
                                  tf32_rn((acc[mt][nt][3] + by) * qscale));
            *(uint2*)base = v0;
            *(uint2*)(base + 8 * DHEAD) = v1;
        }
    }
}

// ---------------------------------------------------------------------------
// Flash attention, mma.sync tf32, 128 threads, 4 warps x 32 Q-rows.
// All tiles in natural [row][64-word] layout with chunk-XOR permutation
//   word(row, d) = row*64 + (((d>>2) ^ f(row)) << 2) + (d&3),
//   f(row) = ((row&3)<<1) | ((row>>2)&1)
// -> conflict-free for cp.async 16B writes, Q/K row fragments, V col fragments.
// SMEM words: Qs[0,8192) | K0[8192) | V0[12288) | K1[16384) | V1[20480) ; 96KB.
// cp.async double-buffered K/V; Q staged once.
// ---------------------------------------------------------------------------
#define ATTN_SMEM 98304

__global__ __launch_bounds__(128) void attn_mma(float* __restrict__ out)
{
    extern __shared__ uint32_t sm[];
    const uint32_t sb = smem_u32(sm);
    const uint32_t KOFF[2] = { 8192u, 16384u };
    const uint32_t VOFF[2] = { 12288u, 20480u };

    const int bh = blockIdx.y;               // 0..63
    const int q0 = blockIdx.x * 128;
    const uint32_t* Qb = (const uint32_t*)g_q + (size_t)bh * SEQ * DHEAD;
    const uint32_t* Kb = (const uint32_t*)g_k + (size_t)bh * SEQ * DHEAD;
    const uint32_t* Vb = (const uint32_t*)g_v + (size_t)bh * SEQ * DHEAD;

    const int tid  = threadIdx.x;
    const int wid  = tid >> 5, lane = tid & 31;
    const int g    = lane >> 2, t = lane & 3;
    const int wrow = wid * 32;

    // loader mapping: 2 threads per row, 8 chunks each
    const int lrow = tid >> 1;
    const int lcb  = (tid & 1) << 3;
    const int lfp  = ((lrow & 3) << 1) | ((lrow >> 2) & 1);

    // ---- prologue: stage Q (group with tile 0) + tiles 0,1 ----
    {
        const int qfp = ((tid & 3) << 1) | ((tid >> 2) & 1);
        const uint32_t* qsrc = Qb + (size_t)(q0 + tid) * DHEAD;
        const uint32_t qdst = sb + tid * 256;   // row*64 words *4B
        #pragma unroll
        for (int c = 0; c < 16; c++)
            CP16(qdst + ((c ^ qfp) << 4), qsrc + c * 4);
    }
    #pragma unroll
    for (int pb = 0; pb < 2; pb++) {
        const uint32_t* ksrc = Kb + (size_t)(pb * 64 + lrow) * DHEAD;
        const uint32_t* vsrc = Vb + (size_t)(pb * 64 + lrow) * DHEAD;
        const uint32_t kdst = sb + (KOFF[pb] + lrow * 64) * 4;
        const uint32_t vdst = sb + (VOFF[pb] + lrow * 64) * 4;
        #pragma unroll
        for (int j = 0; j < 8; j++) {
            const int c = lcb + j;
            CP16(kdst + ((c ^ lfp) << 4), ksrc + c * 4);
            CP16(vdst + ((c ^ lfp) << 4), vsrc + c * 4);
        }
        CP_COMMIT();
    }
    CP_WAIT1();
    __syncthreads();

    float o[2][8][4];
    #pragma unroll
    for (int mb = 0; mb < 2; mb++)
        #pragma unroll
        for (int nt = 0; nt < 8; nt++)
            #pragma unroll
            for (int r = 0; r < 4; r++) o[mb][nt][r] = 0.f;
    float mrow[2][2], lrow_[2][2];
    #pragma unroll
    for (int mb = 0; mb < 2; mb++) {
        mrow[mb][0] = -1e30f; mrow[mb][1] = -1e30f;
        lrow_[mb][0] = 0.f;   lrow_[mb][1] = 0.f;
    }

    const int fq   = ((g & 3) << 1) | (g >> 2);
    const int src  = (lane & ~3) | (t >> 1);
    const int src2 = src + 2;

    const int NKT = SEQ / 64;
    #pragma unroll 1
    for (int kt = 0; kt < NKT; kt++) {
        const int p = kt & 1;
        const uint32_t* Ks = sm + KOFF[p];
        const uint32_t* Vs = sm + VOFF[p];

        // ---- S = Q K^T ----
        float s[2][8][4];
        #pragma unroll
        for (int mb = 0; mb < 2; mb++)
            #pragma unroll
            for (int nt = 0; nt < 8; nt++)
                #pragma unroll
                for (int r = 0; r < 4; r++) s[mb][nt][r] = 0.f;

        #pragma unroll
        for (int ss = 0; ss < 8; ss++) {
            const int c0 = (((2 * ss)     ^ fq) << 2) + t;
            const int c1 = (((2 * ss + 1) ^ fq) << 2) + t;
            uint32_t qa[2][4];
            #pragma unroll
            for (int mb = 0; mb < 2; mb++) {
                const int rr = (wrow + mb * 16 + g) * 64;
                qa[mb][0] = sm[rr + c0];
                qa[mb][1] = sm[rr + 512 + c0];   // +8 rows
                qa[mb][2] = sm[rr + c1];
                qa[mb][3] = sm[rr + 512 + c1];
            }
            #pragma unroll
            for (int nt = 0; nt < 8; nt++) {
                const int kb = (nt * 8 + g) * 64;
                const uint32_t b0 = Ks[kb + c0];
                const uint32_t b1 = Ks[kb + c1];
                mma_tf32(s[0][nt][0], s[0][nt][1], s[0][nt][2], s[0][nt][3],
                         qa[0][0], qa[0][1], qa[0][2], qa[0][3], b0, b1);
                mma_tf32(s[1][nt][0], s[1][nt][1], s[1][nt][2], s[1][nt][3],
                         qa[1][0], qa[1][1], qa[1][2], qa[1][3], b0, b1);
            }
        }

        // ---- online softmax per m-block ----
        #pragma unroll
        for (int mb = 0; mb < 2; mb++) {
            float mx0 = -1e30f, mx1 = -1e30f;
            #pragma unroll
            for (int nt = 0; nt < 8; nt++) {
                mx0 = fmaxf(mx0, fmaxf(s[mb][nt][0], s[mb][nt][1]));
                mx1 = fmaxf(mx1, fmaxf(s[mb][nt][2], s[mb][nt][3]));
            }
            #pragma unroll
            for (int off = 1; off <= 2; off <<= 1) {
                mx0 = fmaxf(mx0, __shfl_xor_sync(0xffffffffu, mx0, off));
                mx1 = fmaxf(mx1, __shfl_xor_sync(0xffffffffu, mx1, off));
            }
            const float mn0 = fmaxf(mrow[mb][0], mx0);
            const float mn1 = fmaxf(mrow[mb][1], mx1);
            const float al0 = __expf(mrow[mb][0] - mn0);
            const float al1 = __expf(mrow[mb][1] - mn1);
            mrow[mb][0] = mn0; mrow[mb][1] = mn1;
            float sum0 = 0.f, sum1 = 0.f;
            #pragma unroll
            for (int nt = 0; nt < 8; nt++) {
                s[mb][nt][0] = __expf(s[mb][nt][0] - mn0);
                s[mb][nt][1] = __expf(s[mb][nt][1] - mn0);
                s[mb][nt][2] = __expf(s[mb][nt][2] - mn1);
                s[mb][nt][3] = __expf(s[mb][nt][3] - mn1);
                sum0 += s[mb][nt][0] + s[mb][nt][1];
                sum1 += s[mb][nt][2] + s[mb][nt][3];
            }
            #pragma unroll
            for (int off = 1; off <= 2; off <<= 1) {
                sum0 += __shfl_xor_sync(0xffffffffu, sum0, off);
                sum1 += __shfl_xor_sync(0xffffffffu, sum1, off);
            }
            lrow_[mb][0] = lrow_[mb][0] * al0 + sum0;
            lrow_[mb][1] = lrow_[mb][1] * al1 + sum1;
            #pragma unroll
            for (int nt = 0; nt < 8; nt++) {
                o[mb][nt][0] *= al0; o[mb][nt][1] *= al0;
                o[mb][nt][2] *= al1; o[mb][nt][3] *= al1;
            }
        }

        // ---- O += P V ----
        const int gh = g >> 2, g3 = g & 3;
        #pragma unroll
        for (int ss = 0; ss < 8; ss++) {
            uint32_t pa[2][4];
            #pragma unroll
            for (int mb = 0; mb < 2; mb++) {
                float x0 = __shfl_sync(0xffffffffu, s[mb][ss][0], src);
                float x1 = __shfl_sync(0xffffffffu, s[mb][ss][1], src);
                float y0 = __shfl_sync(0xffffffffu, s[mb][ss][0], src2);
                float y1 = __shfl_sync(0xffffffffu, s[mb][ss][1], src2);
                float z0 = __shfl_sync(0xffffffffu, s[mb][ss][2], src);
                float z1 = __shfl_sync(0xffffffffu, s[mb][ss][3], src);
                float w0 = __shfl_sync(0xffffffffu, s[mb][ss][2], src2);
                float w1 = __shfl_sync(0xffffffffu, s[mb][ss][3], src2);
                pa[mb][0] = tf32_rn((t & 1) ? x1 : x0);
                pa[mb][2] = tf32_rn((t & 1) ? y1 : y0);
                pa[mb][1] = tf32_rn((t & 1) ? z1 : z0);
                pa[mb][3] = tf32_rn((t & 1) ? w1 : w0);
            }
            const int vr0 = (8 * ss + t) * 64;
            const int vr1 = vr0 + 256;             // +4 rows
            const int e0 = 2 * t, e1 = e0 ^ 1;
            #pragma unroll
            for (int nt = 0; nt < 8; nt++) {
                const int cnk = 2 * nt + gh;
                const uint32_t b0 = Vs[vr0 + ((cnk ^ e0) << 2) + g3];
                const uint32_t b1 = Vs[vr1 + ((cnk ^ e1) << 2) + g3];
                mma_tf32(o[0][nt][0], o[0][nt][1], o[0][nt][2], o[0][nt][3],
                         pa[0][0], pa[0][1], pa[0][2], pa[0][3], b0, b1);
                mma_tf32(o[1][nt][0], o[1][nt][1], o[1][nt][2], o[1][nt][3],
                         pa[1][0], pa[1][1], pa[1][2], pa[1][3], b0, b1);
            }
        }

        __syncthreads();   // all warps done reading buf p
        if (kt + 2 < NKT) {
            const uint32_t* ksrc = Kb + (size_t)((kt + 2) * 64 + lrow) * DHEAD;
            const uint32_t* vsrc = Vb + (size_t)((kt + 2) * 64 + lrow) * DHEAD;
            const uint32_t kdst = sb + (KOFF[p] + lrow * 64) * 4;
            const uint32_t vdst = sb + (VOFF[p] + lrow * 64) * 4;
            #pragma unroll
            for (int j = 0; j < 8; j++) {
                const int c = lcb + j;
                CP16(kdst + ((c ^ lfp) << 4), ksrc + c * 4);
                CP16(vdst + ((c ^ lfp) << 4), vsrc + c * 4);
            }
        }
        CP_COMMIT();       // (possibly empty) group keeps accounting uniform
        CP_WAIT1();        // next iteration's buffer complete
        __syncthreads();
    }

    // ---- epilogue ----
    const int bb = bh >> 4, hh = bh & 15;
    #pragma unroll
    for (int mb = 0; mb < 2; mb++) {
        const float inv0 = 1.f / lrow_[mb][0];
        const float inv1 = 1.f / lrow_[mb][1];
        const int rr0 = q0 + wrow + mb * 16 + g;
        const int rr1 = rr0 + 8;
        #pragma unroll
        for (int nt = 0; nt < 8; nt++) {
            const int d = hh * DHEAD + nt * 8 + 2 * t;
            *(float2*)(out + ((size_t)bb * SEQ + rr0) * (HEADS * DHEAD) + d) =
                make_float2(o[mb][nt][0] * inv0, o[mb][nt][1] * inv0);
            *(float2*)(out + ((size_t)bb * SEQ + rr1) * (HEADS * DHEAD) + d) =
                make_float2(o[mb][nt][2] * inv1, o[mb][nt][3] * inv1);
        }
    }
}

// ---------------------------------------------------------------------------
extern "C" void kernel_launch(void* const* d_in, const int* in_sizes, int n_in,
                              void* d_out, int out_size) {
    const float* x    = (const float*)d_in[0];
    const float* ln_w = (const float*)d_in[1];
    const float* ln_b = (const float*)d_in[2];
    const float* wq   = (const float*)d_in[3];
    const float* bq   = (const float*)d_in[4];
    const float* wk   = (const float*)d_in[5];
    const float* bk   = (const float*)d_in[6];
    const float* wv   = (const float*)d_in[7];
    const float* bv   = (const float*)d_in[8];
    float* out = (float*)d_out;

    cudaFuncSetAttribute(qkv_gemm_mma,
                         cudaFuncAttributeMaxDynamicSharedMemorySize, 65536);
    cudaFuncSetAttribute(attn_mma,
                         cudaFuncAttributeMaxDynamicSharedMemorySize, ATTN_SMEM);

    ln_kernel<<<MTOT, 256>>>(x, ln_w, ln_b);
    cvt_w<<<dim3(DIM * DIM / (256 * 4), 3), 256>>>(wq, wk, wv);
    qkv_gemm_mma<<<dim3(DIM / 128, MTOT / 128, 3), 256, 65536>>>(bq, bk, bv);
    attn_mma<<<dim3(SEQ / 128, BATCH * HEADS), 128, ATTN_SMEM>>>(out);
}

// round 8
// speedup vs baseline: 2.5973x; 1.0053x over previous
#include <cuda_runtime.h>
#include <cstdint>

#define DIM    1024
#define HEADS  16
#define DHEAD  64
#define BATCH  4
#define SEQ    2048
#define MTOT   (BATCH * SEQ)   // 8192

// Scratch (device globals), all tf32 BITS stored as float.
// g_h : [row][1024] rows IL64-interleaved per 8-elem k-group
// g_q : [b,h,n][64]  IL64 rows, pre-scaled by 0.125
// g_k : [b,h,n][64]  IL64 rows
// g_v : TRANSPOSED [b,h,d][2048 keys] with key-IL64
// g_wt: [z][n][1024] W transposed, k-IL64
__device__ float g_h[MTOT * DIM];
__device__ float g_q[MTOT * DIM];
__device__ float g_k[MTOT * DIM];
__device__ float g_v[MTOT * DIM];
__device__ float g_wt[3 * DIM * DIM];

__device__ __forceinline__ uint32_t tf32_rn(float x) {
    uint32_t r;
    asm("cvt.rn.tf32.f32 %0, %1;" : "=r"(r) : "f"(x));
    return r;
}

// IL64 word index of element d within a row (valid for any d, groups of 8)
__device__ __forceinline__ int ilw(int d) {
    return ((d >> 3) << 3) + ((d & 3) << 1) + ((d >> 2) & 1);
}

__device__ __forceinline__ uint32_t smem_u32(const void* p) {
    uint32_t a;
    asm("{ .reg .u64 t; cvta.to.shared.u64 t, %1; cvt.u32.u64 %0, t; }"
        : "=r"(a) : "l"(p));
    return a;
}

#define CP16(dst, src) \
    asm volatile("cp.async.cg.shared.global [%0], [%1], 16;" \
                 :: "r"(dst), "l"(src) : "memory")
#define CP_COMMIT() asm volatile("cp.async.commit_group;" ::: "memory")
#define CP_WAIT1()  asm volatile("cp.async.wait_group 1;" ::: "memory")

__device__ __forceinline__ void mma_tf32(
    float& d0, float& d1, float& d2, float& d3,
    uint32_t a0, uint32_t a1, uint32_t a2, uint32_t a3,
    uint32_t b0, uint32_t b1)
{
    asm volatile(
        "mma.sync.aligned.m16n8k8.row.col.f32.tf32.tf32.f32 "
        "{%0,%1,%2,%3}, {%4,%5,%6,%7}, {%8,%9}, {%0,%1,%2,%3};"
        : "+f"(d0), "+f"(d1), "+f"(d2), "+f"(d3)
        : "r"(a0), "r"(a1), "r"(a2), "r"(a3), "r"(b0), "r"(b1));
}

// ---------------------------------------------------------------------------
// LayerNorm -> tf32 bits, IL64 rows in g_h
// ---------------------------------------------------------------------------
__global__ __launch_bounds__(256) void ln_kernel(
    const float* __restrict__ x,
    const float* __restrict__ w,
    const float* __restrict__ bvec)
{
    const int row = blockIdx.x;
    const int t = threadIdx.x;
    float4 v = ((const float4*)(x + (size_t)row * DIM))[t];
    float s  = v.x + v.y + v.z + v.w;
    float ss = v.x * v.x + v.y * v.y + v.z * v.z + v.w * v.w;
    #pragma unroll
    for (int off = 16; off; off >>= 1) {
        s  += __shfl_xor_sync(0xffffffffu, s,  off);
        ss += __shfl_xor_sync(0xffffffffu, ss, off);
    }
    __shared__ float sh[16];
    const int wid = t >> 5, lane = t & 31;
    if (lane == 0) { sh[wid] = s; sh[8 + wid] = ss; }
    __syncthreads();
    float ts = 0.f, tss = 0.f;
    #pragma unroll
    for (int i = 0; i < 8; i++) { ts += sh[i]; tss += sh[8 + i]; }
    const float mu  = ts * (1.0f / DIM);
    const float var = tss * (1.0f / DIM) - mu * mu;
    const float r   = rsqrtf(var + 1e-5f);
    float4 wv = ((const float4*)w)[t];
    float4 bv = ((const float4*)bvec)[t];
    // d = 4t..4t+3 -> words 8*(t>>1)+(t&1) + {0,2,4,6}
    float* dst = g_h + (size_t)row * DIM + 8 * (t >> 1) + (t & 1);
    dst[0] = __uint_as_float(tf32_rn((v.x - mu) * r * wv.x + bv.x));
    dst[2] = __uint_as_float(tf32_rn((v.y - mu) * r * wv.y + bv.y));
    dst[4] = __uint_as_float(tf32_rn((v.z - mu) * r * wv.z + bv.z));
    dst[6] = __uint_as_float(tf32_rn((v.w - mu) * r * wv.w + bv.w));
}

// ---------------------------------------------------------------------------
// One-shot: transpose W -> g_wt[z][n][k IL64], tf32 bits. grid(32,32,3).
// ---------------------------------------------------------------------------
__global__ __launch_bounds__(256) void cvt_w(
    const float* __restrict__ Wq,
    const float* __restrict__ Wk,
    const float* __restrict__ Wv)
{
    __shared__ float tile[32][33];
    const int z = blockIdx.z;
    const float* src = (z == 0) ? Wq : (z == 1) ? Wk : Wv;
    const int k0 = blockIdx.x * 32, n0 = blockIdx.y * 32;
    {
        const int kl = threadIdx.x >> 3, nl4 = (threadIdx.x & 7) * 4;
        float4 v = *(const float4*)(src + (size_t)(k0 + kl) * DIM + n0 + nl4);
        tile[kl][nl4 + 0] = v.x;
        tile[kl][nl4 + 1] = v.y;
        tile[kl][nl4 + 2] = v.z;
        tile[kl][nl4 + 3] = v.w;
    }
    __syncthreads();
    const int nl = threadIdx.x >> 3, kb = (threadIdx.x & 7) * 4;
    float* dst = g_wt + (size_t)z * DIM * DIM + (size_t)(n0 + nl) * DIM;
    #pragma unroll
    for (int e = 0; e < 4; e++) {
        const int k = k0 + kb + e;
        dst[ilw(k)] = __uint_as_float(tf32_rn(tile[kb + e][nl]));
    }
}

// ---------------------------------------------------------------------------
// QKV GEMM, mma.sync tf32, CTA 128x128, K-chunk 32, 8 warps 2(m)x4(n).
// A tile [m 0..127][32 w], B tile [n 0..127][32 w], both raw-copied from
// IL64 gmem; smem granule XOR: gi = raw ^ 2*(row&3). All fragments LDS.64.
// Epilogue writes g_q/g_k IL64 rows; g_v transposed key-IL64.
// ---------------------------------------------------------------------------
__global__ __launch_bounds__(256) void qkv_gemm_mma(
    const float* __restrict__ Bq,
    const float* __restrict__ Bk,
    const float* __restrict__ Bv)
{
    extern __shared__ uint32_t smem[];
    uint32_t* const As[2] = { smem,        smem + 4096 };
    uint32_t* const Bs[2] = { smem + 8192, smem + 12288 };

    const int which = blockIdx.z;
    const uint32_t* W = (const uint32_t*)g_wt + (size_t)which * DIM * DIM;
    const float* bias = (which == 0) ? Bq : (which == 1) ? Bk : Bv;
    const float qscale = (which == 0) ? 0.125f : 1.0f;

    const int tid  = threadIdx.x;
    const int lane = tid & 31;
    const int gid  = lane >> 2;      // 0..7
    const int tig  = lane & 3;       // 0..3
    const int wm   = (tid >> 5) & 1;
    const int wn   = tid >> 6;

    const int m0 = blockIdx.y * 128;
    const int n0 = blockIdx.x * 128;

    const int lr = tid >> 1;         // loader row 0..127
    const int lh = tid & 1;
    const int lx = 2 * (lr & 3);     // granule XOR for this row
    const uint32_t* Asrc = (const uint32_t*)g_h + (size_t)(m0 + lr) * DIM;
    const uint32_t* Bsrc = W + (size_t)(n0 + lr) * DIM;

    float acc[4][4][4];
    #pragma unroll
    for (int i = 0; i < 4; i++)
        #pragma unroll
        for (int j = 0; j < 4; j++)
            #pragma unroll
            for (int r = 0; r < 4; r++) acc[i][j][r] = 0.f;

    uint4 aReg[4], bReg[4];
    #pragma unroll
    for (int c = 0; c < 4; c++) {
        aReg[c] = *(const uint4*)(Asrc + 8 * c + 4 * lh);
        bReg[c] = *(const uint4*)(Bsrc + 8 * c + 4 * lh);
    }

    const int fL = 2 * (gid & 3);
    const int NCHUNK = DIM / 32;
    #pragma unroll 1
    for (int i = 0; i < NCHUNK; ++i) {
        const int p = i & 1;
        {
            uint32_t* A = As[p];
            uint32_t* B = Bs[p];
            #pragma unroll
            for (int c = 0; c < 4; c++) {
                const int gi = ((2 * c + lh) ^ lx) << 2;
                *(uint4*)&A[lr * 32 + gi] = aReg[c];
                *(uint4*)&B[lr * 32 + gi] = bReg[c];
            }
        }
        __syncthreads();

        if (i + 1 < NCHUNK) {
            const int k0n = (i + 1) * 32;
            #pragma unroll
            for (int c = 0; c < 4; c++) {
                aReg[c] = *(const uint4*)(Asrc + k0n + 8 * c + 4 * lh);
                bReg[c] = *(const uint4*)(Bsrc + k0n + 8 * c + 4 * lh);
            }
        }

        const uint32_t* A = As[p];
        const uint32_t* B = Bs[p];
        #pragma unroll
        for (int s = 0; s < 4; s++) {
            const int off = (((2 * s + (tig >> 1)) ^ fL) << 2) + 2 * (tig & 1);
            uint2 alo[4], ahi[4], bfr[4];
            #pragma unroll
            for (int mt = 0; mt < 4; mt++) {
                const int mr = wm * 64 + mt * 16 + gid;
                alo[mt] = *(const uint2*)&A[mr * 32 + off];
                ahi[mt] = *(const uint2*)&A[(mr + 8) * 32 + off];
            }
            #pragma unroll
            for (int nt = 0; nt < 4; nt++)
                bfr[nt] = *(const uint2*)&B[(wn * 32 + nt * 8 + gid) * 32 + off];
            #pragma unroll
            for (int mt = 0; mt < 4; mt++)
                #pragma unroll
                for (int nt = 0; nt < 4; nt++)
                    mma_tf32(acc[mt][nt][0], acc[mt][nt][1],
                             acc[mt][nt][2], acc[mt][nt][3],
                             alo[mt].x, ahi[mt].x, alo[mt].y, ahi[mt].y,
                             bfr[nt].x, bfr[nt].y);
        }
        __syncthreads();
    }

    // ---- epilogue ----
    if (which < 2) {
        float* C = (which == 0) ? g_q : g_k;
        #pragma unroll
        for (int mt = 0; mt < 4; mt++) {
            const int m  = m0 + wm * 64 + mt * 16 + gid;
            const int bb = m >> 11;
            const int nn = m & (SEQ - 1);
            #pragma unroll
            for (int nt = 0; nt < 4; nt++) {
                const int n  = n0 + wn * 32 + nt * 8 + 2 * tig;
                const int hh = n >> 6;
                const int dd = n & 63;
                const float bx = bias[n], by = bias[n + 1];
                float* base = C + ((size_t)(bb * HEADS + hh) * SEQ + nn) * DHEAD
                            + ilw(dd);
                base[0] = __uint_as_float(tf32_rn((acc[mt][nt][0] + bx) * qscale));
                base[2] = __uint_as_float(tf32_rn((acc[mt][nt][1] + by) * qscale));
                base[512]     = __uint_as_float(tf32_rn((acc[mt][nt][2] + bx) * qscale));
                base[512 + 2] = __uint_as_float(tf32_rn((acc[mt][nt][3] + by) * qscale));
            }
        }
    } else {
        // V: transposed store g_v[(bb*16+hh)*64 + dd][key IL64]
        #pragma unroll
        for (int mt = 0; mt < 4; mt++) {
            const int m   = m0 + wm * 64 + mt * 16 + gid;
            const int bb  = m >> 11;
            const int key = m & (SEQ - 1);
            const int kw  = ilw(key);
            #pragma unroll
            for (int nt = 0; nt < 4; nt++) {
                const int n  = n0 + wn * 32 + nt * 8 + 2 * tig;
                const int hh = n >> 6;
                const int dd = n & 63;
                const float bx = bias[n], by = bias[n + 1];
                float* base = g_v + ((size_t)(bb * HEADS + hh) * DHEAD + dd) * SEQ + kw;
                base[0]        = __uint_as_float(tf32_rn(acc[mt][nt][0] + bx));
                base[SEQ]      = __uint_as_float(tf32_rn(acc[mt][nt][1] + by));
                base[8]        = __uint_as_float(tf32_rn(acc[mt][nt][2] + bx));
                base[SEQ + 8]  = __uint_as_float(tf32_rn(acc[mt][nt][3] + by));
            }
        }
    }
}

// ---------------------------------------------------------------------------
// Flash attention, mma.sync tf32, 128 threads, 4 warps x 32 Q-rows.
// Q/K tiles: [row][64 w] IL64 raw-copy + granule XOR 2*(row&3).
// V tile: [d][64 keys IL64] from transposed g_v. All fragments LDS.64.
// SMEM words: Q[0,8192) K0[8192) V0[12288) K1[16384) V1[20480); 96KB.
// ---------------------------------------------------------------------------
#define ATTN_SMEM 98304

__global__ __launch_bounds__(128) void attn_mma(float* __restrict__ out)
{
    extern __shared__ uint32_t sm[];
    const uint32_t sb = smem_u32(sm);
    const uint32_t KOFF[2] = { 8192u, 16384u };
    const uint32_t VOFF[2] = { 12288u, 20480u };

    const int bh = blockIdx.y;               // 0..63
    const int q0 = blockIdx.x * 128;
    const uint32_t* Qb = (const uint32_t*)g_q + (size_t)bh * SEQ * DHEAD;
    const uint32_t* Kb = (const uint32_t*)g_k + (size_t)bh * SEQ * DHEAD;
    const uint32_t* Vb = (const uint32_t*)g_v + (size_t)bh * DHEAD * SEQ; // [d][key]

    const int tid  = threadIdx.x;
    const int lane = tid & 31;
    const int g    = lane >> 2, t = lane & 3;
    const int wrow = (tid >> 5) * 32;

    // loaders: 2 threads per row, 8 granules (16B) each -> full 64-word rows
    const int lr = tid >> 1;            // 0..63 (K: key row, V: d row)
    const int lh = tid & 1;
    const int lx = 2 * (lr & 3);

    // ---- prologue: stage Q + tiles 0,1 ----
    {
        const int qx = 2 * (tid & 3);
        const uint32_t* qsrc = Qb + (size_t)(q0 + tid) * DHEAD;
        const uint32_t qdst = sb + tid * 256;
        #pragma unroll
        for (int c = 0; c < 16; c++)
            CP16(qdst + ((c ^ qx) << 4), qsrc + 4 * c);
    }
    #pragma unroll
    for (int pb = 0; pb < 2; pb++) {
        const uint32_t* ksrc = Kb + (size_t)(pb * 64 + lr) * DHEAD;
        const uint32_t* vsrc = Vb + (size_t)lr * SEQ + pb * 64;
        const uint32_t kdst = sb + (KOFF[pb] + lr * 64) * 4;
        const uint32_t vdst = sb + (VOFF[pb] + lr * 64) * 4;
        #pragma unroll
        for (int c = 0; c < 8; c++) {
            const int gi = ((2 * c + lh) ^ lx) << 4;
            CP16(kdst + gi, ksrc + 8 * c + 4 * lh);
            CP16(vdst + gi, vsrc + 8 * c + 4 * lh);
        }
        CP_COMMIT();
    }
    CP_WAIT1();
    __syncthreads();

    float o[2][8][4];
    #pragma unroll
    for (int mb = 0; mb < 2; mb++)
        #pragma unroll
        for (int nt = 0; nt < 8; nt++)
            #pragma unroll
            for (int r = 0; r < 4; r++) o[mb][nt][r] = 0.f;
    float mrow[2][2], lsum[2][2];
    #pragma unroll
    for (int mb = 0; mb < 2; mb++) {
        mrow[mb][0] = -1e30f; mrow[mb][1] = -1e30f;
        lsum[mb][0] = 0.f;    lsum[mb][1] = 0.f;
    }

    const int fL   = 2 * (g & 3);
    const int src  = (lane & ~3) | (t >> 1);
    const int src2 = src + 2;

    const int NKT = SEQ / 64;
    #pragma unroll 1
    for (int kt = 0; kt < NKT; kt++) {
        const int p = kt & 1;
        const uint32_t* Ks = sm + KOFF[p];
        const uint32_t* Vs = sm + VOFF[p];

        // ---- S = Q K^T ----
        float s[2][8][4];
        #pragma unroll
        for (int mb = 0; mb < 2; mb++)
            #pragma unroll
            for (int nt = 0; nt < 8; nt++)
                #pragma unroll
                for (int r = 0; r < 4; r++) s[mb][nt][r] = 0.f;

        #pragma unroll
        for (int ss = 0; ss < 8; ss++) {
            const int off = (((2 * ss + (t >> 1)) ^ fL) << 2) + 2 * (t & 1);
            uint2 qa[2][2];
            #pragma unroll
            for (int mb = 0; mb < 2; mb++) {
                const int rr = (wrow + mb * 16 + g) * 64;
                qa[mb][0] = *(const uint2*)&sm[rr + off];
                qa[mb][1] = *(const uint2*)&sm[rr + 512 + off];
            }
            #pragma unroll
            for (int nt = 0; nt < 8; nt++) {
                const uint2 kb = *(const uint2*)&Ks[(nt * 8 + g) * 64 + off];
                mma_tf32(s[0][nt][0], s[0][nt][1], s[0][nt][2], s[0][nt][3],
                         qa[0][0].x, qa[0][1].x, qa[0][0].y, qa[0][1].y,
                         kb.x, kb.y);
                mma_tf32(s[1][nt][0], s[1][nt][1], s[1][nt][2], s[1][nt][3],
                         qa[1][0].x, qa[1][1].x, qa[1][0].y, qa[1][1].y,
                         kb.x, kb.y);
            }
        }

        // ---- online softmax per m-block ----
        #pragma unroll
        for (int mb = 0; mb < 2; mb++) {
            float mx0 = -1e30f, mx1 = -1e30f;
            #pragma unroll
            for (int nt = 0; nt < 8; nt++) {
                mx0 = fmaxf(mx0, fmaxf(s[mb][nt][0], s[mb][nt][1]));
                mx1 = fmaxf(mx1, fmaxf(s[mb][nt][2], s[mb][nt][3]));
            }
            #pragma unroll
            for (int off = 1; off <= 2; off <<= 1) {
                mx0 = fmaxf(mx0, __shfl_xor_sync(0xffffffffu, mx0, off));
                mx1 = fmaxf(mx1, __shfl_xor_sync(0xffffffffu, mx1, off));
            }
            const float mn0 = fmaxf(mrow[mb][0], mx0);
            const float mn1 = fmaxf(mrow[mb][1], mx1);
            const float al0 = __expf(mrow[mb][0] - mn0);
            const float al1 = __expf(mrow[mb][1] - mn1);
            mrow[mb][0] = mn0; mrow[mb][1] = mn1;
            float sum0 = 0.f, sum1 = 0.f;
            #pragma unroll
            for (int nt = 0; nt < 8; nt++) {
                s[mb][nt][0] = __expf(s[mb][nt][0] - mn0);
                s[mb][nt][1] = __expf(s[mb][nt][1] - mn0);
                s[mb][nt][2] = __expf(s[mb][nt][2] - mn1);
                s[mb][nt][3] = __expf(s[mb][nt][3] - mn1);
                sum0 += s[mb][nt][0] + s[mb][nt][1];
                sum1 += s[mb][nt][2] + s[mb][nt][3];
            }
            #pragma unroll
            for (int off = 1; off <= 2; off <<= 1) {
                sum0 += __shfl_xor_sync(0xffffffffu, sum0, off);
                sum1 += __shfl_xor_sync(0xffffffffu, sum1, off);
            }
            lsum[mb][0] = lsum[mb][0] * al0 + sum0;
            lsum[mb][1] = lsum[mb][1] * al1 + sum1;
            #pragma unroll
            for (int nt = 0; nt < 8; nt++) {
                o[mb][nt][0] *= al0; o[mb][nt][1] *= al0;
                o[mb][nt][2] *= al1; o[mb][nt][3] *= al1;
            }
        }

        // ---- O += P V ----
        #pragma unroll
        for (int ss = 0; ss < 8; ss++) {
            uint32_t pa[2][4];
            #pragma unroll
            for (int mb = 0; mb < 2; mb++) {
                float x0 = __shfl_sync(0xffffffffu, s[mb][ss][0], src);
                float x1 = __shfl_sync(0xffffffffu, s[mb][ss][1], src);
                float y0 = __shfl_sync(0xffffffffu, s[mb][ss][0], src2);
                float y1 = __shfl_sync(0xffffffffu, s[mb][ss][1], src2);
                float z0 = __shfl_sync(0xffffffffu, s[mb][ss][2], src);
                float z1 = __shfl_sync(0xffffffffu, s[mb][ss][3], src);
                float w0 = __shfl_sync(0xffffffffu, s[mb][ss][2], src2);
                float w1 = __shfl_sync(0xffffffffu, s[mb][ss][3], src2);
                pa[mb][0] = tf32_rn((t & 1) ? x1 : x0);
                pa[mb][2] = tf32_rn((t & 1) ? y1 : y0);
                pa[mb][1] = tf32_rn((t & 1) ? z1 : z0);
                pa[mb][3] = tf32_rn((t & 1) ? w1 : w0);
            }
            const int off = (((2 * ss + (t >> 1)) ^ fL) << 2) + 2 * (t & 1);
            #pragma unroll
            for (int nt = 0; nt < 8; nt++) {
                const uint2 vb = *(const uint2*)&Vs[(nt * 8 + g) * 64 + off];
                mma_tf32(o[0][nt][0], o[0][nt][1], o[0][nt][2], o[0][nt][3],
                         pa[0][0], pa[0][1], pa[0][2], pa[0][3], vb.x, vb.y);
                mma_tf32(o[1][nt][0], o[1][nt][1], o[1][nt][2], o[1][nt][3],
                         pa[1][0], pa[1][1], pa[1][2], pa[1][3], vb.x, vb.y);
            }
        }

        __syncthreads();   // all warps done reading buf p
        if (kt + 2 < NKT) {
            const uint32_t* ksrc = Kb + (size_t)((kt + 2) * 64 + lr) * DHEAD;
            const uint32_t* vsrc = Vb + (size_t)lr * SEQ + (kt + 2) * 64;
            const uint32_t kdst = sb + (KOFF[p] + lr * 64) * 4;
            const uint32_t vdst = sb + (VOFF[p] + lr * 64) * 4;
            #pragma unroll
            for (int c = 0; c < 8; c++) {
                const int gi = ((2 * c + lh) ^ lx) << 4;
                CP16(kdst + gi, ksrc + 8 * c + 4 * lh);
                CP16(vdst + gi, vsrc + 8 * c + 4 * lh);
            }
        }
        CP_COMMIT();
        CP_WAIT1();
        __syncthreads();
    }

    // ---- epilogue ----
    const int bb = bh >> 4, hh = bh & 15;
    #pragma unroll
    for (int mb = 0; mb < 2; mb++) {
        const float inv0 = 1.f / lsum[mb][0];
        const float inv1 = 1.f / lsum[mb][1];
        const int rr0 = q0 + wrow + mb * 16 + g;
        const int rr1 = rr0 + 8;
        #pragma unroll
        for (int nt = 0; nt < 8; nt++) {
            const int d = hh * DHEAD + nt * 8 + 2 * t;
            *(float2*)(out + ((size_t)bb * SEQ + rr0) * (HEADS * DHEAD) + d) =
                make_float2(o[mb][nt][0] * inv0, o[mb][nt][1] * inv0);
            *(float2*)(out + ((size_t)bb * SEQ + rr1) * (HEADS * DHEAD) + d) =
                make_float2(o[mb][nt][2] * inv1, o[mb][nt][3] * inv1);
        }
    }
}

// ---------------------------------------------------------------------------
extern "C" void kernel_launch(void* const* d_in, const int* in_sizes, int n_in,
                              void* d_out, int out_size) {
    const float* x    = (const float*)d_in[0];
    const float* ln_w = (const float*)d_in[1];
    const float* ln_b = (const float*)d_in[2];
    const float* wq   = (const float*)d_in[3];
    const float* bq   = (const float*)d_in[4];
    const float* wk   = (const float*)d_in[5];
    const float* bk   = (const float*)d_in[6];
    const float* wv   = (const float*)d_in[7];
    const float* bv   = (const float*)d_in[8];
    float* out = (float*)d_out;

    cudaFuncSetAttribute(qkv_gemm_mma,
                         cudaFuncAttributeMaxDynamicSharedMemorySize, 65536);
    cudaFuncSetAttribute(attn_mma,
                         cudaFuncAttributeMaxDynamicSharedMemorySize, ATTN_SMEM);

    ln_kernel<<<MTOT, 256>>>(x, ln_w, ln_b);
    cvt_w<<<dim3(32, 32, 3), 256>>>(wq, wk, wv);
    qkv_gemm_mma<<<dim3(DIM / 128, MTOT / 128, 3), 256, 65536>>>(bq, bk, bv);
    attn_mma<<<dim3(SEQ / 128, BATCH * HEADS), 128, ATTN_SMEM>>>(out);
}

// round 9
// speedup vs baseline: 2.8626x; 1.1022x over previous
#include <cuda_runtime.h>
#include <cuda_fp16.h>
#include <cstdint>

#define DIM    1024
#define HEADS  16
#define DHEAD  64
#define BATCH  4
#define SEQ    2048
#define MTOT   (BATCH * SEQ)   // 8192

// Scratch (device globals).
// g_h : [row][1024] tf32 bits, IL64-interleaved per 8-elem k-group
// g_q : [b,h,n][64] tf32 bits, IL64 rows, pre-scaled by 0.125
// g_k : [b,h,n][64] tf32 bits, IL64 rows
// g_v16: TRANSPOSED fp16 [b,h,d][2048 keys], plain key order
// g_wt: [z][n][1024] W transposed, k-IL64, tf32 bits
__device__ float  g_h[MTOT * DIM];
__device__ float  g_q[MTOT * DIM];
__device__ float  g_k[MTOT * DIM];
__device__ __half g_v16[(size_t)BATCH * HEADS * DHEAD * SEQ];
__device__ float  g_wt[3 * DIM * DIM];

__device__ __forceinline__ uint32_t tf32_rn(float x) {
    uint32_t r;
    asm("cvt.rn.tf32.f32 %0, %1;" : "=r"(r) : "f"(x));
    return r;
}

// pack two f32 -> half2 (lo = first arg)
__device__ __forceinline__ uint32_t pack_h2(float lo, float hi) {
    uint32_t r;
    asm("cvt.rn.f16x2.f32 %0, %1, %2;" : "=r"(r) : "f"(hi), "f"(lo));
    return r;
}

// IL64 word index of element d within a row (valid for any d, groups of 8)
__device__ __forceinline__ int ilw(int d) {
    return ((d >> 3) << 3) + ((d & 3) << 1) + ((d >> 2) & 1);
}

__device__ __forceinline__ uint32_t smem_u32(const void* p) {
    uint32_t a;
    asm("{ .reg .u64 t; cvta.to.shared.u64 t, %1; cvt.u32.u64 %0, t; }"
        : "=r"(a) : "l"(p));
    return a;
}

#define CP16(dst, src) \
    asm volatile("cp.async.cg.shared.global [%0], [%1], 16;" \
                 :: "r"(dst), "l"(src) : "memory")
#define CP_COMMIT() asm volatile("cp.async.commit_group;" ::: "memory")
#define CP_WAIT1()  asm volatile("cp.async.wait_group 1;" ::: "memory")

__device__ __forceinline__ void mma_tf32(
    float& d0, float& d1, float& d2, float& d3,
    uint32_t a0, uint32_t a1, uint32_t a2, uint32_t a3,
    uint32_t b0, uint32_t b1)
{
    asm volatile(
        "mma.sync.aligned.m16n8k8.row.col.f32.tf32.tf32.f32 "
        "{%0,%1,%2,%3}, {%4,%5,%6,%7}, {%8,%9}, {%0,%1,%2,%3};"
        : "+f"(d0), "+f"(d1), "+f"(d2), "+f"(d3)
        : "r"(a0), "r"(a1), "r"(a2), "r"(a3), "r"(b0), "r"(b1));
}

__device__ __forceinline__ void mma_f16(
    float& d0, float& d1, float& d2, float& d3,
    uint32_t a0, uint32_t a1, uint32_t a2, uint32_t a3,
    uint32_t b0, uint32_t b1)
{
    asm volatile(
        "mma.sync.aligned.m16n8k16.row.col.f32.f16.f16.f32 "
        "{%0,%1,%2,%3}, {%4,%5,%6,%7}, {%8,%9}, {%0,%1,%2,%3};"
        : "+f"(d0), "+f"(d1), "+f"(d2), "+f"(d3)
        : "r"(a0), "r"(a1), "r"(a2), "r"(a3), "r"(b0), "r"(b1));
}

// ---------------------------------------------------------------------------
// LayerNorm -> tf32 bits, IL64 rows in g_h
// ---------------------------------------------------------------------------
__global__ __launch_bounds__(256) void ln_kernel(
    const float* __restrict__ x,
    const float* __restrict__ w,
    const float* __restrict__ bvec)
{
    const int row = blockIdx.x;
    const int t = threadIdx.x;
    float4 v = ((const float4*)(x + (size_t)row * DIM))[t];
    float s  = v.x + v.y + v.z + v.w;
    float ss = v.x * v.x + v.y * v.y + v.z * v.z + v.w * v.w;
    #pragma unroll
    for (int off = 16; off; off >>= 1) {
        s  += __shfl_xor_sync(0xffffffffu, s,  off);
        ss += __shfl_xor_sync(0xffffffffu, ss, off);
    }
    __shared__ float sh[16];
    const int wid = t >> 5, lane = t & 31;
    if (lane == 0) { sh[wid] = s; sh[8 + wid] = ss; }
    __syncthreads();
    float ts = 0.f, tss = 0.f;
    #pragma unroll
    for (int i = 0; i < 8; i++) { ts += sh[i]; tss += sh[8 + i]; }
    const float mu  = ts * (1.0f / DIM);
    const float var = tss * (1.0f / DIM) - mu * mu;
    const float r   = rsqrtf(var + 1e-5f);
    float4 wv = ((const float4*)w)[t];
    float4 bv = ((const float4*)bvec)[t];
    // d = 4t..4t+3 -> words 8*(t>>1)+(t&1) + {0,2,4,6}
    float* dst = g_h + (size_t)row * DIM + 8 * (t >> 1) + (t & 1);
    dst[0] = __uint_as_float(tf32_rn((v.x - mu) * r * wv.x + bv.x));
    dst[2] = __uint_as_float(tf32_rn((v.y - mu) * r * wv.y + bv.y));
    dst[4] = __uint_as_float(tf32_rn((v.z - mu) * r * wv.z + bv.z));
    dst[6] = __uint_as_float(tf32_rn((v.w - mu) * r * wv.w + bv.w));
}

// ---------------------------------------------------------------------------
// One-shot: transpose W -> g_wt[z][n][k IL64], tf32 bits. grid(32,32,3).
// ---------------------------------------------------------------------------
__global__ __launch_bounds__(256) void cvt_w(
    const float* __restrict__ Wq,
    const float* __restrict__ Wk,
    const float* __restrict__ Wv)
{
    __shared__ float tile[32][33];
    const int z = blockIdx.z;
    const float* src = (z == 0) ? Wq : (z == 1) ? Wk : Wv;
    const int k0 = blockIdx.x * 32, n0 = blockIdx.y * 32;
    {
        const int kl = threadIdx.x >> 3, nl4 = (threadIdx.x & 7) * 4;
        float4 v = *(const float4*)(src + (size_t)(k0 + kl) * DIM + n0 + nl4);
        tile[kl][nl4 + 0] = v.x;
        tile[kl][nl4 + 1] = v.y;
        tile[kl][nl4 + 2] = v.z;
        tile[kl][nl4 + 3] = v.w;
    }
    __syncthreads();
    const int nl = threadIdx.x >> 3, kb = (threadIdx.x & 7) * 4;
    float* dst = g_wt + (size_t)z * DIM * DIM + (size_t)(n0 + nl) * DIM;
    #pragma unroll
    for (int e = 0; e < 4; e++) {
        const int k = k0 + kb + e;
        dst[ilw(k)] = __uint_as_float(tf32_rn(tile[kb + e][nl]));
    }
}

// ---------------------------------------------------------------------------
// QKV GEMM, mma.sync tf32, CTA 128x128, K-chunk 32, 8 warps 2(m)x4(n).
// A/B tiles raw-copied from IL64 gmem; granule XOR gi = raw ^ 2*(row&3).
// Epilogue: q/k -> IL64 tf32 rows; v -> transposed fp16 [b,h,d][key].
// ---------------------------------------------------------------------------
__global__ __launch_bounds__(256) void qkv_gemm_mma(
    const float* __restrict__ Bq,
    const float* __restrict__ Bk,
    const float* __restrict__ Bv)
{
    extern __shared__ uint32_t smem[];
    uint32_t* const As[2] = { smem,        smem + 4096 };
    uint32_t* const Bs[2] = { smem + 8192, smem + 12288 };

    const int which = blockIdx.z;
    const uint32_t* W = (const uint32_t*)g_wt + (size_t)which * DIM * DIM;
    const float* bias = (which == 0) ? Bq : (which == 1) ? Bk : Bv;
    const float qscale = (which == 0) ? 0.125f : 1.0f;

    const int tid  = threadIdx.x;
    const int lane = tid & 31;
    const int gid  = lane >> 2;      // 0..7
    const int tig  = lane & 3;       // 0..3
    const int wm   = (tid >> 5) & 1;
    const int wn   = tid >> 6;

    const int m0 = blockIdx.y * 128;
    const int n0 = blockIdx.x * 128;

    const int lr = tid >> 1;         // loader row 0..127
    const int lh = tid & 1;
    const int lx = 2 * (lr & 3);     // granule XOR for this row
    const uint32_t* Asrc = (const uint32_t*)g_h + (size_t)(m0 + lr) * DIM;
    const uint32_t* Bsrc = W + (size_t)(n0 + lr) * DIM;

    float acc[4][4][4];
    #pragma unroll
    for (int i = 0; i < 4; i++)
        #pragma unroll
        for (int j = 0; j < 4; j++)
            #pragma unroll
            for (int r = 0; r < 4; r++) acc[i][j][r] = 0.f;

    uint4 aReg[4], bReg[4];
    #pragma unroll
    for (int c = 0; c < 4; c++) {
        aReg[c] = *(const uint4*)(Asrc + 8 * c + 4 * lh);
        bReg[c] = *(const uint4*)(Bsrc + 8 * c + 4 * lh);
    }

    const int fL = 2 * (gid & 3);
    const int NCHUNK = DIM / 32;
    #pragma unroll 1
    for (int i = 0; i < NCHUNK; ++i) {
        const int p = i & 1;
        {
            uint32_t* A = As[p];
            uint32_t* B = Bs[p];
            #pragma unroll
            for (int c = 0; c < 4; c++) {
                const int gi = ((2 * c + lh) ^ lx) << 2;
                *(uint4*)&A[lr * 32 + gi] = aReg[c];
                *(uint4*)&B[lr * 32 + gi] = bReg[c];
            }
        }
        __syncthreads();

        if (i + 1 < NCHUNK) {
            const int k0n = (i + 1) * 32;
            #pragma unroll
            for (int c = 0; c < 4; c++) {
                aReg[c] = *(const uint4*)(Asrc + k0n + 8 * c + 4 * lh);
                bReg[c] = *(const uint4*)(Bsrc + k0n + 8 * c + 4 * lh);
            }
        }

        const uint32_t* A = As[p];
        const uint32_t* B = Bs[p];
        #pragma unroll
        for (int s = 0; s < 4; s++) {
            const int off = (((2 * s + (tig >> 1)) ^ fL) << 2) + 2 * (tig & 1);
            uint2 alo[4], ahi[4], bfr[4];
            #pragma unroll
            for (int mt = 0; mt < 4; mt++) {
                const int mr = wm * 64 + mt * 16 + gid;
                alo[mt] = *(const uint2*)&A[mr * 32 + off];
                ahi[mt] = *(const uint2*)&A[(mr + 8) * 32 + off];
            }
            #pragma unroll
            for (int nt = 0; nt < 4; nt++)
                bfr[nt] = *(const uint2*)&B[(wn * 32 + nt * 8 + gid) * 32 + off];
            #pragma unroll
            for (int mt = 0; mt < 4; mt++)
                #pragma unroll
                for (int nt = 0; nt < 4; nt++)
                    mma_tf32(acc[mt][nt][0], acc[mt][nt][1],
                             acc[mt][nt][2], acc[mt][nt][3],
                             alo[mt].x, ahi[mt].x, alo[mt].y, ahi[mt].y,
                             bfr[nt].x, bfr[nt].y);
        }
        __syncthreads();
    }

    // ---- epilogue ----
    if (which < 2) {
        float* C = (which == 0) ? g_q : g_k;
        #pragma unroll
        for (int mt = 0; mt < 4; mt++) {
            const int m  = m0 + wm * 64 + mt * 16 + gid;
            const int bb = m >> 11;
            const int nn = m & (SEQ - 1);
            #pragma unroll
            for (int nt = 0; nt < 4; nt++) {
                const int n  = n0 + wn * 32 + nt * 8 + 2 * tig;
                const int hh = n >> 6;
                const int dd = n & 63;
                const float bx = bias[n], by = bias[n + 1];
                float* base = C + ((size_t)(bb * HEADS + hh) * SEQ + nn) * DHEAD
                            + ilw(dd);
                base[0] = __uint_as_float(tf32_rn((acc[mt][nt][0] + bx) * qscale));
                base[2] = __uint_as_float(tf32_rn((acc[mt][nt][1] + by) * qscale));
                base[512]     = __uint_as_float(tf32_rn((acc[mt][nt][2] + bx) * qscale));
                base[512 + 2] = __uint_as_float(tf32_rn((acc[mt][nt][3] + by) * qscale));
            }
        }
    } else {
        // V: transposed fp16 store g_v16[(bb*16+hh)*64 + dd][key]
        #pragma unroll
        for (int mt = 0; mt < 4; mt++) {
            const int m   = m0 + wm * 64 + mt * 16 + gid;
            const int bb  = m >> 11;
            const int key = m & (SEQ - 1);
            #pragma unroll
            for (int nt = 0; nt < 4; nt++) {
                const int n  = n0 + wn * 32 + nt * 8 + 2 * tig;
                const int hh = n >> 6;
                const int dd = n & 63;
                const float bx = bias[n], by = bias[n + 1];
                __half* base = g_v16
                    + ((size_t)(bb * HEADS + hh) * DHEAD + dd) * SEQ + key;
                base[0]       = __float2half_rn(acc[mt][nt][0] + bx);
                base[SEQ]     = __float2half_rn(acc[mt][nt][1] + by);
                base[8]       = __float2half_rn(acc[mt][nt][2] + bx);
                base[SEQ + 8] = __float2half_rn(acc[mt][nt][3] + by);
            }
        }
    }
}

// ---------------------------------------------------------------------------
// Flash attention: QK^T in tf32 mma (IL64 layout, LDS.64 fragments),
// PV in fp16 m16n8k16 — S C-fragment == A-fragment, so P needs only
// cvt.rn.f16x2 packs (no shuffles).
// SMEM words: Q[0,8192) K0[8192) K1[12288) V0[16384) V1[18432); 80KB.
// V smem: 64 d-rows x 32 half2-words, word-XOR swizzle w' = w ^ (4*(d&7)).
// ---------------------------------------------------------------------------
#define ATTN_SMEM 81920

__global__ __launch_bounds__(128) void attn_mma(float* __restrict__ out)
{
    extern __shared__ uint32_t sm[];
    const uint32_t sb = smem_u32(sm);
    const uint32_t KOFF[2] = { 8192u, 12288u };
    const uint32_t VOFF[2] = { 16384u, 18432u };

    const int bh = blockIdx.y;               // 0..63
    const int q0 = blockIdx.x * 128;
    const uint32_t* Qb = (const uint32_t*)g_q + (size_t)bh * SEQ * DHEAD;
    const uint32_t* Kb = (const uint32_t*)g_k + (size_t)bh * SEQ * DHEAD;
    const __half*   Vb = g_v16 + (size_t)bh * DHEAD * SEQ;   // [d][key]

    const int tid  = threadIdx.x;
    const int lane = tid & 31;
    const int g    = lane >> 2, t = lane & 3;
    const int wrow = (tid >> 5) * 32;

    // loaders: 2 threads per row
    const int lr = tid >> 1;            // 0..63 (K: key row, V: d row)
    const int lh = tid & 1;
    const int lx = 2 * (lr & 3);        // K granule XOR
    const int vx = lr & 7;              // V 16B-group XOR

    // ---- prologue: stage Q + tiles 0,1 ----
    {
        const int qx = 2 * (tid & 3);
        const uint32_t* qsrc = Qb + (size_t)(q0 + tid) * DHEAD;
        const uint32_t qdst = sb + tid * 256;
        #pragma unroll
        for (int c = 0; c < 16; c++)
            CP16(qdst + ((c ^ qx) << 4), qsrc + 4 * c);
    }
    #pragma unroll
    for (int pb = 0; pb < 2; pb++) {
        const uint32_t* ksrc = Kb + (size_t)(pb * 64 + lr) * DHEAD;
        const __half*   vsrc = Vb + (size_t)lr * SEQ + pb * 64;
        const uint32_t kdst = sb + (KOFF[pb] + lr * 64) * 4;
        const uint32_t vdst = sb + (VOFF[pb] + lr * 32) * 4;
        #pragma unroll
        for (int c = 0; c < 8; c++) {
            const int gi = ((2 * c + lh) ^ lx) << 4;
            CP16(kdst + gi, ksrc + 8 * c + 4 * lh);
        }
        #pragma unroll
        for (int c = 0; c < 4; c++) {
            const int i = 4 * lh + c;          // 16B group 0..7 (8 keys each)
            CP16(vdst + ((i ^ vx) << 4), vsrc + 8 * i);
        }
        CP_COMMIT();
    }
    CP_WAIT1();
    __syncthreads();

    float o[2][8][4];
    #pragma unroll
    for (int mb = 0; mb < 2; mb++)
        #pragma unroll
        for (int nt = 0; nt < 8; nt++)
            #pragma unroll
            for (int r = 0; r < 4; r++) o[mb][nt][r] = 0.f;
    float mrow[2][2], lsum[2][2];
    #pragma unroll
    for (int mb = 0; mb < 2; mb++) {
        mrow[mb][0] = -1e30f; mrow[mb][1] = -1e30f;
        lsum[mb][0] = 0.f;    lsum[mb][1] = 0.f;
    }

    const int fL = 2 * (g & 3);
    const int NKT = SEQ / 64;
    #pragma unroll 1
    for (int kt = 0; kt < NKT; kt++) {
        const int p = kt & 1;
        const uint32_t* Ks = sm + KOFF[p];
        const uint32_t* Vs = sm + VOFF[p];

        // ---- S = Q K^T (tf32) ----
        float s[2][8][4];
        #pragma unroll
        for (int mb = 0; mb < 2; mb++)
            #pragma unroll
            for (int nt = 0; nt < 8; nt++)
                #pragma unroll
                for (int r = 0; r < 4; r++) s[mb][nt][r] = 0.f;

        #pragma unroll
        for (int ss = 0; ss < 8; ss++) {
            const int off = (((2 * ss + (t >> 1)) ^ fL) << 2) + 2 * (t & 1);
            uint2 qa[2][2];
            #pragma unroll
            for (int mb = 0; mb < 2; mb++) {
                const int rr = (wrow + mb * 16 + g) * 64;
                qa[mb][0] = *(const uint2*)&sm[rr + off];
                qa[mb][1] = *(const uint2*)&sm[rr + 512 + off];
            }
            #pragma unroll
            for (int nt = 0; nt < 8; nt++) {
                const uint2 kb = *(const uint2*)&Ks[(nt * 8 + g) * 64 + off];
                mma_tf32(s[0][nt][0], s[0][nt][1], s[0][nt][2], s[0][nt][3],
                         qa[0][0].x, qa[0][1].x, qa[0][0].y, qa[0][1].y,
                         kb.x, kb.y);
                mma_tf32(s[1][nt][0], s[1][nt][1], s[1][nt][2], s[1][nt][3],
                         qa[1][0].x, qa[1][1].x, qa[1][0].y, qa[1][1].y,
                         kb.x, kb.y);
            }
        }

        // ---- online softmax per m-block ----
        #pragma unroll
        for (int mb = 0; mb < 2; mb++) {
            float mx0 = -1e30f, mx1 = -1e30f;
            #pragma unroll
            for (int nt = 0; nt < 8; nt++) {
                mx0 = fmaxf(mx0, fmaxf(s[mb][nt][0], s[mb][nt][1]));
                mx1 = fmaxf(mx1, fmaxf(s[mb][nt][2], s[mb][nt][3]));
            }
            #pragma unroll
            for (int off = 1; off <= 2; off <<= 1) {
                mx0 = fmaxf(mx0, __shfl_xor_sync(0xffffffffu, mx0, off));
                mx1 = fmaxf(mx1, __shfl_xor_sync(0xffffffffu, mx1, off));
            }
            const float mn0 = fmaxf(mrow[mb][0], mx0);
            const float mn1 = fmaxf(mrow[mb][1], mx1);
            const float al0 = __expf(mrow[mb][0] - mn0);
            const float al1 = __expf(mrow[mb][1] - mn1);
            mrow[mb][0] = mn0; mrow[mb][1] = mn1;
            float sum0 = 0.f, sum1 = 0.f;
            #pragma unroll
            for (int nt = 0; nt < 8; nt++) {
                s[mb][nt][0] = __expf(s[mb][nt][0] - mn0);
                s[mb][nt][1] = __expf(s[mb][nt][1] - mn0);
                s[mb][nt][2] = __expf(s[mb][nt][2] - mn1);
                s[mb][nt][3] = __expf(s[mb][nt][3] - mn1);
                sum0 += s[mb][nt][0] + s[mb][nt][1];
                sum1 += s[mb][nt][2] + s[mb][nt][3];
            }
            #pragma unroll
            for (int off = 1; off <= 2; off <<= 1) {
                sum0 += __shfl_xor_sync(0xffffffffu, sum0, off);
                sum1 += __shfl_xor_sync(0xffffffffu, sum1, off);
            }
            lsum[mb][0] = lsum[mb][0] * al0 + sum0;
            lsum[mb][1] = lsum[mb][1] * al1 + sum1;
            #pragma unroll
            for (int nt = 0; nt < 8; nt++) {
                o[mb][nt][0] *= al0; o[mb][nt][1] *= al0;
                o[mb][nt][2] *= al1; o[mb][nt][3] *= al1;
            }
        }

        // ---- O += P V (fp16 m16n8k16; C-fragment feeds A directly) ----
        #pragma unroll
        for (int j = 0; j < 4; j++) {          // 16-key chunks
            uint32_t pa[2][4];
            #pragma unroll
            for (int mb = 0; mb < 2; mb++) {
                pa[mb][0] = pack_h2(s[mb][2 * j][0],     s[mb][2 * j][1]);
                pa[mb][1] = pack_h2(s[mb][2 * j][2],     s[mb][2 * j][3]);
                pa[mb][2] = pack_h2(s[mb][2 * j + 1][0], s[mb][2 * j + 1][1]);
                pa[mb][3] = pack_h2(s[mb][2 * j + 1][2], s[mb][2 * j + 1][3]);
            }
            const int w0 = (8 * j + t)     ^ (4 * g);
            const int w1 = (8 * j + 4 + t) ^ (4 * g);
            #pragma unroll
            for (int nt = 0; nt < 8; nt++) {
                const int row = (nt * 8 + g) * 32;
                const uint32_t b0 = Vs[row + w0];
                const uint32_t b1 = Vs[row + w1];
                mma_f16(o[0][nt][0], o[0][nt][1], o[0][nt][2], o[0][nt][3],
                        pa[0][0], pa[0][1], pa[0][2], pa[0][3], b0, b1);
                mma_f16(o[1][nt][0], o[1][nt][1], o[1][nt][2], o[1][nt][3],
                        pa[1][0], pa[1][1], pa[1][2], pa[1][3], b0, b1);
            }
        }

        __syncthreads();   // all warps done reading buf p
        if (kt + 2 < NKT) {
            const uint32_t* ksrc = Kb + (size_t)((kt + 2) * 64 + lr) * DHEAD;
            const __half*   vsrc = Vb + (size_t)lr * SEQ + (kt + 2) * 64;
            const uint32_t kdst = sb + (KOFF[p] + lr * 64) * 4;
            const uint32_t vdst = sb + (VOFF[p] + lr * 32) * 4;
            #pragma unroll
            for (int c = 0; c < 8; c++) {
                const int gi = ((2 * c + lh) ^ lx) << 4;
                CP16(kdst + gi, ksrc + 8 * c + 4 * lh);
            }
            #pragma unroll
            for (int c = 0; c < 4; c++) {
                const int i = 4 * lh + c;
                CP16(vdst + ((i ^ vx) << 4), vsrc + 8 * i);
            }
        }
        CP_COMMIT();
        CP_WAIT1();
        __syncthreads();
    }

    // ---- epilogue ----
    const int bb = bh >> 4, hh = bh & 15;
    #pragma unroll
    for (int mb = 0; mb < 2; mb++) {
        const float inv0 = 1.f / lsum[mb][0];
        const float inv1 = 1.f / lsum[mb][1];
        const int rr0 = q0 + wrow + mb * 16 + g;
        const int rr1 = rr0 + 8;
        #pragma unroll
        for (int nt = 0; nt < 8; nt++) {
            const int d = hh * DHEAD + nt * 8 + 2 * t;
            *(float2*)(out + ((size_t)bb * SEQ + rr0) * (HEADS * DHEAD) + d) =
                make_float2(o[mb][nt][0] * inv0, o[mb][nt][1] * inv0);
            *(float2*)(out + ((size_t)bb * SEQ + rr1) * (HEADS * DHEAD) + d) =
                make_float2(o[mb][nt][2] * inv1, o[mb][nt][3] * inv1);
        }
    }
}

// ---------------------------------------------------------------------------
extern "C" void kernel_launch(void* const* d_in, const int* in_sizes, int n_in,
                              void* d_out, int out_size) {
    const float* x    = (const float*)d_in[0];
    const float* ln_w = (const float*)d_in[1];
    const float* ln_b = (const float*)d_in[2];
    const float* wq   = (const float*)d_in[3];
    const float* bq   = (const float*)d_in[4];
    const float* wk   = (const float*)d_in[5];
    const float* bk   = (const float*)d_in[6];
    const float* wv   = (const float*)d_in[7];
    const float* bv   = (const float*)d_in[8];
    float* out = (float*)d_out;

    cudaFuncSetAttribute(qkv_gemm_mma,
                         cudaFuncAttributeMaxDynamicSharedMemorySize, 65536);
    cudaFuncSetAttribute(attn_mma,
                         cudaFuncAttributeMaxDynamicSharedMemorySize, ATTN_SMEM);

    ln_kernel<<<MTOT, 256>>>(x, ln_w, ln_b);
    cvt_w<<<dim3(32, 32, 3), 256>>>(wq, wk, wv);
    qkv_gemm_mma<<<dim3(DIM / 128, MTOT / 128, 3), 256, 65536>>>(bq, bk, bv);
    attn_mma<<<dim3(SEQ / 128, BATCH * HEADS), 128, ATTN_SMEM>>>(out);
}

// round 10
// speedup vs baseline: 6.1729x; 2.1564x over previous
#include <cuda_runtime.h>
#include <cuda_fp16.h>
#include <cstdint>

#define DIM    1024
#define HEADS  16
#define DHEAD  64
#define BATCH  4
#define SEQ    2048
#define MTOT   (BATCH * SEQ)   // 8192

// All fp16, word(=half2)-interleaved per 8-word group: logical word l ->
// physical 2*(l&3) + (l>>2). Fragment pairs (k,k+8-halves) become one LDS.64.
// g_h16 : [row][1024]
// g_q16 : [b,h,n][64]  (pre-scaled by 0.125)
// g_k16 : [b,h,n][64]
// g_v16 : TRANSPOSED [b,h,d][2048 keys]
// g_wt16: [z][n][1024] (W transposed)
__device__ __half g_h16[(size_t)MTOT * DIM];
__device__ __half g_q16[(size_t)MTOT * DIM];
__device__ __half g_k16[(size_t)MTOT * DIM];
__device__ __half g_v16[(size_t)MTOT * DIM];
__device__ __half g_wt16[(size_t)3 * DIM * DIM];

// pack two f32 -> half2 word (lo = first arg)
__device__ __forceinline__ uint32_t pack_h2(float lo, float hi) {
    uint32_t r;
    asm("cvt.rn.f16x2.f32 %0, %1, %2;" : "=r"(r) : "f"(hi), "f"(lo));
    return r;
}

// interleaved physical position of logical word w within its 8-word group
__device__ __forceinline__ int ilw2(int w) {
    return (w & ~7) | (2 * (w & 3) + ((w >> 2) & 1));
}

__device__ __forceinline__ uint32_t smem_u32(const void* p) {
    uint32_t a;
    asm("{ .reg .u64 t; cvta.to.shared.u64 t, %1; cvt.u32.u64 %0, t; }"
        : "=r"(a) : "l"(p));
    return a;
}

#define CP16(dst, src) \
    asm volatile("cp.async.cg.shared.global [%0], [%1], 16;" \
                 :: "r"(dst), "l"(src) : "memory")
#define CP_COMMIT() asm volatile("cp.async.commit_group;" ::: "memory")
#define CP_WAIT1()  asm volatile("cp.async.wait_group 1;" ::: "memory")

__device__ __forceinline__ void mma_f16(
    float& d0, float& d1, float& d2, float& d3,
    uint32_t a0, uint32_t a1, uint32_t a2, uint32_t a3,
    uint32_t b0, uint32_t b1)
{
    asm volatile(
        "mma.sync.aligned.m16n8k16.row.col.f32.f16.f16.f32 "
        "{%0,%1,%2,%3}, {%4,%5,%6,%7}, {%8,%9}, {%0,%1,%2,%3};"
        : "+f"(d0), "+f"(d1), "+f"(d2), "+f"(d3)
        : "r"(a0), "r"(a1), "r"(a2), "r"(a3), "r"(b0), "r"(b1));
}

// ---------------------------------------------------------------------------
// LayerNorm -> fp16 interleaved rows in g_h16
// ---------------------------------------------------------------------------
__global__ __launch_bounds__(256) void ln_kernel(
    const float* __restrict__ x,
    const float* __restrict__ w,
    const float* __restrict__ bvec)
{
    const int row = blockIdx.x;
    const int t = threadIdx.x;
    float4 v = ((const float4*)(x + (size_t)row * DIM))[t];
    float s  = v.x + v.y + v.z + v.w;
    float ss = v.x * v.x + v.y * v.y + v.z * v.z + v.w * v.w;
    #pragma unroll
    for (int off = 16; off; off >>= 1) {
        s  += __shfl_xor_sync(0xffffffffu, s,  off);
        ss += __shfl_xor_sync(0xffffffffu, ss, off);
    }
    __shared__ float sh[16];
    const int wid = t >> 5, lane = t & 31;
    if (lane == 0) { sh[wid] = s; sh[8 + wid] = ss; }
    __syncthreads();
    float ts = 0.f, tss = 0.f;
    #pragma unroll
    for (int i = 0; i < 8; i++) { ts += sh[i]; tss += sh[8 + i]; }
    const float mu  = ts * (1.0f / DIM);
    const float var = tss * (1.0f / DIM) - mu * mu;
    const float r   = rsqrtf(var + 1e-5f);
    float4 wv = ((const float4*)w)[t];
    float4 bv = ((const float4*)bvec)[t];
    const float o0 = (v.x - mu) * r * wv.x + bv.x;
    const float o1 = (v.y - mu) * r * wv.y + bv.y;
    const float o2 = (v.z - mu) * r * wv.z + bv.z;
    const float o3 = (v.w - mu) * r * wv.w + bv.w;
    uint32_t* dst = (uint32_t*)(g_h16 + (size_t)row * DIM);
    dst[ilw2(2 * t)]     = pack_h2(o0, o1);
    dst[ilw2(2 * t + 1)] = pack_h2(o2, o3);
}

// ---------------------------------------------------------------------------
// One-shot: transpose W -> g_wt16[z][n][k interleaved]. grid(32,32,3).
// ---------------------------------------------------------------------------
__global__ __launch_bounds__(256) void cvt_w(
    const float* __restrict__ Wq,
    const float* __restrict__ Wk,
    const float* __restrict__ Wv)
{
    __shared__ float tile[32][33];
    const int z = blockIdx.z;
    const float* src = (z == 0) ? Wq : (z == 1) ? Wk : Wv;
    const int k0 = blockIdx.x * 32, n0 = blockIdx.y * 32;
    {
        const int kl = threadIdx.x >> 3, nl4 = (threadIdx.x & 7) * 4;
        float4 v = *(const float4*)(src + (size_t)(k0 + kl) * DIM + n0 + nl4);
        tile[kl][nl4 + 0] = v.x;
        tile[kl][nl4 + 1] = v.y;
        tile[kl][nl4 + 2] = v.z;
        tile[kl][nl4 + 3] = v.w;
    }
    __syncthreads();
    const int nl = threadIdx.x >> 3, kb = (threadIdx.x & 7) * 4;
    uint32_t* dst = (uint32_t*)(g_wt16 + (size_t)z * DIM * DIM
                                + (size_t)(n0 + nl) * DIM);
    const int w0 = (k0 + kb) >> 1;   // even
    dst[ilw2(w0)]     = pack_h2(tile[kb + 0][nl], tile[kb + 1][nl]);
    dst[ilw2(w0 + 1)] = pack_h2(tile[kb + 2][nl], tile[kb + 3][nl]);
}

// ---------------------------------------------------------------------------
// QKV GEMM, fp16 m16n8k16, CTA 128x128, K-chunk 64 (4 k16 steps), 16 chunks,
// 8 warps 2(m)x4(n), cp.async double buffer.
// Tiles: [row 0..127][32 words], unit(8B) XOR (row&3)<<2. Fragments: LDS.64 at
// unit u = (4s+t)^((g&3)<<2) for every A/B row (all rows ≡ g mod 8).
// SMEM words: A0 0 | A1 4096 | B0 8192 | B1 12288  (64KB).
// ---------------------------------------------------------------------------
#define GEMM_SMEM 65536

__global__ __launch_bounds__(256) void qkv_gemm_mma(
    const float* __restrict__ Bq,
    const float* __restrict__ Bk,
    const float* __restrict__ Bv)
{
    extern __shared__ uint32_t smem[];
    const uint32_t sb = smem_u32(smem);

    const int which = blockIdx.z;
    const __half* W = g_wt16 + (size_t)which * DIM * DIM;
    const float* bias = (which == 0) ? Bq : (which == 1) ? Bk : Bv;
    const float qscale = (which == 0) ? 0.125f : 1.0f;

    const int tid  = threadIdx.x;
    const int lane = tid & 31;
    const int gid  = lane >> 2;      // 0..7
    const int tig  = lane & 3;       // 0..3
    const int wm   = (tid >> 5) & 1;
    const int wn   = tid >> 6;

    const int m0 = blockIdx.y * 128;
    const int n0 = blockIdx.x * 128;

    const int lr = tid >> 1;         // loader row 0..127
    const int lh = tid & 1;
    const int xr = (lr & 3) << 2;    // unit XOR
    const __half* Asrc = g_h16 + (size_t)(m0 + lr) * DIM;
    const __half* Bsrc = W + (size_t)(n0 + lr) * DIM;
    const uint32_t abase = sb + (lr * 32) * 4;          // + p*16384 bytes
    const uint32_t bbase = sb + (8192 + lr * 32) * 4;

    float acc[4][4][4];
    #pragma unroll
    for (int i = 0; i < 4; i++)
        #pragma unroll
        for (int j = 0; j < 4; j++)
            #pragma unroll
            for (int r = 0; r < 4; r++) acc[i][j][r] = 0.f;

    // prologue: chunks 0, 1
    #pragma unroll
    for (int pb = 0; pb < 2; pb++) {
        const int k0 = pb * 64;
        #pragma unroll
        for (int c = 0; c < 4; c++) {
            const int j  = 4 * lh + c;
            const int pu = (2 * j) ^ xr;
            CP16(abase + pb * 16384 + pu * 8, Asrc + k0 + j * 8);
            CP16(bbase + pb * 16384 + pu * 8, Bsrc + k0 + j * 8);
        }
        CP_COMMIT();
    }
    CP_WAIT1();
    __syncthreads();

    const int gx = (gid & 3) << 2;
    const int NCHUNK = DIM / 64;     // 16
    #pragma unroll 1
    for (int i = 0; i < NCHUNK; ++i) {
        const int p = i & 1;
        const uint32_t* A = smem + p * 4096;
        const uint32_t* B = smem + 8192 + p * 4096;

        #pragma unroll
        for (int s = 0; s < 4; s++) {
            const int u2 = 2 * ((4 * s + tig) ^ gx);
            uint2 alo[4], ahi[4], bf[4];
            #pragma unroll
            for (int mt = 0; mt < 4; mt++) {
                const int mr = wm * 64 + mt * 16 + gid;
                alo[mt] = *(const uint2*)&A[mr * 32 + u2];
                ahi[mt] = *(const uint2*)&A[(mr + 8) * 32 + u2];
            }
            #pragma unroll
            for (int nt = 0; nt < 4; nt++)
                bf[nt] = *(const uint2*)&B[(wn * 32 + nt * 8 + gid) * 32 + u2];
            #pragma unroll
            for (int mt = 0; mt < 4; mt++)
                #pragma unroll
                for (int nt = 0; nt < 4; nt++)
                    mma_f16(acc[mt][nt][0], acc[mt][nt][1],
                            acc[mt][nt][2], acc[mt][nt][3],
                            alo[mt].x, ahi[mt].x, alo[mt].y, ahi[mt].y,
                            bf[nt].x, bf[nt].y);
        }

        __syncthreads();
        if (i + 2 < NCHUNK) {
            const int k0 = (i + 2) * 64;
            #pragma unroll
            for (int c = 0; c < 4; c++) {
                const int j  = 4 * lh + c;
                const int pu = (2 * j) ^ xr;
                CP16(abase + p * 16384 + pu * 8, Asrc + k0 + j * 8);
                CP16(bbase + p * 16384 + pu * 8, Bsrc + k0 + j * 8);
            }
        }
        CP_COMMIT();
        CP_WAIT1();
        __syncthreads();
    }

    // ---- epilogue ----
    if (which < 2) {
        uint32_t* C = (uint32_t*)((which == 0) ? g_q16 : g_k16);
        #pragma unroll
        for (int mt = 0; mt < 4; mt++) {
            const int m  = m0 + wm * 64 + mt * 16 + gid;
            const int bb = m >> 11;
            const int nn = m & (SEQ - 1);
            #pragma unroll
            for (int nt = 0; nt < 4; nt++) {
                const int n  = n0 + wn * 32 + nt * 8 + 2 * tig;
                const int hh = n >> 6;
                const int dd = n & 63;
                const float bx = bias[n], by = bias[n + 1];
                const size_t rowb = ((size_t)(bb * HEADS + hh) * SEQ + nn) * 32;
                const int pw = ilw2(dd >> 1);
                C[rowb + pw] = pack_h2((acc[mt][nt][0] + bx) * qscale,
                                       (acc[mt][nt][1] + by) * qscale);
                C[rowb + 8 * 32 + pw] = pack_h2((acc[mt][nt][2] + bx) * qscale,
                                                (acc[mt][nt][3] + by) * qscale);
            }
        }
    } else {
        // V transposed: g_v16[(bb*16+hh)*64 + dd][key interleaved]
        #pragma unroll
        for (int mt = 0; mt < 4; mt++) {
            const int m   = m0 + wm * 64 + mt * 16 + gid;
            const int bb  = m >> 11;
            const int key = m & (SEQ - 1);
            const int e   = key & 1;
            const int pwa = ilw2(key >> 1);
            const int pwb = ilw2((key >> 1) + 4);
            #pragma unroll
            for (int nt = 0; nt < 4; nt++) {
                const int n  = n0 + wn * 32 + nt * 8 + 2 * tig;
                const int hh = n >> 6;
                const int dd = n & 63;
                const float bx = bias[n], by = bias[n + 1];
                __half* r0 = g_v16
                    + ((size_t)(bb * HEADS + hh) * DHEAD + dd) * SEQ;
                __half* r1 = r0 + SEQ;
                r0[2 * pwa + e] = __float2half_rn(acc[mt][nt][0] + bx);
                r1[2 * pwa + e] = __float2half_rn(acc[mt][nt][1] + by);
                r0[2 * pwb + e] = __float2half_rn(acc[mt][nt][2] + bx);
                r1[2 * pwb + e] = __float2half_rn(acc[mt][nt][3] + by);
            }
        }
    }
}

// ---------------------------------------------------------------------------
// Flash attention, all-fp16 mma (m16n8k16), 128 threads, 4 warps x 32 Q-rows.
// Q/K/V rows: 32 interleaved words, unit XOR (row&3)<<2; every fragment LDS.64.
// SMEM words: Q[0,4096) K0[4096) K1[6144) V0[8192) V1[10240); 48KB.
// ---------------------------------------------------------------------------
#define ATTN_SMEM 49152

__global__ __launch_bounds__(128) void attn_mma(float* __restrict__ out)
{
    extern __shared__ uint32_t sm[];
    const uint32_t sb = smem_u32(sm);
    const uint32_t KOFF[2] = { 4096u, 6144u };
    const uint32_t VOFF[2] = { 8192u, 10240u };

    const int bh = blockIdx.y;               // 0..63
    const int q0 = blockIdx.x * 128;
    const __half* Qb = g_q16 + (size_t)bh * SEQ * DHEAD;
    const __half* Kb = g_k16 + (size_t)bh * SEQ * DHEAD;
    const __half* Vb = g_v16 + (size_t)bh * DHEAD * SEQ;   // [d][key]

    const int tid  = threadIdx.x;
    const int lane = tid & 31;
    const int g    = lane >> 2, t = lane & 3;
    const int wrow = (tid >> 5) * 32;

    const int lr = tid >> 1;            // 0..63
    const int lh = tid & 1;
    const int xr = (lr & 3) << 2;

    // ---- prologue: stage Q + tiles 0,1 ----
    {
        const int qx = (tid & 3) << 2;
        const __half* qsrc = Qb + (size_t)(q0 + tid) * DHEAD;
        const uint32_t qdst = sb + tid * 128;   // row*32 words *4B
        #pragma unroll
        for (int c = 0; c < 8; c++) {
            const int pu = (2 * c) ^ qx;
            CP16(qdst + pu * 8, qsrc + c * 8);
        }
    }
    #pragma unroll
    for (int pb = 0; pb < 2; pb++) {
        const __half* ksrc = Kb + (size_t)(pb * 64 + lr) * DHEAD;
        const __half* vsrc = Vb + (size_t)lr * SEQ + pb * 64;
        const uint32_t kdst = sb + (KOFF[pb] + lr * 32) * 4;
        const uint32_t vdst = sb + (VOFF[pb] + lr * 32) * 4;
        #pragma unroll
        for (int c = 0; c < 4; c++) {
            const int j  = 4 * lh + c;
            const int pu = (2 * j) ^ xr;
            CP16(kdst + pu * 8, ksrc + j * 8);
            CP16(vdst + pu * 8, vsrc + j * 8);
        }
        CP_COMMIT();
    }
    CP_WAIT1();
    __syncthreads();

    float o[2][8][4];
    #pragma unroll
    for (int mb = 0; mb < 2; mb++)
        #pragma unroll
        for (int nt = 0; nt < 8; nt++)
            #pragma unroll
            for (int r = 0; r < 4; r++) o[mb][nt][r] = 0.f;
    float mrow[2][2], lsum[2][2];
    #pragma unroll
    for (int mb = 0; mb < 2; mb++) {
        mrow[mb][0] = -1e30f; mrow[mb][1] = -1e30f;
        lsum[mb][0] = 0.f;    lsum[mb][1] = 0.f;
    }

    const int gx = (g & 3) << 2;
    const int NKT = SEQ / 64;
    #pragma unroll 1
    for (int kt = 0; kt < NKT; kt++) {
        const int p = kt & 1;
        const uint32_t* Ks = sm + KOFF[p];
        const uint32_t* Vs = sm + VOFF[p];

        // ---- S = Q K^T (fp16 k16) ----
        float s[2][8][4];
        #pragma unroll
        for (int mb = 0; mb < 2; mb++)
            #pragma unroll
            for (int nt = 0; nt < 8; nt++)
                #pragma unroll
                for (int r = 0; r < 4; r++) s[mb][nt][r] = 0.f;

        #pragma unroll
        for (int ss = 0; ss < 4; ss++) {
            const int u2 = 2 * ((4 * ss + t) ^ gx);
            uint2 qlo[2], qhi[2];
            #pragma unroll
            for (int mb = 0; mb < 2; mb++) {
                const int rq = wrow + mb * 16 + g;
                qlo[mb] = *(const uint2*)&sm[rq * 32 + u2];
                qhi[mb] = *(const uint2*)&sm[(rq + 8) * 32 + u2];
            }
            #pragma unroll
            for (int nt = 0; nt < 8; nt++) {
                const uint2 kf = *(const uint2*)&Ks[(nt * 8 + g) * 32 + u2];
                mma_f16(s[0][nt][0], s[0][nt][1], s[0][nt][2], s[0][nt][3],
                        qlo[0].x, qhi[0].x, qlo[0].y, qhi[0].y, kf.x, kf.y);
                mma_f16(s[1][nt][0], s[1][nt][1], s[1][nt][2], s[1][nt][3],
                        qlo[1].x, qhi[1].x, qlo[1].y, qhi[1].y, kf.x, kf.y);
            }
        }

        // ---- online softmax per m-block ----
        #pragma unroll
        for (int mb = 0; mb < 2; mb++) {
            float mx0 = -1e30f, mx1 = -1e30f;
            #pragma unroll
            for (int nt = 0; nt < 8; nt++) {
                mx0 = fmaxf(mx0, fmaxf(s[mb][nt][0], s[mb][nt][1]));
                mx1 = fmaxf(mx1, fmaxf(s[mb][nt][2], s[mb][nt][3]));
            }
            #pragma unroll
            for (int off = 1; off <= 2; off <<= 1) {
                mx0 = fmaxf(mx0, __shfl_xor_sync(0xffffffffu, mx0, off));
                mx1 = fmaxf(mx1, __shfl_xor_sync(0xffffffffu, mx1, off));
            }
            const float mn0 = fmaxf(mrow[mb][0], mx0);
            const float mn1 = fmaxf(mrow[mb][1], mx1);
            const float al0 = __expf(mrow[mb][0] - mn0);
            const float al1 = __expf(mrow[mb][1] - mn1);
            mrow[mb][0] = mn0; mrow[mb][1] = mn1;
            float sum0 = 0.f, sum1 = 0.f;
            #pragma unroll
            for (int nt = 0; nt < 8; nt++) {
                s[mb][nt][0] = __expf(s[mb][nt][0] - mn0);
                s[mb][nt][1] = __expf(s[mb][nt][1] - mn0);
                s[mb][nt][2] = __expf(s[mb][nt][2] - mn1);
                s[mb][nt][3] = __expf(s[mb][nt][3] - mn1);
                sum0 += s[mb][nt][0] + s[mb][nt][1];
                sum1 += s[mb][nt][2] + s[mb][nt][3];
            }
            #pragma unroll
            for (int off = 1; off <= 2; off <<= 1) {
                sum0 += __shfl_xor_sync(0xffffffffu, sum0, off);
                sum1 += __shfl_xor_sync(0xffffffffu, sum1, off);
            }
            lsum[mb][0] = lsum[mb][0] * al0 + sum0;
            lsum[mb][1] = lsum[mb][1] * al1 + sum1;
            #pragma unroll
            for (int nt = 0; nt < 8; nt++) {
                o[mb][nt][0] *= al0; o[mb][nt][1] *= al0;
                o[mb][nt][2] *= al1; o[mb][nt][3] *= al1;
            }
        }

        // ---- O += P V (fp16; S C-fragment feeds A directly) ----
        #pragma unroll
        for (int j = 0; j < 4; j++) {          // 16-key chunks
            uint32_t pa[2][4];
            #pragma unroll
            for (int mb = 0; mb < 2; mb++) {
                pa[mb][0] = pack_h2(s[mb][2 * j][0],     s[mb][2 * j][1]);
                pa[mb][1] = pack_h2(s[mb][2 * j][2],     s[mb][2 * j][3]);
                pa[mb][2] = pack_h2(s[mb][2 * j + 1][0], s[mb][2 * j + 1][1]);
                pa[mb][3] = pack_h2(s[mb][2 * j + 1][2], s[mb][2 * j + 1][3]);
            }
            const int u2 = 2 * ((4 * j + t) ^ gx);
            #pragma unroll
            for (int nt = 0; nt < 8; nt++) {
                const uint2 vb = *(const uint2*)&Vs[(nt * 8 + g) * 32 + u2];
                mma_f16(o[0][nt][0], o[0][nt][1], o[0][nt][2], o[0][nt][3],
                        pa[0][0], pa[0][1], pa[0][2], pa[0][3], vb.x, vb.y);
                mma_f16(o[1][nt][0], o[1][nt][1], o[1][nt][2], o[1][nt][3],
                        pa[1][0], pa[1][1], pa[1][2], pa[1][3], vb.x, vb.y);
            }
        }

        __syncthreads();   // all warps done reading buf p
        if (kt + 2 < NKT) {
            const __half* ksrc = Kb + (size_t)((kt + 2) * 64 + lr) * DHEAD;
            const __half* vsrc = Vb + (size_t)lr * SEQ + (kt + 2) * 64;
            const uint32_t kdst = sb + (KOFF[p] + lr * 32) * 4;
            const uint32_t vdst = sb + (VOFF[p] + lr * 32) * 4;
            #pragma unroll
            for (int c = 0; c < 4; c++) {
                const int j  = 4 * lh + c;
                const int pu = (2 * j) ^ xr;
                CP16(kdst + pu * 8, ksrc + j * 8);
                CP16(vdst + pu * 8, vsrc + j * 8);
            }
        }
        CP_COMMIT();
        CP_WAIT1();
        __syncthreads();
    }

    // ---- epilogue ----
    const int bb = bh >> 4, hh = bh & 15;
    #pragma unroll
    for (int mb = 0; mb < 2; mb++) {
        const float inv0 = 1.f / lsum[mb][0];
        const float inv1 = 1.f / lsum[mb][1];
        const int rr0 = q0 + wrow + mb * 16 + g;
        const int rr1 = rr0 + 8;
        #pragma unroll
        for (int nt = 0; nt < 8; nt++) {
            const int d = hh * DHEAD + nt * 8 + 2 * t;
            *(float2*)(out + ((size_t)bb * SEQ + rr0) * (HEADS * DHEAD) + d) =
                make_float2(o[mb][nt][0] * inv0, o[mb][nt][1] * inv0);
            *(float2*)(out + ((size_t)bb * SEQ + rr1) * (HEADS * DHEAD) + d) =
                make_float2(o[mb][nt][2] * inv1, o[mb][nt][3] * inv1);
        }
    }
}

// ---------------------------------------------------------------------------
extern "C" void kernel_launch(void* const* d_in, const int* in_sizes, int n_in,
                              void* d_out, int out_size) {
    const float* x    = (const float*)d_in[0];
    const float* ln_w = (const float*)d_in[1];
    const float* ln_b = (const float*)d_in[2];
    const float* wq   = (const float*)d_in[3];
    const float* bq   = (const float*)d_in[4];
    const float* wk   = (const float*)d_in[5];
    const float* bk   = (const float*)d_in[6];
    const float* wv   = (const float*)d_in[7];
    const float* bv   = (const float*)d_in[8];
    float* out = (float*)d_out;

    cudaFuncSetAttribute(qkv_gemm_mma,
                         cudaFuncAttributeMaxDynamicSharedMemorySize, GEMM_SMEM);
    cudaFuncSetAttribute(attn_mma,
                         cudaFuncAttributeMaxDynamicSharedMemorySize, ATTN_SMEM);

    ln_kernel<<<MTOT, 256>>>(x, ln_w, ln_b);
    cvt_w<<<dim3(32, 32, 3), 256>>>(wq, wk, wv);
    qkv_gemm_mma<<<dim3(DIM / 128, MTOT / 128, 3), 256, GEMM_SMEM>>>(bq, bk, bv);
    attn_mma<<<dim3(SEQ / 128, BATCH * HEADS), 128, ATTN_SMEM>>>(out);
}

// round 11
// speedup vs baseline: 6.5923x; 1.0679x over previous
#include <cuda_runtime.h>
#include <cuda_fp16.h>
#include <cstdint>

#define DIM    1024
#define HEADS  16
#define DHEAD  64
#define BATCH  4
#define SEQ    2048
#define MTOT   (BATCH * SEQ)   // 8192
#define LOG2E  1.4426950408889634f

// All fp16, word(=half2)-interleaved per 8-word group: logical word l ->
// physical 2*(l&3) + (l>>2). Fragment pairs (k,k+8-halves) become one LDS.64.
// g_h16 : [row][1024]
// g_q16 : [b,h,n][64]  (pre-scaled by 0.125*log2e -> S in log2 domain)
// g_k16 : [b,h,n][64]
// g_v16 : TRANSPOSED [b,h,d][2048 keys]
// g_wt16: [z][n][1024] (W transposed)
__device__ __half g_h16[(size_t)MTOT * DIM];
__device__ __half g_q16[(size_t)MTOT * DIM];
__device__ __half g_k16[(size_t)MTOT * DIM];
__device__ __half g_v16[(size_t)MTOT * DIM];
__device__ __half g_wt16[(size_t)3 * DIM * DIM];

// pack two f32 -> half2 word (lo = first arg)
__device__ __forceinline__ uint32_t pack_h2(float lo, float hi) {
    uint32_t r;
    asm("cvt.rn.f16x2.f32 %0, %1, %2;" : "=r"(r) : "f"(hi), "f"(lo));
    return r;
}

__device__ __forceinline__ uint32_t hsub2_u(uint32_t a, uint32_t b) {
    uint32_t r;
    asm("sub.rn.f16x2 %0, %1, %2;" : "=r"(r) : "r"(a), "r"(b));
    return r;
}

__device__ __forceinline__ uint32_t hadd2_u(uint32_t a, uint32_t b) {
    uint32_t r;
    asm("add.rn.f16x2 %0, %1, %2;" : "=r"(r) : "r"(a), "r"(b));
    return r;
}

__device__ __forceinline__ uint32_t ex2_h2(uint32_t a) {
    uint32_t r;
    asm("ex2.approx.f16x2 %0, %1;" : "=r"(r) : "r"(a));
    return r;
}

__device__ __forceinline__ float ex2f(float x) {
    float r;
    asm("ex2.approx.f32 %0, %1;" : "=f"(r) : "f"(x));
    return r;
}

// sum of the two halves of a half2 word, in f32
__device__ __forceinline__ float h2sumf(uint32_t w) {
    __half2 h = *reinterpret_cast<__half2*>(&w);
    float2 f = __half22float2(h);
    return f.x + f.y;
}

// interleaved physical position of logical word w within its 8-word group
__device__ __forceinline__ int ilw2(int w) {
    return (w & ~7) | (2 * (w & 3) + ((w >> 2) & 1));
}

__device__ __forceinline__ uint32_t smem_u32(const void* p) {
    uint32_t a;
    asm("{ .reg .u64 t; cvta.to.shared.u64 t, %1; cvt.u32.u64 %0, t; }"
        : "=r"(a) : "l"(p));
    return a;
}

#define CP16(dst, src) \
    asm volatile("cp.async.cg.shared.global [%0], [%1], 16;" \
                 :: "r"(dst), "l"(src) : "memory")
#define CP_COMMIT() asm volatile("cp.async.commit_group;" ::: "memory")
#define CP_WAIT1()  asm volatile("cp.async.wait_group 1;" ::: "memory")

__device__ __forceinline__ void mma_f16(
    float& d0, float& d1, float& d2, float& d3,
    uint32_t a0, uint32_t a1, uint32_t a2, uint32_t a3,
    uint32_t b0, uint32_t b1)
{
    asm volatile(
        "mma.sync.aligned.m16n8k16.row.col.f32.f16.f16.f32 "
        "{%0,%1,%2,%3}, {%4,%5,%6,%7}, {%8,%9}, {%0,%1,%2,%3};"
        : "+f"(d0), "+f"(d1), "+f"(d2), "+f"(d3)
        : "r"(a0), "r"(a1), "r"(a2), "r"(a3), "r"(b0), "r"(b1));
}

// ---------------------------------------------------------------------------
// LayerNorm -> fp16 interleaved rows in g_h16
// ---------------------------------------------------------------------------
__global__ __launch_bounds__(256) void ln_kernel(
    const float* __restrict__ x,
    const float* __restrict__ w,
    const float* __restrict__ bvec)
{
    const int row = blockIdx.x;
    const int t = threadIdx.x;
    float4 v = ((const float4*)(x + (size_t)row * DIM))[t];
    float s  = v.x + v.y + v.z + v.w;
    float ss = v.x * v.x + v.y * v.y + v.z * v.z + v.w * v.w;
    #pragma unroll
    for (int off = 16; off; off >>= 1) {
        s  += __shfl_xor_sync(0xffffffffu, s,  off);
        ss += __shfl_xor_sync(0xffffffffu, ss, off);
    }
    __shared__ float sh[16];
    const int wid = t >> 5, lane = t & 31;
    if (lane == 0) { sh[wid] = s; sh[8 + wid] = ss; }
    __syncthreads();
    float ts = 0.f, tss = 0.f;
    #pragma unroll
    for (int i = 0; i < 8; i++) { ts += sh[i]; tss += sh[8 + i]; }
    const float mu  = ts * (1.0f / DIM);
    const float var = tss * (1.0f / DIM) - mu * mu;
    const float r   = rsqrtf(var + 1e-5f);
    float4 wv = ((const float4*)w)[t];
    float4 bv = ((const float4*)bvec)[t];
    const float o0 = (v.x - mu) * r * wv.x + bv.x;
    const float o1 = (v.y - mu) * r * wv.y + bv.y;
    const float o2 = (v.z - mu) * r * wv.z + bv.z;
    const float o3 = (v.w - mu) * r * wv.w + bv.w;
    uint32_t* dst = (uint32_t*)(g_h16 + (size_t)row * DIM);
    dst[ilw2(2 * t)]     = pack_h2(o0, o1);
    dst[ilw2(2 * t + 1)] = pack_h2(o2, o3);
}

// ---------------------------------------------------------------------------
// One-shot: transpose W -> g_wt16[z][n][k interleaved]. grid(32,32,3).
// ---------------------------------------------------------------------------
__global__ __launch_bounds__(256) void cvt_w(
    const float* __restrict__ Wq,
    const float* __restrict__ Wk,
    const float* __restrict__ Wv)
{
    __shared__ float tile[32][33];
    const int z = blockIdx.z;
    const float* src = (z == 0) ? Wq : (z == 1) ? Wk : Wv;
    const int k0 = blockIdx.x * 32, n0 = blockIdx.y * 32;
    {
        const int kl = threadIdx.x >> 3, nl4 = (threadIdx.x & 7) * 4;
        float4 v = *(const float4*)(src + (size_t)(k0 + kl) * DIM + n0 + nl4);
        tile[kl][nl4 + 0] = v.x;
        tile[kl][nl4 + 1] = v.y;
        tile[kl][nl4 + 2] = v.z;
        tile[kl][nl4 + 3] = v.w;
    }
    __syncthreads();
    const int nl = threadIdx.x >> 3, kb = (threadIdx.x & 7) * 4;
    uint32_t* dst = (uint32_t*)(g_wt16 + (size_t)z * DIM * DIM
                                + (size_t)(n0 + nl) * DIM);
    const int w0 = (k0 + kb) >> 1;   // even
    dst[ilw2(w0)]     = pack_h2(tile[kb + 0][nl], tile[kb + 1][nl]);
    dst[ilw2(w0 + 1)] = pack_h2(tile[kb + 2][nl], tile[kb + 3][nl]);
}

// ---------------------------------------------------------------------------
// QKV GEMM, fp16 m16n8k16, CTA 128x128, K-chunk 64 (4 k16 steps), 16 chunks,
// 8 warps 2(m)x4(n), cp.async double buffer.
// ---------------------------------------------------------------------------
#define GEMM_SMEM 65536

__global__ __launch_bounds__(256) void qkv_gemm_mma(
    const float* __restrict__ Bq,
    const float* __restrict__ Bk,
    const float* __restrict__ Bv)
{
    extern __shared__ uint32_t smem[];
    const uint32_t sb = smem_u32(smem);

    const int which = blockIdx.z;
    const __half* W = g_wt16 + (size_t)which * DIM * DIM;
    const float* bias = (which == 0) ? Bq : (which == 1) ? Bk : Bv;
    const float qscale = (which == 0) ? 0.125f * LOG2E : 1.0f;

    const int tid  = threadIdx.x;
    const int lane = tid & 31;
    const int gid  = lane >> 2;      // 0..7
    const int tig  = lane & 3;       // 0..3
    const int wm   = (tid >> 5) & 1;
    const int wn   = tid >> 6;

    const int m0 = blockIdx.y * 128;
    const int n0 = blockIdx.x * 128;

    const int lr = tid >> 1;         // loader row 0..127
    const int lh = tid & 1;
    const int xr = (lr & 3) << 2;    // unit XOR
    const __half* Asrc = g_h16 + (size_t)(m0 + lr) * DIM;
    const __half* Bsrc = W + (size_t)(n0 + lr) * DIM;
    const uint32_t abase = sb + (lr * 32) * 4;          // + p*16384 bytes
    const uint32_t bbase = sb + (8192 + lr * 32) * 4;

    float acc[4][4][4];
    #pragma unroll
    for (int i = 0; i < 4; i++)
        #pragma unroll
        for (int j = 0; j < 4; j++)
            #pragma unroll
            for (int r = 0; r < 4; r++) acc[i][j][r] = 0.f;

    // prologue: chunks 0, 1
    #pragma unroll
    for (int pb = 0; pb < 2; pb++) {
        const int k0 = pb * 64;
        #pragma unroll
        for (int c = 0; c < 4; c++) {
            const int j  = 4 * lh + c;
            const int pu = (2 * j) ^ xr;
            CP16(abase + pb * 16384 + pu * 8, Asrc + k0 + j * 8);
            CP16(bbase + pb * 16384 + pu * 8, Bsrc + k0 + j * 8);
        }
        CP_COMMIT();
    }
    CP_WAIT1();
    __syncthreads();

    const int gx = (gid & 3) << 2;
    const int NCHUNK = DIM / 64;     // 16
    #pragma unroll 1
    for (int i = 0; i < NCHUNK; ++i) {
        const int p = i & 1;
        const uint32_t* A = smem + p * 4096;
        const uint32_t* B = smem + 8192 + p * 4096;

        #pragma unroll
        for (int s = 0; s < 4; s++) {
            const int u2 = 2 * ((4 * s + tig) ^ gx);
            uint2 alo[4], ahi[4], bf[4];
            #pragma unroll
            for (int mt = 0; mt < 4; mt++) {
                const int mr = wm * 64 + mt * 16 + gid;
                alo[mt] = *(const uint2*)&A[mr * 32 + u2];
                ahi[mt] = *(const uint2*)&A[(mr + 8) * 32 + u2];
            }
            #pragma unroll
            for (int nt = 0; nt < 4; nt++)
                bf[nt] = *(const uint2*)&B[(wn * 32 + nt * 8 + gid) * 32 + u2];
            #pragma unroll
            for (int mt = 0; mt < 4; mt++)
                #pragma unroll
                for (int nt = 0; nt < 4; nt++)
                    mma_f16(acc[mt][nt][0], acc[mt][nt][1],
                            acc[mt][nt][2], acc[mt][nt][3],
                            alo[mt].x, ahi[mt].x, alo[mt].y, ahi[mt].y,
                            bf[nt].x, bf[nt].y);
        }

        __syncthreads();
        if (i + 2 < NCHUNK) {
            const int k0 = (i + 2) * 64;
            #pragma unroll
            for (int c = 0; c < 4; c++) {
                const int j  = 4 * lh + c;
                const int pu = (2 * j) ^ xr;
                CP16(abase + p * 16384 + pu * 8, Asrc + k0 + j * 8);
                CP16(bbase + p * 16384 + pu * 8, Bsrc + k0 + j * 8);
            }
        }
        CP_COMMIT();
        CP_WAIT1();
        __syncthreads();
    }

    // ---- epilogue ----
    if (which < 2) {
        uint32_t* C = (uint32_t*)((which == 0) ? g_q16 : g_k16);
        #pragma unroll
        for (int mt = 0; mt < 4; mt++) {
            const int m  = m0 + wm * 64 + mt * 16 + gid;
            const int bb = m >> 11;
            const int nn = m & (SEQ - 1);
            #pragma unroll
            for (int nt = 0; nt < 4; nt++) {
                const int n  = n0 + wn * 32 + nt * 8 + 2 * tig;
                const int hh = n >> 6;
                const int dd = n & 63;
                const float bx = bias[n], by = bias[n + 1];
                const size_t rowb = ((size_t)(bb * HEADS + hh) * SEQ + nn) * 32;
                const int pw = ilw2(dd >> 1);
                C[rowb + pw] = pack_h2((acc[mt][nt][0] + bx) * qscale,
                                       (acc[mt][nt][1] + by) * qscale);
                C[rowb + 8 * 32 + pw] = pack_h2((acc[mt][nt][2] + bx) * qscale,
                                                (acc[mt][nt][3] + by) * qscale);
            }
        }
    } else {
        // V transposed: g_v16[(bb*16+hh)*64 + dd][key interleaved]
        #pragma unroll
        for (int mt = 0; mt < 4; mt++) {
            const int m   = m0 + wm * 64 + mt * 16 + gid;
            const int bb  = m >> 11;
            const int key = m & (SEQ - 1);
            const int e   = key & 1;
            const int pwa = ilw2(key >> 1);
            const int pwb = ilw2((key >> 1) + 4);
            #pragma unroll
            for (int nt = 0; nt < 4; nt++) {
                const int n  = n0 + wn * 32 + nt * 8 + 2 * tig;
                const int hh = n >> 6;
                const int dd = n & 63;
                const float bx = bias[n], by = bias[n + 1];
                __half* r0 = g_v16
                    + ((size_t)(bb * HEADS + hh) * DHEAD + dd) * SEQ;
                __half* r1 = r0 + SEQ;
                r0[2 * pwa + e] = __float2half_rn(acc[mt][nt][0] + bx);
                r1[2 * pwa + e] = __float2half_rn(acc[mt][nt][1] + by);
                r0[2 * pwb + e] = __float2half_rn(acc[mt][nt][2] + bx);
                r1[2 * pwb + e] = __float2half_rn(acc[mt][nt][3] + by);
            }
        }
    }
}

// ---------------------------------------------------------------------------
// Flash attention, all-fp16 mma (m16n8k16), softmax in log2 domain with
// ex2.approx.f16x2. 128 threads, 4 warps x 32 Q-rows.
// SMEM words: Q[0,4096) K0[4096) K1[6144) V0[8192) V1[10240); 48KB.
// ---------------------------------------------------------------------------
#define ATTN_SMEM 49152

__global__ __launch_bounds__(128) void attn_mma(float* __restrict__ out)
{
    extern __shared__ uint32_t sm[];
    const uint32_t sb = smem_u32(sm);
    const uint32_t KOFF[2] = { 4096u, 6144u };
    const uint32_t VOFF[2] = { 8192u, 10240u };

    const int bh = blockIdx.y;               // 0..63
    const int q0 = blockIdx.x * 128;
    const __half* Qb = g_q16 + (size_t)bh * SEQ * DHEAD;
    const __half* Kb = g_k16 + (size_t)bh * SEQ * DHEAD;
    const __half* Vb = g_v16 + (size_t)bh * DHEAD * SEQ;   // [d][key]

    const int tid  = threadIdx.x;
    const int lane = tid & 31;
    const int g    = lane >> 2, t = lane & 3;
    const int wrow = (tid >> 5) * 32;

    const int lr = tid >> 1;            // 0..63
    const int lh = tid & 1;
    const int xr = (lr & 3) << 2;

    // ---- prologue: stage Q + tiles 0,1 ----
    {
        const int qx = (tid & 3) << 2;
        const __half* qsrc = Qb + (size_t)(q0 + tid) * DHEAD;
        const uint32_t qdst = sb + tid * 128;   // row*32 words *4B
        #pragma unroll
        for (int c = 0; c < 8; c++) {
            const int pu = (2 * c) ^ qx;
            CP16(qdst + pu * 8, qsrc + c * 8);
        }
    }
    #pragma unroll
    for (int pb = 0; pb < 2; pb++) {
        const __half* ksrc = Kb + (size_t)(pb * 64 + lr) * DHEAD;
        const __half* vsrc = Vb + (size_t)lr * SEQ + pb * 64;
        const uint32_t kdst = sb + (KOFF[pb] + lr * 32) * 4;
        const uint32_t vdst = sb + (VOFF[pb] + lr * 32) * 4;
        #pragma unroll
        for (int c = 0; c < 4; c++) {
            const int j  = 4 * lh + c;
            const int pu = (2 * j) ^ xr;
            CP16(kdst + pu * 8, ksrc + j * 8);
            CP16(vdst + pu * 8, vsrc + j * 8);
        }
        CP_COMMIT();
    }
    CP_WAIT1();
    __syncthreads();

    float o[2][8][4];
    #pragma unroll
    for (int mb = 0; mb < 2; mb++)
        #pragma unroll
        for (int nt = 0; nt < 8; nt++)
            #pragma unroll
            for (int r = 0; r < 4; r++) o[mb][nt][r] = 0.f;
    float mrow[2][2], lsum[2][2];
    #pragma unroll
    for (int mb = 0; mb < 2; mb++) {
        mrow[mb][0] = -1e30f; mrow[mb][1] = -1e30f;
        lsum[mb][0] = 0.f;    lsum[mb][1] = 0.f;
    }

    const int gx = (g & 3) << 2;
    const int NKT = SEQ / 64;
    #pragma unroll 1
    for (int kt = 0; kt < NKT; kt++) {
        const int p = kt & 1;
        const uint32_t* Ks = sm + KOFF[p];
        const uint32_t* Vs = sm + VOFF[p];

        // ---- S = Q K^T (fp16 k16), log2 domain ----
        float s[2][8][4];
        #pragma unroll
        for (int mb = 0; mb < 2; mb++)
            #pragma unroll
            for (int nt = 0; nt < 8; nt++)
                #pragma unroll
                for (int r = 0; r < 4; r++) s[mb][nt][r] = 0.f;

        #pragma unroll
        for (int ss = 0; ss < 4; ss++) {
            const int u2 = 2 * ((4 * ss + t) ^ gx);
            uint2 qlo[2], qhi[2];
            #pragma unroll
            for (int mb = 0; mb < 2; mb++) {
                const int rq = wrow + mb * 16 + g;
                qlo[mb] = *(const uint2*)&sm[rq * 32 + u2];
                qhi[mb] = *(const uint2*)&sm[(rq + 8) * 32 + u2];
            }
            #pragma unroll
            for (int nt = 0; nt < 8; nt++) {
                const uint2 kf = *(const uint2*)&Ks[(nt * 8 + g) * 32 + u2];
                mma_f16(s[0][nt][0], s[0][nt][1], s[0][nt][2], s[0][nt][3],
                        qlo[0].x, qhi[0].x, qlo[0].y, qhi[0].y, kf.x, kf.y);
                mma_f16(s[1][nt][0], s[1][nt][1], s[1][nt][2], s[1][nt][3],
                        qlo[1].x, qhi[1].x, qlo[1].y, qhi[1].y, kf.x, kf.y);
            }
        }

        // ---- online softmax (log2 domain, f16x2 exp) ----
        uint32_t ph[2][8][2];   // p as half2: [mb][nt][row-half]
        #pragma unroll
        for (int mb = 0; mb < 2; mb++) {
            float mx0 = -1e30f, mx1 = -1e30f;
            #pragma unroll
            for (int nt = 0; nt < 8; nt++) {
                mx0 = fmaxf(mx0, fmaxf(s[mb][nt][0], s[mb][nt][1]));
                mx1 = fmaxf(mx1, fmaxf(s[mb][nt][2], s[mb][nt][3]));
            }
            #pragma unroll
            for (int off = 1; off <= 2; off <<= 1) {
                mx0 = fmaxf(mx0, __shfl_xor_sync(0xffffffffu, mx0, off));
                mx1 = fmaxf(mx1, __shfl_xor_sync(0xffffffffu, mx1, off));
            }
            const float mn0 = fmaxf(mrow[mb][0], mx0);
            const float mn1 = fmaxf(mrow[mb][1], mx1);
            const float al0 = ex2f(mrow[mb][0] - mn0);
            const float al1 = ex2f(mrow[mb][1] - mn1);
            mrow[mb][0] = mn0; mrow[mb][1] = mn1;
            const uint32_t mh0 = pack_h2(mn0, mn0);
            const uint32_t mh1 = pack_h2(mn1, mn1);
            #pragma unroll
            for (int nt = 0; nt < 8; nt++) {
                uint32_t a0 = pack_h2(s[mb][nt][0], s[mb][nt][1]);
                uint32_t a1 = pack_h2(s[mb][nt][2], s[mb][nt][3]);
                ph[mb][nt][0] = ex2_h2(hsub2_u(a0, mh0));
                ph[mb][nt][1] = ex2_h2(hsub2_u(a1, mh1));
            }
            // row sums: one HADD2 level (single fp16 rounding), finish in f32
            float sum0, sum1;
            {
                uint32_t w0 = hadd2_u(ph[mb][0][0], ph[mb][1][0]);
                uint32_t w1 = hadd2_u(ph[mb][2][0], ph[mb][3][0]);
                uint32_t w2 = hadd2_u(ph[mb][4][0], ph[mb][5][0]);
                uint32_t w3 = hadd2_u(ph[mb][6][0], ph[mb][7][0]);
                sum0 = (h2sumf(w0) + h2sumf(w1)) + (h2sumf(w2) + h2sumf(w3));
                w0 = hadd2_u(ph[mb][0][1], ph[mb][1][1]);
                w1 = hadd2_u(ph[mb][2][1], ph[mb][3][1]);
                w2 = hadd2_u(ph[mb][4][1], ph[mb][5][1]);
                w3 = hadd2_u(ph[mb][6][1], ph[mb][7][1]);
                sum1 = (h2sumf(w0) + h2sumf(w1)) + (h2sumf(w2) + h2sumf(w3));
            }
            #pragma unroll
            for (int off = 1; off <= 2; off <<= 1) {
                sum0 += __shfl_xor_sync(0xffffffffu, sum0, off);
                sum1 += __shfl_xor_sync(0xffffffffu, sum1, off);
            }
            lsum[mb][0] = lsum[mb][0] * al0 + sum0;
            lsum[mb][1] = lsum[mb][1] * al1 + sum1;
            #pragma unroll
            for (int nt = 0; nt < 8; nt++) {
                o[mb][nt][0] *= al0; o[mb][nt][1] *= al0;
                o[mb][nt][2] *= al1; o[mb][nt][3] *= al1;
            }
        }

        // ---- O += P V (fp16; ph feeds A fragments directly) ----
        #pragma unroll
        for (int j = 0; j < 4; j++) {          // 16-key chunks
            const int u2 = 2 * ((4 * j + t) ^ gx);
            #pragma unroll
            for (int nt = 0; nt < 8; nt++) {
                const uint2 vb = *(const uint2*)&Vs[(nt * 8 + g) * 32 + u2];
                mma_f16(o[0][nt][0], o[0][nt][1], o[0][nt][2], o[0][nt][3],
                        ph[0][2 * j][0], ph[0][2 * j][1],
                        ph[0][2 * j + 1][0], ph[0][2 * j + 1][1], vb.x, vb.y);
                mma_f16(o[1][nt][0], o[1][nt][1], o[1][nt][2], o[1][nt][3],
                        ph[1][2 * j][0], ph[1][2 * j][1],
                        ph[1][2 * j + 1][0], ph[1][2 * j + 1][1], vb.x, vb.y);
            }
        }

        __syncthreads();   // all warps done reading buf p
        if (kt + 2 < NKT) {
            const __half* ksrc = Kb + (size_t)((kt + 2) * 64 + lr) * DHEAD;
            const __half* vsrc = Vb + (size_t)lr * SEQ + (kt + 2) * 64;
            const uint32_t kdst = sb + (KOFF[p] + lr * 32) * 4;
            const uint32_t vdst = sb + (VOFF[p] + lr * 32) * 4;
            #pragma unroll
            for (int c = 0; c < 4; c++) {
                const int j  = 4 * lh + c;
                const int pu = (2 * j) ^ xr;
                CP16(kdst + pu * 8, ksrc + j * 8);
                CP16(vdst + pu * 8, vsrc + j * 8);
            }
        }
        CP_COMMIT();
        CP_WAIT1();
        __syncthreads();
    }

    // ---- epilogue ----
    const int bb = bh >> 4, hh = bh & 15;
    #pragma unroll
    for (int mb = 0; mb < 2; mb++) {
        const float inv0 = 1.f / lsum[mb][0];
        const float inv1 = 1.f / lsum[mb][1];
        const int rr0 = q0 + wrow + mb * 16 + g;
        const int rr1 = rr0 + 8;
        #pragma unroll
        for (int nt = 0; nt < 8; nt++) {
            const int d = hh * DHEAD + nt * 8 + 2 * t;
            *(float2*)(out + ((size_t)bb * SEQ + rr0) * (HEADS * DHEAD) + d) =
                make_float2(o[mb][nt][0] * inv0, o[mb][nt][1] * inv0);
            *(float2*)(out + ((size_t)bb * SEQ + rr1) * (HEADS * DHEAD) + d) =
                make_float2(o[mb][nt][2] * inv1, o[mb][nt][3] * inv1);
        }
    }
}

// ---------------------------------------------------------------------------
extern "C" void kernel_launch(void* const* d_in, const int* in_sizes, int n_in,
                              void* d_out, int out_size) {
    const float* x    = (const float*)d_in[0];
    const float* ln_w = (const float*)d_in[1];
    const float* ln_b = (const float*)d_in[2];
    const float* wq   = (const float*)d_in[3];
    const float* bq   = (const float*)d_in[4];
    const float* wk   = (const float*)d_in[5];
    const float* bk   = (const float*)d_in[6];
    const float* wv   = (const float*)d_in[7];
    const float* bv   = (const float*)d_in[8];
    float* out = (float*)d_out;

    cudaFuncSetAttribute(qkv_gemm_mma,
                         cudaFuncAttributeMaxDynamicSharedMemorySize, GEMM_SMEM);
    cudaFuncSetAttribute(attn_mma,
                         cudaFuncAttributeMaxDynamicSharedMemorySize, ATTN_SMEM);

    ln_kernel<<<MTOT, 256>>>(x, ln_w, ln_b);
    cvt_w<<<dim3(32, 32, 3), 256>>>(wq, wk, wv);
    qkv_gemm_mma<<<dim3(DIM / 128, MTOT / 128, 3), 256, GEMM_SMEM>>>(bq, bk, bv);
    attn_mma<<<dim3(SEQ / 128, BATCH * HEADS), 128, ATTN_SMEM>>>(out);
}

// round 12
// speedup vs baseline: 6.8251x; 1.0353x over previous
#include <cuda_runtime.h>
#include <cuda_fp16.h>
#include <cstdint>

#define DIM    1024
#define HEADS  16
#define DHEAD  64
#define BATCH  4
#define SEQ    2048
#define MTOT   (BATCH * SEQ)   // 8192
#define LOG2E  1.4426950408889634f

// All fp16, word(=half2)-interleaved per 8-word group: logical word l ->
// physical 2*(l&3) + (l>>2). Fragment pairs (k,k+8-halves) become one LDS.64.
__device__ __half g_h16[(size_t)MTOT * DIM];
__device__ __half g_q16[(size_t)MTOT * DIM];   // pre-scaled by 0.125*log2e
__device__ __half g_k16[(size_t)MTOT * DIM];
__device__ __half g_v16[(size_t)MTOT * DIM];   // TRANSPOSED [b,h,d][key]
__device__ __half g_wt16[(size_t)3 * DIM * DIM];

__device__ __forceinline__ uint32_t pack_h2(float lo, float hi) {
    uint32_t r;
    asm("cvt.rn.f16x2.f32 %0, %1, %2;" : "=r"(r) : "f"(hi), "f"(lo));
    return r;
}

__device__ __forceinline__ uint32_t hsub2_u(uint32_t a, uint32_t b) {
    uint32_t r;
    asm("sub.rn.f16x2 %0, %1, %2;" : "=r"(r) : "r"(a), "r"(b));
    return r;
}

__device__ __forceinline__ uint32_t hadd2_u(uint32_t a, uint32_t b) {
    uint32_t r;
    asm("add.rn.f16x2 %0, %1, %2;" : "=r"(r) : "r"(a), "r"(b));
    return r;
}

__device__ __forceinline__ uint32_t ex2_h2(uint32_t a) {
    uint32_t r;
    asm("ex2.approx.f16x2 %0, %1;" : "=r"(r) : "r"(a));
    return r;
}

__device__ __forceinline__ float ex2f(float x) {
    float r;
    asm("ex2.approx.f32 %0, %1;" : "=f"(r) : "f"(x));
    return r;
}

__device__ __forceinline__ float h2sumf(uint32_t w) {
    __half2 h = *reinterpret_cast<__half2*>(&w);
    float2 f = __half22float2(h);
    return f.x + f.y;
}

__device__ __forceinline__ int ilw2(int w) {
    return (w & ~7) | (2 * (w & 3) + ((w >> 2) & 1));
}

__device__ __forceinline__ uint32_t smem_u32(const void* p) {
    uint32_t a;
    asm("{ .reg .u64 t; cvta.to.shared.u64 t, %1; cvt.u32.u64 %0, t; }"
        : "=r"(a) : "l"(p));
    return a;
}

#define CP16(dst, src) \
    asm volatile("cp.async.cg.shared.global [%0], [%1], 16;" \
                 :: "r"(dst), "l"(src) : "memory")
#define CP_COMMIT() asm volatile("cp.async.commit_group;" ::: "memory")
#define CP_WAIT1()  asm volatile("cp.async.wait_group 1;" ::: "memory")

__device__ __forceinline__ void mma_f16(
    float& d0, float& d1, float& d2, float& d3,
    uint32_t a0, uint32_t a1, uint32_t a2, uint32_t a3,
    uint32_t b0, uint32_t b1)
{
    asm volatile(
        "mma.sync.aligned.m16n8k16.row.col.f32.f16.f16.f32 "
        "{%0,%1,%2,%3}, {%4,%5,%6,%7}, {%8,%9}, {%0,%1,%2,%3};"
        : "+f"(d0), "+f"(d1), "+f"(d2), "+f"(d3)
        : "r"(a0), "r"(a1), "r"(a2), "r"(a3), "r"(b0), "r"(b1));
}

// ---------------------------------------------------------------------------
// LayerNorm -> fp16 interleaved rows in g_h16
// ---------------------------------------------------------------------------
__global__ __launch_bounds__(256) void ln_kernel(
    const float* __restrict__ x,
    const float* __restrict__ w,
    const float* __restrict__ bvec)
{
    const int row = blockIdx.x;
    const int t = threadIdx.x;
    float4 v = ((const float4*)(x + (size_t)row * DIM))[t];
    float s  = v.x + v.y + v.z + v.w;
    float ss = v.x * v.x + v.y * v.y + v.z * v.z + v.w * v.w;
    #pragma unroll
    for (int off = 16; off; off >>= 1) {
        s  += __shfl_xor_sync(0xffffffffu, s,  off);
        ss += __shfl_xor_sync(0xffffffffu, ss, off);
    }
    __shared__ float sh[16];
    const int wid = t >> 5, lane = t & 31;
    if (lane == 0) { sh[wid] = s; sh[8 + wid] = ss; }
    __syncthreads();
    float ts = 0.f, tss = 0.f;
    #pragma unroll
    for (int i = 0; i < 8; i++) { ts += sh[i]; tss += sh[8 + i]; }
    const float mu  = ts * (1.0f / DIM);
    const float var = tss * (1.0f / DIM) - mu * mu;
    const float r   = rsqrtf(var + 1e-5f);
    float4 wv = ((const float4*)w)[t];
    float4 bv = ((const float4*)bvec)[t];
    const float o0 = (v.x - mu) * r * wv.x + bv.x;
    const float o1 = (v.y - mu) * r * wv.y + bv.y;
    const float o2 = (v.z - mu) * r * wv.z + bv.z;
    const float o3 = (v.w - mu) * r * wv.w + bv.w;
    uint32_t* dst = (uint32_t*)(g_h16 + (size_t)row * DIM);
    dst[ilw2(2 * t)]     = pack_h2(o0, o1);
    dst[ilw2(2 * t + 1)] = pack_h2(o2, o3);
}

// ---------------------------------------------------------------------------
// One-shot: transpose W -> g_wt16[z][n][k interleaved]. grid(32,32,3).
// ---------------------------------------------------------------------------
__global__ __launch_bounds__(256) void cvt_w(
    const float* __restrict__ Wq,
    const float* __restrict__ Wk,
    const float* __restrict__ Wv)
{
    __shared__ float tile[32][33];
    const int z = blockIdx.z;
    const float* src = (z == 0) ? Wq : (z == 1) ? Wk : Wv;
    const int k0 = blockIdx.x * 32, n0 = blockIdx.y * 32;
    {
        const int kl = threadIdx.x >> 3, nl4 = (threadIdx.x & 7) * 4;
        float4 v = *(const float4*)(src + (size_t)(k0 + kl) * DIM + n0 + nl4);
        tile[kl][nl4 + 0] = v.x;
        tile[kl][nl4 + 1] = v.y;
        tile[kl][nl4 + 2] = v.z;
        tile[kl][nl4 + 3] = v.w;
    }
    __syncthreads();
    const int nl = threadIdx.x >> 3, kb = (threadIdx.x & 7) * 4;
    uint32_t* dst = (uint32_t*)(g_wt16 + (size_t)z * DIM * DIM
                                + (size_t)(n0 + nl) * DIM);
    const int w0 = (k0 + kb) >> 1;
    dst[ilw2(w0)]     = pack_h2(tile[kb + 0][nl], tile[kb + 1][nl]);
    dst[ilw2(w0 + 1)] = pack_h2(tile[kb + 2][nl], tile[kb + 3][nl]);
}

// ---------------------------------------------------------------------------
// QKV GEMM, fp16 m16n8k16, CTA 128x128, K-chunk 64, cp.async double buffer.
// ---------------------------------------------------------------------------
#define GEMM_SMEM 65536

__global__ __launch_bounds__(256) void qkv_gemm_mma(
    const float* __restrict__ Bq,
    const float* __restrict__ Bk,
    const float* __restrict__ Bv)
{
    extern __shared__ uint32_t smem[];
    const uint32_t sb = smem_u32(smem);

    const int which = blockIdx.z;
    const __half* W = g_wt16 + (size_t)which * DIM * DIM;
    const float* bias = (which == 0) ? Bq : (which == 1) ? Bk : Bv;
    const float qscale = (which == 0) ? 0.125f * LOG2E : 1.0f;

    const int tid  = threadIdx.x;
    const int lane = tid & 31;
    const int gid  = lane >> 2;
    const int tig  = lane & 3;
    const int wm   = (tid >> 5) & 1;
    const int wn   = tid >> 6;

    const int m0 = blockIdx.y * 128;
    const int n0 = blockIdx.x * 128;

    const int lr = tid >> 1;
    const int lh = tid & 1;
    const int xr = (lr & 3) << 2;
    const __half* Asrc = g_h16 + (size_t)(m0 + lr) * DIM;
    const __half* Bsrc = W + (size_t)(n0 + lr) * DIM;
    const uint32_t abase = sb + (lr * 32) * 4;
    const uint32_t bbase = sb + (8192 + lr * 32) * 4;

    float acc[4][4][4];
    #pragma unroll
    for (int i = 0; i < 4; i++)
        #pragma unroll
        for (int j = 0; j < 4; j++)
            #pragma unroll
            for (int r = 0; r < 4; r++) acc[i][j][r] = 0.f;

    #pragma unroll
    for (int pb = 0; pb < 2; pb++) {
        const int k0 = pb * 64;
        #pragma unroll
        for (int c = 0; c < 4; c++) {
            const int j  = 4 * lh + c;
            const int pu = (2 * j) ^ xr;
            CP16(abase + pb * 16384 + pu * 8, Asrc + k0 + j * 8);
            CP16(bbase + pb * 16384 + pu * 8, Bsrc + k0 + j * 8);
        }
        CP_COMMIT();
    }
    CP_WAIT1();
    __syncthreads();

    const int gx = (gid & 3) << 2;
    const int NCHUNK = DIM / 64;
    #pragma unroll 1
    for (int i = 0; i < NCHUNK; ++i) {
        const int p = i & 1;
        const uint32_t* A = smem + p * 4096;
        const uint32_t* B = smem + 8192 + p * 4096;

        #pragma unroll
        for (int s = 0; s < 4; s++) {
            const int u2 = 2 * ((4 * s + tig) ^ gx);
            uint2 alo[4], ahi[4], bf[4];
            #pragma unroll
            for (int mt = 0; mt < 4; mt++) {
                const int mr = wm * 64 + mt * 16 + gid;
                alo[mt] = *(const uint2*)&A[mr * 32 + u2];
                ahi[mt] = *(const uint2*)&A[(mr + 8) * 32 + u2];
            }
            #pragma unroll
            for (int nt = 0; nt < 4; nt++)
                bf[nt] = *(const uint2*)&B[(wn * 32 + nt * 8 + gid) * 32 + u2];
            #pragma unroll
            for (int mt = 0; mt < 4; mt++)
                #pragma unroll
                for (int nt = 0; nt < 4; nt++)
                    mma_f16(acc[mt][nt][0], acc[mt][nt][1],
                            acc[mt][nt][2], acc[mt][nt][3],
                            alo[mt].x, ahi[mt].x, alo[mt].y, ahi[mt].y,
                            bf[nt].x, bf[nt].y);
        }

        __syncthreads();
        if (i + 2 < NCHUNK) {
            const int k0 = (i + 2) * 64;
            #pragma unroll
            for (int c = 0; c < 4; c++) {
                const int j  = 4 * lh + c;
                const int pu = (2 * j) ^ xr;
                CP16(abase + p * 16384 + pu * 8, Asrc + k0 + j * 8);
                CP16(bbase + p * 16384 + pu * 8, Bsrc + k0 + j * 8);
            }
        }
        CP_COMMIT();
        CP_WAIT1();
        __syncthreads();
    }

    if (which < 2) {
        uint32_t* C = (uint32_t*)((which == 0) ? g_q16 : g_k16);
        #pragma unroll
        for (int mt = 0; mt < 4; mt++) {
            const int m  = m0 + wm * 64 + mt * 16 + gid;
            const int bb = m >> 11;
            const int nn = m & (SEQ - 1);
            #pragma unroll
            for (int nt = 0; nt < 4; nt++) {
                const int n  = n0 + wn * 32 + nt * 8 + 2 * tig;
                const int hh = n >> 6;
                const int dd = n & 63;
                const float bx = bias[n], by = bias[n + 1];
                const size_t rowb = ((size_t)(bb * HEADS + hh) * SEQ + nn) * 32;
                const int pw = ilw2(dd >> 1);
                C[rowb + pw] = pack_h2((acc[mt][nt][0] + bx) * qscale,
                                       (acc[mt][nt][1] + by) * qscale);
                C[rowb + 8 * 32 + pw] = pack_h2((acc[mt][nt][2] + bx) * qscale,
                                                (acc[mt][nt][3] + by) * qscale);
            }
        }
    } else {
        #pragma unroll
        for (int mt = 0; mt < 4; mt++) {
            const int m   = m0 + wm * 64 + mt * 16 + gid;
            const int bb  = m >> 11;
            const int key = m & (SEQ - 1);
            const int e   = key & 1;
            const int pwa = ilw2(key >> 1);
            const int pwb = ilw2((key >> 1) + 4);
            #pragma unroll
            for (int nt = 0; nt < 4; nt++) {
                const int n  = n0 + wn * 32 + nt * 8 + 2 * tig;
                const int hh = n >> 6;
                const int dd = n & 63;
                const float bx = bias[n], by = bias[n + 1];
                __half* r0 = g_v16
                    + ((size_t)(bb * HEADS + hh) * DHEAD + dd) * SEQ;
                __half* r1 = r0 + SEQ;
                r0[2 * pwa + e] = __float2half_rn(acc[mt][nt][0] + bx);
                r1[2 * pwa + e] = __float2half_rn(acc[mt][nt][1] + by);
                r0[2 * pwb + e] = __float2half_rn(acc[mt][nt][2] + bx);
                r1[2 * pwb + e] = __float2half_rn(acc[mt][nt][3] + by);
            }
        }
    }
}

// ---------------------------------------------------------------------------
// Flash attention, all-fp16 mma, log2-domain softmax, 256 threads,
// 8 warps x 16 Q-rows (128 rows/CTA). 2 CTAs/SM (reg-capped at 128).
// Loaders: threads 0..127 stage K, 128..255 stage V (2 threads/row).
// SMEM words: Q[0,4096) K0[4096) K1[6144) V0[8192) V1[10240); 48KB.
// ---------------------------------------------------------------------------
#define ATTN_SMEM 49152

__global__ __launch_bounds__(256, 2) void attn_mma(float* __restrict__ out)
{
    extern __shared__ uint32_t sm[];
    const uint32_t sb = smem_u32(sm);
    const uint32_t KOFF[2] = { 4096u, 6144u };
    const uint32_t VOFF[2] = { 8192u, 10240u };

    const int bh = blockIdx.y;               // 0..63
    const int q0 = blockIdx.x * 128;
    const __half* Qb = g_q16 + (size_t)bh * SEQ * DHEAD;
    const __half* Kb = g_k16 + (size_t)bh * SEQ * DHEAD;
    const __half* Vb = g_v16 + (size_t)bh * DHEAD * SEQ;   // [d][key]

    const int tid  = threadIdx.x;
    const int lane = tid & 31;
    const int g    = lane >> 2, t = lane & 3;
    const int wrow = (tid >> 5) * 16;

    // loaders: lower half -> K, upper half -> V; 2 threads per row
    const int lt = tid & 127;
    const int lr = lt >> 1;             // 0..63
    const int lh = lt & 1;
    const int xr = (lr & 3) << 2;
    const bool isV = tid >= 128;
    const __half* kvsrc0 = isV ? (Vb + (size_t)lr * SEQ)
                               : (Kb + (size_t)lr * DHEAD);
    const size_t kvstep = isV ? 64 : (size_t)64 * DHEAD;   // per key-tile
    const uint32_t kvbase[2] = {
        sb + ((isV ? VOFF[0] : KOFF[0]) + lr * 32) * 4,
        sb + ((isV ? VOFF[1] : KOFF[1]) + lr * 32) * 4
    };

    // ---- prologue: stage Q + tiles 0,1 ----
    {
        const int qr = tid >> 1;
        const int qh = tid & 1;
        const int qx = (qr & 3) << 2;
        const __half* qsrc = Qb + (size_t)(q0 + qr) * DHEAD;
        const uint32_t qdst = sb + qr * 128;
        #pragma unroll
        for (int c = 0; c < 4; c++) {
            const int j  = 4 * qh + c;
            const int pu = (2 * j) ^ qx;
            CP16(qdst + pu * 8, qsrc + j * 8);
        }
    }
    #pragma unroll
    for (int pb = 0; pb < 2; pb++) {
        const __half* src = kvsrc0 + pb * kvstep;
        #pragma unroll
        for (int c = 0; c < 4; c++) {
            const int j  = 4 * lh + c;
            const int pu = (2 * j) ^ xr;
            CP16(kvbase[pb] + pu * 8, src + j * 8);
        }
        CP_COMMIT();
    }
    CP_WAIT1();
    __syncthreads();

    float o[8][4];
    #pragma unroll
    for (int nt = 0; nt < 8; nt++)
        #pragma unroll
        for (int r = 0; r < 4; r++) o[nt][r] = 0.f;
    float m0 = -1e30f, m1 = -1e30f, l0 = 0.f, l1 = 0.f;

    const int gx = (g & 3) << 2;
    const int NKT = SEQ / 64;
    #pragma unroll 1
    for (int kt = 0; kt < NKT; kt++) {
        const int p = kt & 1;
        const uint32_t* Ks = sm + KOFF[p];
        const uint32_t* Vs = sm + VOFF[p];

        // ---- S = Q K^T (fp16 k16), log2 domain ----
        float s[8][4];
        #pragma unroll
        for (int nt = 0; nt < 8; nt++)
            #pragma unroll
            for (int r = 0; r < 4; r++) s[nt][r] = 0.f;

        #pragma unroll
        for (int ss = 0; ss < 4; ss++) {
            const int u2 = 2 * ((4 * ss + t) ^ gx);
            const int rq = wrow + g;
            const uint2 qlo = *(const uint2*)&sm[rq * 32 + u2];
            const uint2 qhi = *(const uint2*)&sm[(rq + 8) * 32 + u2];
            #pragma unroll
            for (int nt = 0; nt < 8; nt++) {
                const uint2 kf = *(const uint2*)&Ks[(nt * 8 + g) * 32 + u2];
                mma_f16(s[nt][0], s[nt][1], s[nt][2], s[nt][3],
                        qlo.x, qhi.x, qlo.y, qhi.y, kf.x, kf.y);
            }
        }

        // ---- online softmax (log2 domain, f16x2 exp) ----
        uint32_t ph[8][2];
        {
            float mx0 = -1e30f, mx1 = -1e30f;
            #pragma unroll
            for (int nt = 0; nt < 8; nt++) {
                mx0 = fmaxf(mx0, fmaxf(s[nt][0], s[nt][1]));
                mx1 = fmaxf(mx1, fmaxf(s[nt][2], s[nt][3]));
            }
            #pragma unroll
            for (int off = 1; off <= 2; off <<= 1) {
                mx0 = fmaxf(mx0, __shfl_xor_sync(0xffffffffu, mx0, off));
                mx1 = fmaxf(mx1, __shfl_xor_sync(0xffffffffu, mx1, off));
            }
            const float mn0 = fmaxf(m0, mx0);
            const float mn1 = fmaxf(m1, mx1);
            const float al0 = ex2f(m0 - mn0);
            const float al1 = ex2f(m1 - mn1);
            m0 = mn0; m1 = mn1;
            const uint32_t mh0 = pack_h2(mn0, mn0);
            const uint32_t mh1 = pack_h2(mn1, mn1);
            #pragma unroll
            for (int nt = 0; nt < 8; nt++) {
                uint32_t a0 = pack_h2(s[nt][0], s[nt][1]);
                uint32_t a1 = pack_h2(s[nt][2], s[nt][3]);
                ph[nt][0] = ex2_h2(hsub2_u(a0, mh0));
                ph[nt][1] = ex2_h2(hsub2_u(a1, mh1));
            }
            float sum0, sum1;
            {
                uint32_t w0 = hadd2_u(ph[0][0], ph[1][0]);
                uint32_t w1 = hadd2_u(ph[2][0], ph[3][0]);
                uint32_t w2 = hadd2_u(ph[4][0], ph[5][0]);
                uint32_t w3 = hadd2_u(ph[6][0], ph[7][0]);
                sum0 = (h2sumf(w0) + h2sumf(w1)) + (h2sumf(w2) + h2sumf(w3));
                w0 = hadd2_u(ph[0][1], ph[1][1]);
                w1 = hadd2_u(ph[2][1], ph[3][1]);
                w2 = hadd2_u(ph[4][1], ph[5][1]);
                w3 = hadd2_u(ph[6][1], ph[7][1]);
                sum1 = (h2sumf(w0) + h2sumf(w1)) + (h2sumf(w2) + h2sumf(w3));
            }
            #pragma unroll
            for (int off = 1; off <= 2; off <<= 1) {
                sum0 += __shfl_xor_sync(0xffffffffu, sum0, off);
                sum1 += __shfl_xor_sync(0xffffffffu, sum1, off);
            }
            l0 = l0 * al0 + sum0;
            l1 = l1 * al1 + sum1;
            #pragma unroll
            for (int nt = 0; nt < 8; nt++) {
                o[nt][0] *= al0; o[nt][1] *= al0;
                o[nt][2] *= al1; o[nt][3] *= al1;
            }
        }

        // ---- O += P V (fp16; ph feeds A fragments directly) ----
        #pragma unroll
        for (int j = 0; j < 4; j++) {
            const int u2 = 2 * ((4 * j + t) ^ gx);
            #pragma unroll
            for (int nt = 0; nt < 8; nt++) {
                const uint2 vb = *(const uint2*)&Vs[(nt * 8 + g) * 32 + u2];
                mma_f16(o[nt][0], o[nt][1], o[nt][2], o[nt][3],
                        ph[2 * j][0], ph[2 * j][1],
                        ph[2 * j + 1][0], ph[2 * j + 1][1], vb.x, vb.y);
            }
        }

        __syncthreads();   // all warps done reading buf p
        if (kt + 2 < NKT) {
            const __half* src = kvsrc0 + (size_t)(kt + 2) * kvstep;
            #pragma unroll
            for (int c = 0; c < 4; c++) {
                const int j  = 4 * lh + c;
                const int pu = (2 * j) ^ xr;
                CP16(kvbase[p] + pu * 8, src + j * 8);
            }
        }
        CP_COMMIT();
        CP_WAIT1();
        __syncthreads();
    }

    // ---- epilogue ----
    const int bb = bh >> 4, hh = bh & 15;
    const float inv0 = 1.f / l0, inv1 = 1.f / l1;
    const int rr0 = q0 + wrow + g, rr1 = rr0 + 8;
    #pragma unroll
    for (int nt = 0; nt < 8; nt++) {
        const int d = hh * DHEAD + nt * 8 + 2 * t;
        *(float2*)(out + ((size_t)bb * SEQ + rr0) * (HEADS * DHEAD) + d) =
            make_float2(o[nt][0] * inv0, o[nt][1] * inv0);
        *(float2*)(out + ((size_t)bb * SEQ + rr1) * (HEADS * DHEAD) + d) =
            make_float2(o[nt][2] * inv1, o[nt][3] * inv1);
    }
}

// ---------------------------------------------------------------------------
extern "C" void kernel_launch(void* const* d_in, const int* in_sizes, int n_in,
                              void* d_out, int out_size) {
    const float* x    = (const float*)d_in[0];
    const float* ln_w = (const float*)d_in[1];
    const float* ln_b = (const float*)d_in[2];
    const float* wq   = (const float*)d_in[3];
    const float* bq   = (const float*)d_in[4];
    const float* wk   = (const float*)d_in[5];
    const float* bk   = (const float*)d_in[6];
    const float* wv   = (const float*)d_in[7];
    const float* bv   = (const float*)d_in[8];
    float* out = (float*)d_out;

    cudaFuncSetAttribute(qkv_gemm_mma,
                         cudaFuncAttributeMaxDynamicSharedMemorySize, GEMM_SMEM);
    cudaFuncSetAttribute(attn_mma,
                         cudaFuncAttributeMaxDynamicSharedMemorySize, ATTN_SMEM);

    ln_kernel<<<MTOT, 256>>>(x, ln_w, ln_b);
    cvt_w<<<dim3(32, 32, 3), 256>>>(wq, wk, wv);
    qkv_gemm_mma<<<dim3(DIM / 128, MTOT / 128, 3), 256, GEMM_SMEM>>>(bq, bk, bv);
    attn_mma<<<dim3(SEQ / 128, BATCH * HEADS), 256, ATTN_SMEM>>>(out);
}

// round 13
// speedup vs baseline: 6.9182x; 1.0136x over previous
#include <cuda_runtime.h>
#include <cuda_fp16.h>
#include <cstdint>

#define DIM    1024
#define HEADS  16
#define DHEAD  64
#define BATCH  4
#define SEQ    2048
#define MTOT   (BATCH * SEQ)   // 8192
#define LOG2E  1.4426950408889634f

// All fp16, word(=half2)-interleaved per 8-word group: logical word l ->
// physical 2*(l&3) + (l>>2). Fragment pairs (k,k+8-halves) become one LDS.64.
__device__ __half g_h16[(size_t)MTOT * DIM];
__device__ __half g_q16[(size_t)MTOT * DIM];   // pre-scaled by 0.125*log2e
__device__ __half g_k16[(size_t)MTOT * DIM];
__device__ __half g_v16[(size_t)MTOT * DIM];   // TRANSPOSED [b,h,d][key]
__device__ __half g_wt16[(size_t)3 * DIM * DIM];

__device__ __forceinline__ uint32_t pack_h2(float lo, float hi) {
    uint32_t r;
    asm("cvt.rn.f16x2.f32 %0, %1, %2;" : "=r"(r) : "f"(hi), "f"(lo));
    return r;
}

__device__ __forceinline__ uint32_t hsub2_u(uint32_t a, uint32_t b) {
    uint32_t r;
    asm("sub.rn.f16x2 %0, %1, %2;" : "=r"(r) : "r"(a), "r"(b));
    return r;
}

__device__ __forceinline__ uint32_t hadd2_u(uint32_t a, uint32_t b) {
    uint32_t r;
    asm("add.rn.f16x2 %0, %1, %2;" : "=r"(r) : "r"(a), "r"(b));
    return r;
}

__device__ __forceinline__ uint32_t ex2_h2(uint32_t a) {
    uint32_t r;
    asm("ex2.approx.f16x2 %0, %1;" : "=r"(r) : "r"(a));
    return r;
}

__device__ __forceinline__ float ex2f(float x) {
    float r;
    asm("ex2.approx.f32 %0, %1;" : "=f"(r) : "f"(x));
    return r;
}

__device__ __forceinline__ float h2sumf(uint32_t w) {
    __half2 h = *reinterpret_cast<__half2*>(&w);
    float2 f = __half22float2(h);
    return f.x + f.y;
}

__device__ __forceinline__ int ilw2(int w) {
    return (w & ~7) | (2 * (w & 3) + ((w >> 2) & 1));
}

__device__ __forceinline__ uint32_t smem_u32(const void* p) {
    uint32_t a;
    asm("{ .reg .u64 t; cvta.to.shared.u64 t, %1; cvt.u32.u64 %0, t; }"
        : "=r"(a) : "l"(p));
    return a;
}

#define CP16(dst, src) \
    asm volatile("cp.async.cg.shared.global [%0], [%1], 16;" \
                 :: "r"(dst), "l"(src) : "memory")
#define CP_COMMIT() asm volatile("cp.async.commit_group;" ::: "memory")
#define CP_WAIT1()  asm volatile("cp.async.wait_group 1;" ::: "memory")

__device__ __forceinline__ void mma_f16(
    float& d0, float& d1, float& d2, float& d3,
    uint32_t a0, uint32_t a1, uint32_t a2, uint32_t a3,
    uint32_t b0, uint32_t b1)
{
    asm volatile(
        "mma.sync.aligned.m16n8k16.row.col.f32.f16.f16.f32 "
        "{%0,%1,%2,%3}, {%4,%5,%6,%7}, {%8,%9}, {%0,%1,%2,%3};"
        : "+f"(d0), "+f"(d1), "+f"(d2), "+f"(d3)
        : "r"(a0), "r"(a1), "r"(a2), "r"(a3), "r"(b0), "r"(b1));
}

// ---------------------------------------------------------------------------
// LayerNorm -> fp16 interleaved rows in g_h16
// ---------------------------------------------------------------------------
__global__ __launch_bounds__(256) void ln_kernel(
    const float* __restrict__ x,
    const float* __restrict__ w,
    const float* __restrict__ bvec)
{
    const int row = blockIdx.x;
    const int t = threadIdx.x;
    float4 v = ((const float4*)(x + (size_t)row * DIM))[t];
    float s  = v.x + v.y + v.z + v.w;
    float ss = v.x * v.x + v.y * v.y + v.z * v.z + v.w * v.w;
    #pragma unroll
    for (int off = 16; off; off >>= 1) {
        s  += __shfl_xor_sync(0xffffffffu, s,  off);
        ss += __shfl_xor_sync(0xffffffffu, ss, off);
    }
    __shared__ float sh[16];
    const int wid = t >> 5, lane = t & 31;
    if (lane == 0) { sh[wid] = s; sh[8 + wid] = ss; }
    __syncthreads();
    float ts = 0.f, tss = 0.f;
    #pragma unroll
    for (int i = 0; i < 8; i++) { ts += sh[i]; tss += sh[8 + i]; }
    const float mu  = ts * (1.0f / DIM);
    const float var = tss * (1.0f / DIM) - mu * mu;
    const float r   = rsqrtf(var + 1e-5f);
    float4 wv = ((const float4*)w)[t];
    float4 bv = ((const float4*)bvec)[t];
    const float o0 = (v.x - mu) * r * wv.x + bv.x;
    const float o1 = (v.y - mu) * r * wv.y + bv.y;
    const float o2 = (v.z - mu) * r * wv.z + bv.z;
    const float o3 = (v.w - mu) * r * wv.w + bv.w;
    uint32_t* dst = (uint32_t*)(g_h16 + (size_t)row * DIM);
    dst[ilw2(2 * t)]     = pack_h2(o0, o1);
    dst[ilw2(2 * t + 1)] = pack_h2(o2, o3);
}

// ---------------------------------------------------------------------------
// One-shot: transpose W -> g_wt16[z][n][k interleaved]. grid(32,32,3).
// ---------------------------------------------------------------------------
__global__ __launch_bounds__(256) void cvt_w(
    const float* __restrict__ Wq,
    const float* __restrict__ Wk,
    const float* __restrict__ Wv)
{
    __shared__ float tile[32][33];
    const int z = blockIdx.z;
    const float* src = (z == 0) ? Wq : (z == 1) ? Wk : Wv;
    const int k0 = blockIdx.x * 32, n0 = blockIdx.y * 32;
    {
        const int kl = threadIdx.x >> 3, nl4 = (threadIdx.x & 7) * 4;
        float4 v = *(const float4*)(src + (size_t)(k0 + kl) * DIM + n0 + nl4);
        tile[kl][nl4 + 0] = v.x;
        tile[kl][nl4 + 1] = v.y;
        tile[kl][nl4 + 2] = v.z;
        tile[kl][nl4 + 3] = v.w;
    }
    __syncthreads();
    const int nl = threadIdx.x >> 3, kb = (threadIdx.x & 7) * 4;
    uint32_t* dst = (uint32_t*)(g_wt16 + (size_t)z * DIM * DIM
                                + (size_t)(n0 + nl) * DIM);
    const int w0 = (k0 + kb) >> 1;
    dst[ilw2(w0)]     = pack_h2(tile[kb + 0][nl], tile[kb + 1][nl]);
    dst[ilw2(w0 + 1)] = pack_h2(tile[kb + 2][nl], tile[kb + 3][nl]);
}

// ---------------------------------------------------------------------------
// QKV GEMM, fp16 m16n8k16, CTA 128x128, K-chunk 64, 3-stage cp.async
// pipeline, ONE __syncthreads per iteration.
// SMEM: A bufs [0,12288) words (3 x 4096), B bufs [12288,24576); 96KB.
// ---------------------------------------------------------------------------
#define GEMM_SMEM 98304

__global__ __launch_bounds__(256, 2) void qkv_gemm_mma(
    const float* __restrict__ Bq,
    const float* __restrict__ Bk,
    const float* __restrict__ Bv)
{
    extern __shared__ uint32_t smem[];
    const uint32_t sb = smem_u32(smem);

    const int which = blockIdx.z;
    const __half* W = g_wt16 + (size_t)which * DIM * DIM;
    const float* bias = (which == 0) ? Bq : (which == 1) ? Bk : Bv;
    const float qscale = (which == 0) ? 0.125f * LOG2E : 1.0f;

    const int tid  = threadIdx.x;
    const int lane = tid & 31;
    const int gid  = lane >> 2;
    const int tig  = lane & 3;
    const int wm   = (tid >> 5) & 1;
    const int wn   = tid >> 6;

    const int m0 = blockIdx.y * 128;
    const int n0 = blockIdx.x * 128;

    const int lr = tid >> 1;
    const int lh = tid & 1;
    const int xr = (lr & 3) << 2;
    const __half* Asrc = g_h16 + (size_t)(m0 + lr) * DIM;
    const __half* Bsrc = W + (size_t)(n0 + lr) * DIM;
    const uint32_t abase = sb + (lr * 32) * 4;            // + buf*16384 B
    const uint32_t bbase = sb + (12288 + lr * 32) * 4;

    float acc[4][4][4];
    #pragma unroll
    for (int i = 0; i < 4; i++)
        #pragma unroll
        for (int j = 0; j < 4; j++)
            #pragma unroll
            for (int r = 0; r < 4; r++) acc[i][j][r] = 0.f;

    // prologue: issue chunks 0, 1 (two commit groups)
    #pragma unroll
    for (int pb = 0; pb < 2; pb++) {
        const int k0 = pb * 64;
        #pragma unroll
        for (int c = 0; c < 4; c++) {
            const int j  = 4 * lh + c;
            const int pu = (2 * j) ^ xr;
            CP16(abase + pb * 16384 + pu * 8, Asrc + k0 + j * 8);
            CP16(bbase + pb * 16384 + pu * 8, Bsrc + k0 + j * 8);
        }
        CP_COMMIT();
    }

    const int gx = (gid & 3) << 2;
    const int NCHUNK = DIM / 64;     // 16
    int bi = 0;                      // buffer of current chunk
    int bn = 2;                      // buffer of chunk i+2
    #pragma unroll 1
    for (int i = 0; i < NCHUNK; ++i) {
        CP_WAIT1();
        __syncthreads();

        // issue loads for chunk i+2 into buffer bn (freed by iter i-1)
        if (i + 2 < NCHUNK) {
            const int k0 = (i + 2) * 64;
            #pragma unroll
            for (int c = 0; c < 4; c++) {
                const int j  = 4 * lh + c;
                const int pu = (2 * j) ^ xr;
                CP16(abase + bn * 16384 + pu * 8, Asrc + k0 + j * 8);
                CP16(bbase + bn * 16384 + pu * 8, Bsrc + k0 + j * 8);
            }
        }
        CP_COMMIT();

        const uint32_t* A = smem + bi * 4096;
        const uint32_t* B = smem + 12288 + bi * 4096;
        #pragma unroll
        for (int s = 0; s < 4; s++) {
            const int u2 = 2 * ((4 * s + tig) ^ gx);
            uint2 alo[4], ahi[4], bf[4];
            #pragma unroll
            for (int mt = 0; mt < 4; mt++) {
                const int mr = wm * 64 + mt * 16 + gid;
                alo[mt] = *(const uint2*)&A[mr * 32 + u2];
                ahi[mt] = *(const uint2*)&A[(mr + 8) * 32 + u2];
            }
            #pragma unroll
            for (int nt = 0; nt < 4; nt++)
                bf[nt] = *(const uint2*)&B[(wn * 32 + nt * 8 + gid) * 32 + u2];
            #pragma unroll
            for (int mt = 0; mt < 4; mt++)
                #pragma unroll
                for (int nt = 0; nt < 4; nt++)
                    mma_f16(acc[mt][nt][0], acc[mt][nt][1],
                            acc[mt][nt][2], acc[mt][nt][3],
                            alo[mt].x, ahi[mt].x, alo[mt].y, ahi[mt].y,
                            bf[nt].x, bf[nt].y);
        }

        bi = (bi == 2) ? 0 : bi + 1;
        bn = (bn == 2) ? 0 : bn + 1;
    }

    if (which < 2) {
        uint32_t* C = (uint32_t*)((which == 0) ? g_q16 : g_k16);
        #pragma unroll
        for (int mt = 0; mt < 4; mt++) {
            const int m  = m0 + wm * 64 + mt * 16 + gid;
            const int bb = m >> 11;
            const int nn = m & (SEQ - 1);
            #pragma unroll
            for (int nt = 0; nt < 4; nt++) {
                const int n  = n0 + wn * 32 + nt * 8 + 2 * tig;
                const int hh = n >> 6;
                const int dd = n & 63;
                const float bx = bias[n], by = bias[n + 1];
                const size_t rowb = ((size_t)(bb * HEADS + hh) * SEQ + nn) * 32;
                const int pw = ilw2(dd >> 1);
                C[rowb + pw] = pack_h2((acc[mt][nt][0] + bx) * qscale,
                                       (acc[mt][nt][1] + by) * qscale);
                C[rowb + 8 * 32 + pw] = pack_h2((acc[mt][nt][2] + bx) * qscale,
                                                (acc[mt][nt][3] + by) * qscale);
            }
        }
    } else {
        #pragma unroll
        for (int mt = 0; mt < 4; mt++) {
            const int m   = m0 + wm * 64 + mt * 16 + gid;
            const int bb  = m >> 11;
            const int key = m & (SEQ - 1);
            const int e   = key & 1;
            const int pwa = ilw2(key >> 1);
            const int pwb = ilw2((key >> 1) + 4);
            #pragma unroll
            for (int nt = 0; nt < 4; nt++) {
                const int n  = n0 + wn * 32 + nt * 8 + 2 * tig;
                const int hh = n >> 6;
                const int dd = n & 63;
                const float bx = bias[n], by = bias[n + 1];
                __half* r0 = g_v16
                    + ((size_t)(bb * HEADS + hh) * DHEAD + dd) * SEQ;
                __half* r1 = r0 + SEQ;
                r0[2 * pwa + e] = __float2half_rn(acc[mt][nt][0] + bx);
                r1[2 * pwa + e] = __float2half_rn(acc[mt][nt][1] + by);
                r0[2 * pwb + e] = __float2half_rn(acc[mt][nt][2] + bx);
                r1[2 * pwb + e] = __float2half_rn(acc[mt][nt][3] + by);
            }
        }
    }
}

// ---------------------------------------------------------------------------
// Flash attention, all-fp16 mma, log2-domain softmax, 256 threads,
// 8 warps x 16 Q-rows, 3-stage K/V cp.async pipeline, ONE sync per iter.
// SMEM words: Q[0,4096) K0/K1/K2 [4096..10240) V0/V1/V2 [10240..16384); 64KB.
// ---------------------------------------------------------------------------
#define ATTN_SMEM 65536

__global__ __launch_bounds__(256, 2) void attn_mma(float* __restrict__ out)
{
    extern __shared__ uint32_t sm[];
    const uint32_t sb = smem_u32(sm);
    const uint32_t KOFF[3] = { 4096u, 6144u, 8192u };
    const uint32_t VOFF[3] = { 10240u, 12288u, 14336u };

    const int bh = blockIdx.y;               // 0..63
    const int q0 = blockIdx.x * 128;
    const __half* Qb = g_q16 + (size_t)bh * SEQ * DHEAD;
    const __half* Kb = g_k16 + (size_t)bh * SEQ * DHEAD;
    const __half* Vb = g_v16 + (size_t)bh * DHEAD * SEQ;   // [d][key]

    const int tid  = threadIdx.x;
    const int lane = tid & 31;
    const int g    = lane >> 2, t = lane & 3;
    const int wrow = (tid >> 5) * 16;

    // loaders: lower half -> K, upper half -> V; 2 threads per row
    const int lt = tid & 127;
    const int lr = lt >> 1;             // 0..63
    const int lh = lt & 1;
    const int xr = (lr & 3) << 2;
    const bool isV = tid >= 128;
    const __half* kvsrc0 = isV ? (Vb + (size_t)lr * SEQ)
                               : (Kb + (size_t)lr * DHEAD);
    const size_t kvstep = isV ? 64 : (size_t)64 * DHEAD;   // per key-tile
    const uint32_t kvbase[3] = {
        sb + ((isV ? VOFF[0] : KOFF[0]) + lr * 32) * 4,
        sb + ((isV ? VOFF[1] : KOFF[1]) + lr * 32) * 4,
        sb + ((isV ? VOFF[2] : KOFF[2]) + lr * 32) * 4
    };

    // ---- prologue: Q (grouped with tile 0) + tiles 0,1 ----
    {
        const int qr = tid >> 1;
        const int qh = tid & 1;
        const int qx = (qr & 3) << 2;
        const __half* qsrc = Qb + (size_t)(q0 + qr) * DHEAD;
        const uint32_t qdst = sb + qr * 128;
        #pragma unroll
        for (int c = 0; c < 4; c++) {
            const int j  = 4 * qh + c;
            const int pu = (2 * j) ^ qx;
            CP16(qdst + pu * 8, qsrc + j * 8);
        }
    }
    #pragma unroll
    for (int pb = 0; pb < 2; pb++) {
        const __half* src = kvsrc0 + pb * kvstep;
        #pragma unroll
        for (int c = 0; c < 4; c++) {
            const int j  = 4 * lh + c;
            const int pu = (2 * j) ^ xr;
            CP16(kvbase[pb] + pu * 8, src + j * 8);
        }
        CP_COMMIT();
    }

    float o[8][4];
    #pragma unroll
    for (int nt = 0; nt < 8; nt++)
        #pragma unroll
        for (int r = 0; r < 4; r++) o[nt][r] = 0.f;
    float m0 = -1e30f, m1 = -1e30f, l0 = 0.f, l1 = 0.f;

    const int gx = (g & 3) << 2;
    const int NKT = SEQ / 64;
    int bi = 0, bn = 2;
    #pragma unroll 1
    for (int kt = 0; kt < NKT; kt++) {
        CP_WAIT1();
        __syncthreads();

        // issue loads for tile kt+2 into buffer bn (freed by iter kt-1)
        if (kt + 2 < NKT) {
            const __half* src = kvsrc0 + (size_t)(kt + 2) * kvstep;
            #pragma unroll
            for (int c = 0; c < 4; c++) {
                const int j  = 4 * lh + c;
                const int pu = (2 * j) ^ xr;
                CP16(kvbase[bn] + pu * 8, src + j * 8);
            }
        }
        CP_COMMIT();

        const uint32_t* Ks = sm + KOFF[bi];
        const uint32_t* Vs = sm + VOFF[bi];

        // ---- S = Q K^T (fp16 k16), log2 domain ----
        float s[8][4];
        #pragma unroll
        for (int nt = 0; nt < 8; nt++)
            #pragma unroll
            for (int r = 0; r < 4; r++) s[nt][r] = 0.f;

        #pragma unroll
        for (int ss = 0; ss < 4; ss++) {
            const int u2 = 2 * ((4 * ss + t) ^ gx);
            const int rq = wrow + g;
            const uint2 qlo = *(const uint2*)&sm[rq * 32 + u2];
            const uint2 qhi = *(const uint2*)&sm[(rq + 8) * 32 + u2];
            #pragma unroll
            for (int nt = 0; nt < 8; nt++) {
                const uint2 kf = *(const uint2*)&Ks[(nt * 8 + g) * 32 + u2];
                mma_f16(s[nt][0], s[nt][1], s[nt][2], s[nt][3],
                        qlo.x, qhi.x, qlo.y, qhi.y, kf.x, kf.y);
            }
        }

        // ---- online softmax (log2 domain, f16x2 exp) ----
        uint32_t ph[8][2];
        {
            float mx0 = -1e30f, mx1 = -1e30f;
            #pragma unroll
            for (int nt = 0; nt < 8; nt++) {
                mx0 = fmaxf(mx0, fmaxf(s[nt][0], s[nt][1]));
                mx1 = fmaxf(mx1, fmaxf(s[nt][2], s[nt][3]));
            }
            #pragma unroll
            for (int off = 1; off <= 2; off <<= 1) {
                mx0 = fmaxf(mx0, __shfl_xor_sync(0xffffffffu, mx0, off));
                mx1 = fmaxf(mx1, __shfl_xor_sync(0xffffffffu, mx1, off));
            }
            const float mn0 = fmaxf(m0, mx0);
            const float mn1 = fmaxf(m1, mx1);
            const float al0 = ex2f(m0 - mn0);
            const float al1 = ex2f(m1 - mn1);
            m0 = mn0; m1 = mn1;
            const uint32_t mh0 = pack_h2(mn0, mn0);
            const uint32_t mh1 = pack_h2(mn1, mn1);
            #pragma unroll
            for (int nt = 0; nt < 8; nt++) {
                uint32_t a0 = pack_h2(s[nt][0], s[nt][1]);
                uint32_t a1 = pack_h2(s[nt][2], s[nt][3]);
                ph[nt][0] = ex2_h2(hsub2_u(a0, mh0));
                ph[nt][1] = ex2_h2(hsub2_u(a1, mh1));
            }
            float sum0, sum1;
            {
                uint32_t w0 = hadd2_u(ph[0][0], ph[1][0]);
                uint32_t w1 = hadd2_u(ph[2][0], ph[3][0]);
                uint32_t w2 = hadd2_u(ph[4][0], ph[5][0]);
                uint32_t w3 = hadd2_u(ph[6][0], ph[7][0]);
                sum0 = (h2sumf(w0) + h2sumf(w1)) + (h2sumf(w2) + h2sumf(w3));
                w0 = hadd2_u(ph[0][1], ph[1][1]);
                w1 = hadd2_u(ph[2][1], ph[3][1]);
                w2 = hadd2_u(ph[4][1], ph[5][1]);
                w3 = hadd2_u(ph[6][1], ph[7][1]);
                sum1 = (h2sumf(w0) + h2sumf(w1)) + (h2sumf(w2) + h2sumf(w3));
            }
            #pragma unroll
            for (int off = 1; off <= 2; off <<= 1) {
                sum0 += __shfl_xor_sync(0xffffffffu, sum0, off);
                sum1 += __shfl_xor_sync(0xffffffffu, sum1, off);
            }
            l0 = l0 * al0 + sum0;
            l1 = l1 * al1 + sum1;
            #pragma unroll
            for (int nt = 0; nt < 8; nt++) {
                o[nt][0] *= al0; o[nt][1] *= al0;
                o[nt][2] *= al1; o[nt][3] *= al1;
            }
        }

        // ---- O += P V (fp16; ph feeds A fragments directly) ----
        #pragma unroll
        for (int j = 0; j < 4; j++) {
            const int u2 = 2 * ((4 * j + t) ^ gx);
            #pragma unroll
            for (int nt = 0; nt < 8; nt++) {
                const uint2 vb = *(const uint2*)&Vs[(nt * 8 + g) * 32 + u2];
                mma_f16(o[nt][0], o[nt][1], o[nt][2], o[nt][3],
                        ph[2 * j][0], ph[2 * j][1],
                        ph[2 * j + 1][0], ph[2 * j + 1][1], vb.x, vb.y);
            }
        }

        bi = (bi == 2) ? 0 : bi + 1;
        bn = (bn == 2) ? 0 : bn + 1;
    }

    // ---- epilogue ----
    const int bb = bh >> 4, hh = bh & 15;
    const float inv0 = 1.f / l0, inv1 = 1.f / l1;
    const int rr0 = q0 + wrow + g, rr1 = rr0 + 8;
    #pragma unroll
    for (int nt = 0; nt < 8; nt++) {
        const int d = hh * DHEAD + nt * 8 + 2 * t;
        *(float2*)(out + ((size_t)bb * SEQ + rr0) * (HEADS * DHEAD) + d) =
            make_float2(o[nt][0] * inv0, o[nt][1] * inv0);
        *(float2*)(out + ((size_t)bb * SEQ + rr1) * (HEADS * DHEAD) + d) =
            make_float2(o[nt][2] * inv1, o[nt][3] * inv1);
    }
}

// ---------------------------------------------------------------------------
extern "C" void kernel_launch(void* const* d_in, const int* in_sizes, int n_in,
                              void* d_out, int out_size) {
    const float* x    = (const float*)d_in[0];
    const float* ln_w = (const float*)d_in[1];
    const float* ln_b = (const float*)d_in[2];
    const float* wq   = (const float*)d_in[3];
    const float* bq   = (const float*)d_in[4];
    const float* wk   = (const float*)d_in[5];
    const float* bk   = (const float*)d_in[6];
    const float* wv   = (const float*)d_in[7];
    const float* bv   = (const float*)d_in[8];
    float* out = (float*)d_out;

    cudaFuncSetAttribute(qkv_gemm_mma,
                         cudaFuncAttributeMaxDynamicSharedMemorySize, GEMM_SMEM);
    cudaFuncSetAttribute(attn_mma,
                         cudaFuncAttributeMaxDynamicSharedMemorySize, ATTN_SMEM);

    ln_kernel<<<MTOT, 256>>>(x, ln_w, ln_b);
    cvt_w<<<dim3(32, 32, 3), 256>>>(wq, wk, wv);
    qkv_gemm_mma<<<dim3(DIM / 128, MTOT / 128, 3), 256, GEMM_SMEM>>>(bq, bk, bv);
    attn_mma<<<dim3(SEQ / 128, BATCH * HEADS), 256, ATTN_SMEM>>>(out);
}